// round 11
// baseline (speedup 1.0000x reference)
#include <cuda_runtime.h>
#include <cuda_fp16.h>
#include <cstdint>
#include <math.h>

// ---------------- problem constants ----------------
#define NB 5
#define BATCH 512
#define KQ 64
#define D 200
#define HEADS 4
#define HD 50
#define TKV 320
#define HID 512
#define FIN 64000
#define BAND_STRIDE 6553600ull   // BATCH*KQ*D (elements)
#define ROW_STRIDE 12800         // KQ*D
#define R_NSPLIT 9

// ---------------- scratch ----------------
__device__ float  g_hpart[(size_t)R_NSPLIT * BATCH * HID];
__device__ int    g_sel[BATCH];
__device__ __half g_bh [(size_t)NB * BAND_STRIDE];   // bands * 4, hi
__device__ __half g_bl [(size_t)NB * BAND_STRIDE];   // bands * 4, lo
__device__ __half g_w1h[(size_t)HID * FIN];          // w1 * 256, hi
__device__ __half g_w1l[(size_t)HID * FIN];          // w1 * 256, lo
__device__ __half g_wkvh[448 * 256];                 // wk|wv * 256 padded, hi
__device__ __half g_wkvl[448 * 256];                 // lo
__device__ __half g_wqh[256 * 256];                  // wq * 256 padded, hi
__device__ __half g_wql[256 * 256];                  // lo
__device__ __half g_woh[256 * 256];                  // out_w * 256 padded, hi
__device__ __half g_wol[256 * 256];                  // lo
// head-split padded layouts, values scaled *32, pad cols 50..55 zero
__device__ __half g_qh[(size_t)BATCH * HEADS * 64 * 56];
__device__ __half g_ql[(size_t)BATCH * HEADS * 64 * 56];
__device__ __half g_kh[(size_t)BATCH * HEADS * 320 * 56];
__device__ __half g_kl[(size_t)BATCH * HEADS * 320 * 56];
__device__ __half g_vh[(size_t)BATCH * HEADS * 320 * 56];
__device__ __half g_vl[(size_t)BATCH * HEADS * 320 * 56];
// attention output, scaled *32, [b*64][200]
__device__ __half g_oh[(size_t)BATCH * KQ * D];
__device__ __half g_ol[(size_t)BATCH * KQ * D];

// =====================================================================
// helpers
// =====================================================================
__device__ __forceinline__ uint32_t smem_u32(const void* p) {
    uint32_t a;
    asm("{ .reg .u64 t; cvta.to.shared.u64 t, %1; cvt.u32.u64 %0, t; }" : "=r"(a) : "l"(p));
    return a;
}
__device__ __forceinline__ void cp16(uint32_t dst, const void* src) {
    asm volatile("cp.async.cg.shared.global [%0], [%1], 16;" :: "r"(dst), "l"(src));
}
#define CP_COMMIT() asm volatile("cp.async.commit_group;" ::: "memory")
#define CP_WAIT1()  asm volatile("cp.async.wait_group 1;" ::: "memory")
#define CP_WAIT0()  asm volatile("cp.async.wait_group 0;" ::: "memory")

__device__ __forceinline__ void ldsm4(uint32_t* r, uint32_t a) {
    asm volatile("ldmatrix.sync.aligned.m8n8.x4.shared.b16 {%0,%1,%2,%3}, [%4];"
        : "=r"(r[0]), "=r"(r[1]), "=r"(r[2]), "=r"(r[3]) : "r"(a));
}
__device__ __forceinline__ void ldsm2(uint32_t* r, uint32_t a) {
    asm volatile("ldmatrix.sync.aligned.m8n8.x2.shared.b16 {%0,%1}, [%2];"
        : "=r"(r[0]), "=r"(r[1]) : "r"(a));
}
__device__ __forceinline__ void ldsm2t(uint32_t* r, uint32_t a) {
    asm volatile("ldmatrix.sync.aligned.m8n8.x2.trans.shared.b16 {%0,%1}, [%2];"
        : "=r"(r[0]), "=r"(r[1]) : "r"(a));
}
__device__ __forceinline__ void mma16816(float* c, const uint32_t* a, const uint32_t* b) {
    asm volatile("mma.sync.aligned.m16n8k16.row.col.f32.f16.f16.f32 "
        "{%0,%1,%2,%3}, {%4,%5,%6,%7}, {%8,%9}, {%0,%1,%2,%3};"
        : "+f"(c[0]), "+f"(c[1]), "+f"(c[2]), "+f"(c[3])
        : "r"(a[0]), "r"(a[1]), "r"(a[2]), "r"(a[3]), "r"(b[0]), "r"(b[1]));
}

// =====================================================================
// Conversion kernels
// =====================================================================
__global__ __launch_bounds__(256) void conv_split(const float* __restrict__ src,
                                                  __half* __restrict__ dh,
                                                  __half* __restrict__ dl,
                                                  int n4, float s)
{
    int i = blockIdx.x * blockDim.x + threadIdx.x;
    if (i >= n4) return;
    float4 v = ((const float4*)src)[i];
    float x0 = v.x * s, x1 = v.y * s, x2 = v.z * s, x3 = v.w * s;
    __half h0 = __float2half_rn(x0), h1 = __float2half_rn(x1);
    __half h2 = __float2half_rn(x2), h3 = __float2half_rn(x3);
    __half l0 = __float2half_rn(x0 - __half2float(h0));
    __half l1 = __float2half_rn(x1 - __half2float(h1));
    __half l2 = __float2half_rn(x2 - __half2float(h2));
    __half l3 = __float2half_rn(x3 - __half2float(h3));
    ((__half2*)dh)[2 * i]     = __halves2half2(h0, h1);
    ((__half2*)dh)[2 * i + 1] = __halves2half2(h2, h3);
    ((__half2*)dl)[2 * i]     = __halves2half2(l0, l1);
    ((__half2*)dl)[2 * i + 1] = __halves2half2(l2, l3);
}

__global__ __launch_bounds__(256) void conv_wkv_k(const float* __restrict__ ipw)
{
    const int row = blockIdx.x;
    const int col = threadIdx.x;
    float v = 0.f;
    if (row < 400 && col < 200) v = ipw[(size_t)(200 + row) * 200 + col] * 256.f;
    __half h = __float2half_rn(v);
    __half l = __float2half_rn(v - __half2float(h));
    g_wkvh[row * 256 + col] = h;
    g_wkvl[row * 256 + col] = l;
}

// generic 200x200 -> padded 256x256 hi/lo (for wq and out_w)
__global__ __launch_bounds__(256) void conv_w256(const float* __restrict__ W,
                                                 __half* __restrict__ dh,
                                                 __half* __restrict__ dl)
{
    const int row = blockIdx.x;
    const int col = threadIdx.x;
    float v = 0.f;
    if (row < 200 && col < 200) v = W[(size_t)row * 200 + col] * 256.f;
    __half h = __float2half_rn(v);
    __half l = __float2half_rn(v - __half2float(h));
    dh[row * 256 + col] = h;
    dl[row * 256 + col] = l;
}

// =====================================================================
// Router GEMM: 3-stage cp.async pipeline, M=128, N=128, kc=64, splitK=9
// =====================================================================
#define R_SMEM (3 * 65536)
__global__ __launch_bounds__(256) void router_mma(void)
{
    extern __shared__ char smc[];
    const uint32_t sb = smem_u32(smc);
    const int tid = threadIdx.x, lane = tid & 31, wid = tid >> 5;
    const int jt = blockIdx.x, mt = blockIdx.y, sp = blockIdx.z;
    const int b0 = mt * 128, j0 = jt * 128;
    const int wm = wid & 1, wn = wid >> 1;
    const int m_base = wm * 64, n_base = wn * 32;

    const int a_row  = (lane & 7) + ((lane >> 3) & 1) * 8;
    const int a_koff = (lane >> 4) * 16;
    const int bl_    = lane & 15;
    const int b_row  = bl_ & 7;
    const int b_koff = (bl_ >> 3) * 16;
    int rowbyteA[4], rowbyteB[4];
#pragma unroll
    for (int mi = 0; mi < 4; mi++) rowbyteA[mi] = (m_base + mi * 16 + a_row) * 128;
#pragma unroll
    for (int ni = 0; ni < 4; ni++) rowbyteB[ni] = (n_base + ni * 8 + b_row) * 128;
    const int swzA = (lane & 7) << 4;
    const int swzB = b_row << 4;

    float C[4][4][4];
#pragma unroll
    for (int a = 0; a < 4; a++)
#pragma unroll
        for (int b = 0; b < 4; b++)
#pragma unroll
            for (int c = 0; c < 4; c++) C[a][b][c] = 0.f;

    const int cbeg = sp * 111 + (sp > 0 ? 1 : 0);
    const int cnt  = 111 + (sp == 0 ? 1 : 0);

    auto issue_chunk = [&](int c, int p) {
        const int n = c / 200;
        const int rr = (c - n * 200) * 64;
        const __half* Ah = g_bh + (size_t)n * BAND_STRIDE + (size_t)b0 * ROW_STRIDE + rr;
        const __half* Al = g_bl + (size_t)n * BAND_STRIDE + (size_t)b0 * ROW_STRIDE + rr;
        const size_t f0 = (size_t)c * 64;
        const uint32_t so = sb + p * 65536;
#pragma unroll
        for (int j = 0; j < 4; j++) {
            const int u = tid + j * 256;
            const int row = u >> 3, uu = u & 7;
            const uint32_t d = row * 128 + ((uu * 16) ^ ((row & 7) << 4));
            cp16(so + d,         Ah + (size_t)row * ROW_STRIDE + uu * 8);
            cp16(so + 16384 + d, Al + (size_t)row * ROW_STRIDE + uu * 8);
            const __half* Bh = g_w1h + (size_t)(j0 + row) * FIN + f0 + uu * 8;
            const __half* Bl = g_w1l + (size_t)(j0 + row) * FIN + f0 + uu * 8;
            cp16(so + 32768 + d, Bh);
            cp16(so + 49152 + d, Bl);
        }
    };

    issue_chunk(cbeg, 0);     CP_COMMIT();
    issue_chunk(cbeg + 1, 1); CP_COMMIT();

    for (int c = 0; c < cnt; c++) {
        const int p = c % 3;
        if (c + 1 < cnt) CP_WAIT1(); else CP_WAIT0();
        __syncthreads();
        if (c + 2 < cnt) { issue_chunk(cbeg + c + 2, (c + 2) % 3); CP_COMMIT(); }
        const uint32_t so = sb + p * 65536;
#pragma unroll
        for (int ks = 0; ks < 4; ks++) {
            uint32_t bhf[4][2], blf[4][2];
#pragma unroll
            for (int ni = 0; ni < 4; ni++) {
                const uint32_t ad = so + 32768 + rowbyteB[ni] + ((ks * 32 + b_koff) ^ swzB);
                ldsm2(bhf[ni], ad);
                ldsm2(blf[ni], ad + 16384);
            }
#pragma unroll
            for (int mi = 0; mi < 4; mi++) {
                uint32_t ah[4], al[4];
                const uint32_t aa = so + rowbyteA[mi] + ((ks * 32 + a_koff) ^ swzA);
                ldsm4(ah, aa);
                ldsm4(al, aa + 16384);
#pragma unroll
                for (int ni = 0; ni < 4; ni++) {
                    mma16816(C[mi][ni], ah, bhf[ni]);
                    mma16816(C[mi][ni], ah, blf[ni]);
                    mma16816(C[mi][ni], al, bhf[ni]);
                }
            }
        }
    }

    const float invS = 1.f / 1024.f;
    float* outp = g_hpart + (size_t)sp * (BATCH * HID);
    const int g = lane >> 2, qp = lane & 3;
#pragma unroll
    for (int mi = 0; mi < 4; mi++) {
#pragma unroll
        for (int ni = 0; ni < 4; ni++) {
            const int row = b0 + m_base + mi * 16 + g;
            const int col = j0 + n_base + ni * 8 + qp * 2;
            *(float2*)(outp + (size_t)row * HID + col) =
                make_float2(C[mi][ni][0] * invS, C[mi][ni][1] * invS);
            *(float2*)(outp + (size_t)(row + 8) * HID + col) =
                make_float2(C[mi][ni][2] * invS, C[mi][ni][3] * invS);
        }
    }
}

// =====================================================================
// Router select
// =====================================================================
__global__ __launch_bounds__(128) void router_select(const float* __restrict__ b1,
                                                     const float* __restrict__ w2,
                                                     const float* __restrict__ b2)
{
    const int b = blockIdx.x, tid = threadIdx.x;
    float acc[NB] = {0.f, 0.f, 0.f, 0.f, 0.f};
    for (int j = tid; j < HID; j += 128) {
        float hv = b1[j];
#pragma unroll
        for (int s = 0; s < R_NSPLIT; s++)
            hv += g_hpart[(size_t)s * BATCH * HID + (size_t)b * HID + j];
        hv = fmaxf(hv, 0.f);
#pragma unroll
        for (int n = 0; n < NB; n++) acc[n] += hv * w2[n * HID + j];
    }
    __shared__ float red[NB][128];
#pragma unroll
    for (int n = 0; n < NB; n++) red[n][tid] = acc[n];
    __syncthreads();
    for (int s = 64; s > 0; s >>= 1) {
        if (tid < s) {
#pragma unroll
            for (int n = 0; n < NB; n++) red[n][tid] += red[n][tid + s];
        }
        __syncthreads();
    }
    if (tid == 0) {
        int best = 0;
        float bv = red[0][0] + b2[0];
        for (int n = 1; n < NB; n++) {
            float v = red[n][0] + b2[n];
            if (v > bv) { bv = v; best = n; }
        }
        g_sel[b] = best;
    }
}

// =====================================================================
// Q projection HMMA: per b, M=64, N=256(pad of 200), K=208 -> g_qh/g_ql
// B chunks double-buffered via cp.async (2 stages of 64KB)
// =====================================================================
#define QM_AH 0
#define QM_AL 32768
#define QM_B  65536          // stage p: hi @ +p*65536, lo @ +p*65536+32768
#define QM_SMEM (65536 + 2 * 65536)
__global__ __launch_bounds__(256) void q_mma(const float* __restrict__ ipb)
{
    extern __shared__ char smc[];
    const uint32_t sb = smem_u32(smc);
    const int tid = threadIdx.x, lane = tid & 31, wid = tid >> 5;
    const int b = blockIdx.x;
    const int wm = wid & 1, wn = wid >> 1;
    const int m_base = wm * 32;

    for (int i = tid; i < 896; i += 256) {
        const int a = i / 448, rem = i % 448;
        const int r = rem / 7, u = 1 + rem % 7;
        const uint32_t off = (a ? QM_AL : QM_AH) + 3 * 8192 + r * 128 + ((u * 16) ^ ((r & 7) << 4));
        *(uint4*)(smc + off) = make_uint4(0, 0, 0, 0);
    }

    auto load_B = [&](const __half* Wh, const __half* Wl, int ck, int p) {
        const uint32_t so = sb + QM_B + p * 65536;
        for (int i = tid; i < 4096; i += 256) {
            const int a = i >> 11, rem = i & 2047;
            const int r = rem >> 3, u = rem & 7;
            const __half* src = (a ? Wl : Wh) + (size_t)r * 256 + ck * 64 + u * 8;
            cp16(so + a * 32768 + r * 128 + ((u * 16) ^ ((r & 7) << 4)), src);
        }
    };

    // group 0: A + B chunk 0
    const size_t abase = (size_t)g_sel[b] * BAND_STRIDE + (size_t)b * ROW_STRIDE;
    for (int i = tid; i < 3200; i += 256) {
        const int a = i / 1600, rem = i % 1600;
        const int r = rem / 25, cu = rem % 25, ch = cu >> 3, u = cu & 7;
        const __half* src = (a ? g_bl : g_bh) + abase + (size_t)r * 200 + ch * 64 + u * 8;
        cp16(sb + (a ? QM_AL : QM_AH) + ch * 8192 + r * 128 + ((u * 16) ^ ((r & 7) << 4)), src);
    }
    load_B(g_wqh, g_wql, 0, 0);
    CP_COMMIT();
    load_B(g_wqh, g_wql, 1, 1);
    CP_COMMIT();

    const int a_row  = (lane & 7) + ((lane >> 3) & 1) * 8;
    const int a_koff = (lane >> 4) * 16;
    const int b_row  = lane & 7;
    const int b_koff = ((lane >> 3) & 1) * 16;

    float C[2][8][4];
#pragma unroll
    for (int a = 0; a < 2; a++)
#pragma unroll
        for (int n = 0; n < 8; n++)
#pragma unroll
            for (int c = 0; c < 4; c++) C[a][n][c] = 0.f;

    for (int ck = 0; ck < 4; ck++) {
        const int p = ck & 1;
        if (ck < 3) CP_WAIT1(); else CP_WAIT0();
        __syncthreads();
        const uint32_t soB = sb + QM_B + p * 65536;
        const int nks = (ck < 3) ? 4 : 1;
        for (int ks = 0; ks < nks; ks++) {
            uint32_t bhf[8][2], blf[8][2];
#pragma unroll
            for (int ni = 0; ni < 8; ni++) {
                const int nr = wn * 64 + ni * 8 + b_row;
                const uint32_t ad = soB + nr * 128 + ((ks * 32 + b_koff) ^ ((nr & 7) << 4));
                ldsm2(bhf[ni], ad);
                ldsm2(blf[ni], ad + 32768);
            }
#pragma unroll
            for (int mi = 0; mi < 2; mi++) {
                const int ar = m_base + mi * 16 + a_row;
                uint32_t ah[4], al[4];
                const uint32_t aa = sb + QM_AH + ck * 8192 + ar * 128 + ((ks * 32 + a_koff) ^ ((ar & 7) << 4));
                ldsm4(ah, aa);
                ldsm4(al, aa + 32768);
#pragma unroll
                for (int ni = 0; ni < 8; ni++) {
                    mma16816(C[mi][ni], ah, bhf[ni]);
                    mma16816(C[mi][ni], ah, blf[ni]);
                    mma16816(C[mi][ni], al, bhf[ni]);
                }
            }
        }
        __syncthreads();
        if (ck + 2 < 4) { load_B(g_wqh, g_wql, ck + 2, p); CP_COMMIT(); }
    }

    const int g = lane >> 2, qp = lane & 3;
    const float invS = 1.f / 1024.f;
#pragma unroll
    for (int mi = 0; mi < 2; mi++) {
#pragma unroll
        for (int ni = 0; ni < 8; ni++) {
            const int j = wn * 64 + ni * 8 + qp * 2;
#pragma unroll
            for (int e = 0; e < 2; e++) {
                const int jj = j + e;
                if (jj >= 200) continue;
                const int hh = jj / 50, dd = jj % 50;
                const float bia = __ldg(ipb + jj);
#pragma unroll
                for (int hf = 0; hf < 2; hf++) {
                    const int r = m_base + mi * 16 + g + hf * 8;
                    const float v = C[mi][ni][hf * 2 + e] * invS + bia;
                    const float v32 = v * 32.f;
                    const __half ph = __float2half_rn(v32);
                    const __half pl = __float2half_rn(v32 - __half2float(ph));
                    const size_t idx = ((size_t)(b * 4 + hh) * 64 + r) * 56 + dd;
                    g_qh[idx] = ph;
                    g_ql[idx] = pl;
                }
            }
        }
    }
    for (int i = tid; i < 1536; i += 256) {
        const int a = i / 768, rem = i % 768;
        const int hh = rem / 192, rem2 = rem % 192;
        const int t = rem2 / 3, uo = rem2 % 3;
        __half* base = a ? g_ql : g_qh;
        *((uint32_t*)(base + ((size_t)(b * 4 + hh) * 64 + t) * 56 + 50) + uo) = 0u;
    }
}

// =====================================================================
// K/V projection HMMA -> fp16 hi/lo head-split layout
// A resident (128x208 hi/lo), B streamed as 13 N-tiles of 32 rows,
// 2-stage cp.async ring (load nt+2 after compute of nt).
// =====================================================================
#define KV_AH 0
#define KV_AL 65536
#define KV_B  131072          // stage p: hi @ +p*32768, lo @ +p*32768+16384
#define KV_BIAS 196608
#define KV_SMEM (196608 + 1664)
#define KV_NT 13
__global__ __launch_bounds__(256) void kv_mma(const float* __restrict__ ipb)
{
    extern __shared__ char smc[];
    const uint32_t sb = smem_u32(smc);
    const int tid = threadIdx.x, lane = tid & 31, wid = tid >> 5;
    const int n = blockIdx.x, bp = blockIdx.y;
    const int wm = wid & 1, wn = wid >> 1;       // 2(M) x 4(N=8 cols each)
    const int m_base = wm * 64;

    float* bias = (float*)(smc + KV_BIAS);
    for (int i = tid; i < 400; i += 256) bias[i] = ipb[200 + i];

    // zero A pad (chunk 3, units 1..7)
#pragma unroll
    for (int j = 0; j < 4; j++) {
        const int u = tid + j * 256;
        if (u < 896) {
            const int row = u / 7, uu = 1 + (u % 7);
            const uint32_t d = 3 * 16384 + row * 128 + ((uu * 16) ^ ((row & 7) << 4));
            *(uint4*)(smc + KV_AH + d) = make_uint4(0, 0, 0, 0);
            *(uint4*)(smc + KV_AL + d) = make_uint4(0, 0, 0, 0);
        }
    }

    auto load_B = [&](int nt, int p) {
        const uint32_t so = sb + KV_B + p * 32768;
#pragma unroll
        for (int j = 0; j < 8; j++) {
            const int u = tid + j * 256;        // 0..2047
            const int a = u >> 10;              // 0=hi 1=lo
            const int rem = u & 1023;
            const int r = rem >> 5;             // 0..31
            const int cu = rem & 31;
            const int ch = cu >> 3, uu = cu & 7;
            const int nr = nt * 32 + r;
            const __half* src = (a ? g_wkvl : g_wkvh) + (size_t)nr * 256 + ch * 64 + uu * 8;
            cp16(so + a * 16384 + ch * 4096 + r * 128 + ((uu * 16) ^ ((r & 7) << 4)), src);
        }
    };

    // group 0: A + B tile 0
    {
        const size_t abase = (size_t)n * BAND_STRIDE + (size_t)(bp * 128) * 200;
#pragma unroll
        for (int j = 0; j < 13; j++) {
            const int u = tid + j * 256;
            if (u < 3200) {
                const int row = u / 25;
                const int rem = u - row * 25;
                const int ch = rem >> 3, uu = rem & 7;
                const uint32_t d = ch * 16384 + row * 128 + ((uu * 16) ^ ((row & 7) << 4));
                const size_t srow = abase + (size_t)row * 200 + ch * 64 + uu * 8;
                cp16(sb + KV_AH + d, g_bh + srow);
                cp16(sb + KV_AL + d, g_bl + srow);
            }
        }
    }
    load_B(0, 0);
    CP_COMMIT();
    load_B(1, 1);
    CP_COMMIT();

    const int a_row  = (lane & 7) + ((lane >> 3) & 1) * 8;
    const int a_koff = (lane >> 4) * 16;
    const int bl_    = lane & 15;
    const int b_row  = bl_ & 7;
    const int b_koff = (bl_ >> 3) * 16;
    int rowbyteA[4];
#pragma unroll
    for (int mi = 0; mi < 4; mi++) rowbyteA[mi] = (m_base + mi * 16 + a_row) * 128;
    const int rowbyteB = (wn * 8 + b_row) * 128;
    const int swzA = (lane & 7) << 4;
    const int swzB = b_row << 4;
    const int g = lane >> 2, qp = lane & 3;
    const float invS = 1.f / 1024.f;

    for (int nt = 0; nt < KV_NT; nt++) {
        const int p = nt & 1;
        if (nt + 1 < KV_NT) CP_WAIT1(); else CP_WAIT0();
        __syncthreads();

        const uint32_t soB = sb + KV_B + p * 32768;
        float C[4][4];
#pragma unroll
        for (int a = 0; a < 4; a++)
#pragma unroll
            for (int c = 0; c < 4; c++) C[a][c] = 0.f;

        for (int ks = 0; ks < 13; ks++) {
            const int ch = ks >> 2, ki = ks & 3;
            uint32_t bhf[2], blf[2];
            const uint32_t ad = soB + ch * 4096 + rowbyteB + ((ki * 32 + b_koff) ^ swzB);
            ldsm2(bhf, ad);
            ldsm2(blf, ad + 16384);
#pragma unroll
            for (int mi = 0; mi < 4; mi++) {
                uint32_t ah[4], al[4];
                const uint32_t aa = sb + KV_AH + ch * 16384 + rowbyteA[mi] + ((ki * 32 + a_koff) ^ swzA);
                ldsm4(ah, aa);
                ldsm4(al, aa + 65536);
                mma16816(C[mi], ah, bhf);
                mma16816(C[mi], ah, blf);
                mma16816(C[mi], al, bhf);
            }
        }
        __syncthreads();
        if (nt + 2 < KV_NT) { load_B(nt + 2, p); CP_COMMIT(); }

        // epilogue: scaled fp16 hi/lo into head-split K/V
#pragma unroll
        for (int mi = 0; mi < 4; mi++) {
            const int col = nt * 32 + wn * 8 + qp * 2;
#pragma unroll
            for (int e = 0; e < 2; e++) {
                const int ce = col + e;
                if (ce >= 400) continue;
                const float bia = bias[ce];
                const int isV = (ce >= 200);
                const int c2 = isV ? (ce - 200) : ce;
                const int hh = c2 / 50, dd = c2 % 50;
                __half* dsth = isV ? g_vh : g_kh;
                __half* dstl = isV ? g_vl : g_kl;
#pragma unroll
                for (int hf = 0; hf < 2; hf++) {
                    const int r = m_base + mi * 16 + g + hf * 8;
                    const int b = 2 * bp + (r >> 6);
                    const int tloc = n * 64 + (r & 63);
                    const float v = C[mi][hf * 2 + e] * invS + bia;
                    const float v32 = v * 32.f;
                    const __half ph = __float2half_rn(v32);
                    const __half pl = __float2half_rn(v32 - __half2float(ph));
                    const size_t idx = ((size_t)(b * 4 + hh) * 320 + tloc) * 56 + dd;
                    dsth[idx] = ph;
                    dstl[idx] = pl;
                }
            }
        }
    }
    for (int i = tid; i < 6144; i += 256) {
        const int a = i / 1536, rem = i % 1536;
        const int bb = rem / 768, rem2 = rem % 768;
        const int hh = rem2 / 192, rem3 = rem2 % 192;
        const int tt = rem3 / 3, uo = rem3 % 3;
        const int bg = 2 * bp + bb;
        const int t = n * 64 + tt;
        __half* base = (a == 0) ? g_kh : (a == 1) ? g_kl : (a == 2) ? g_vh : g_vl;
        *((uint32_t*)(base + ((size_t)(bg * 4 + hh) * 320 + t) * 56 + 50) + uo) = 0u;
    }
}

// =====================================================================
// Attention HMMA: prefetch (Q,K + V groups), register softmax,
// P single fp16 (2-term PV: P_h*(V_h + V_l))
// =====================================================================
#define AT_QH 0
#define AT_QL 8192
#define AT_KH 16384      // later P hi
#define AT_KL 57344
#define AT_VH 98304
#define AT_VL 139264
#define AT_RED  180224   // 128 floats
#define AT_RED2 180736   // 128 floats
#define AT_SMEM 181248
__global__ __launch_bounds__(256) void attn_mma()
{
    extern __shared__ char smc[];
    const uint32_t sb = smem_u32(smc);
    const int tid = threadIdx.x, lane = tid & 31, wid = tid >> 5;
    const int h = blockIdx.x, b = blockIdx.y;
    const size_t kvbase = ((size_t)b * 4 + h) * 320;
    const size_t qbase  = ((size_t)b * 4 + h) * 64;

    for (int i = tid; i < 768; i += 256) {
        uint32_t base; int row;
        if (i < 64)       { base = AT_QH; row = i; }
        else if (i < 128) { base = AT_QL; row = i - 64; }
        else if (i < 448) { base = AT_KH; row = i - 128; }
        else              { base = AT_KL; row = i - 448; }
        *(uint4*)(smc + base + row * 128 + (112 ^ ((row & 7) << 4))) = make_uint4(0, 0, 0, 0);
    }
    for (int i = tid; i < 896; i += 256) {
        const int a = i / 448, rem = i % 448;
        const int r = rem / 7, u = rem % 7;
        const __half* src = (a ? g_ql : g_qh) + (qbase + r) * 56 + u * 8;
        cp16(sb + (a ? AT_QL : AT_QH) + r * 128 + ((u * 16) ^ ((r & 7) << 4)), src);
    }
    for (int i = tid; i < 4480; i += 256) {
        const int a = i / 2240, rem = i % 2240;
        const int r = rem / 7, u = rem % 7;
        const __half* src = (a ? g_kl : g_kh) + (kvbase + r) * 56 + u * 8;
        cp16(sb + (a ? AT_KL : AT_KH) + r * 128 + ((u * 16) ^ ((r & 7) << 4)), src);
    }
    CP_COMMIT();
    for (int i = tid; i < 4480; i += 256) {
        const int a = i / 2240, rem = i % 2240;
        const int r = rem / 7, u = rem % 7;
        const __half* src = (a ? g_vl : g_vh) + (kvbase + r) * 56 + u * 8;
        cp16(sb + (a ? AT_VL : AT_VH) + r * 128 + ((u * 16) ^ ((r & 7) << 4)), src);
    }
    CP_COMMIT();
    CP_WAIT1();
    __syncthreads();

    // ---- QK^T ----
    const int wm = wid & 3, wn = wid >> 2;
    const int m_base = wm * 16, n_base = wn * 160;
    const int a_row  = m_base + (lane & 7) + ((lane >> 3) & 1) * 8;
    const int a_koff = (lane >> 4) * 16;
    const int b_row  = lane & 7;
    const int b_koff = ((lane >> 3) & 1) * 16;
    const int g = lane >> 2, qp = lane & 3;

    float C[20][4];
#pragma unroll
    for (int i = 0; i < 20; i++)
#pragma unroll
        for (int j = 0; j < 4; j++) C[i][j] = 0.f;

#pragma unroll
    for (int ks = 0; ks < 4; ks++) {
        uint32_t qh4[4], ql4[4];
        const uint32_t aoff = a_row * 128 + ((ks * 32 + a_koff) ^ ((a_row & 7) << 4));
        ldsm4(qh4, sb + AT_QH + aoff);
        ldsm4(ql4, sb + AT_QL + aoff);
#pragma unroll
        for (int ni = 0; ni < 20; ni++) {
            const int trow = n_base + ni * 8 + b_row;
            const uint32_t boff = trow * 128 + ((ks * 32 + b_koff) ^ ((trow & 7) << 4));
            uint32_t kh2[2], kl2[2];
            ldsm2(kh2, sb + AT_KH + boff);
            ldsm2(kl2, sb + AT_KL + boff);
            mma16816(C[ni], qh4, kh2);
            mma16816(C[ni], qh4, kl2);
            mma16816(C[ni], ql4, kh2);
        }
    }

    // ---- register softmax ----
    const float sc = 0.14142135623730951f / 1024.f;
#pragma unroll
    for (int ni = 0; ni < 20; ni++)
#pragma unroll
        for (int j = 0; j < 4; j++) C[ni][j] *= sc;

    float* RED1 = (float*)(smc + AT_RED);
    float* RED2 = (float*)(smc + AT_RED2);
    const int r0 = m_base + g;

    float m0 = -1e30f, m1 = -1e30f;
#pragma unroll
    for (int ni = 0; ni < 20; ni++) {
        m0 = fmaxf(m0, fmaxf(C[ni][0], C[ni][1]));
        m1 = fmaxf(m1, fmaxf(C[ni][2], C[ni][3]));
    }
    m0 = fmaxf(m0, __shfl_xor_sync(0xffffffffu, m0, 1));
    m0 = fmaxf(m0, __shfl_xor_sync(0xffffffffu, m0, 2));
    m1 = fmaxf(m1, __shfl_xor_sync(0xffffffffu, m1, 1));
    m1 = fmaxf(m1, __shfl_xor_sync(0xffffffffu, m1, 2));
    if (qp == 0) { RED1[wn * 64 + r0] = m0; RED1[wn * 64 + r0 + 8] = m1; }
    __syncthreads();
    const float M0 = fmaxf(RED1[r0], RED1[64 + r0]);
    const float M1 = fmaxf(RED1[r0 + 8], RED1[64 + r0 + 8]);

    float s0 = 0.f, s1 = 0.f;
#pragma unroll
    for (int ni = 0; ni < 20; ni++) {
        C[ni][0] = __expf(C[ni][0] - M0); s0 += C[ni][0];
        C[ni][1] = __expf(C[ni][1] - M0); s0 += C[ni][1];
        C[ni][2] = __expf(C[ni][2] - M1); s1 += C[ni][2];
        C[ni][3] = __expf(C[ni][3] - M1); s1 += C[ni][3];
    }
    s0 += __shfl_xor_sync(0xffffffffu, s0, 1);
    s0 += __shfl_xor_sync(0xffffffffu, s0, 2);
    s1 += __shfl_xor_sync(0xffffffffu, s1, 1);
    s1 += __shfl_xor_sync(0xffffffffu, s1, 2);
    if (qp == 0) { RED2[wn * 64 + r0] = s0; RED2[wn * 64 + r0 + 8] = s1; }
    __syncthreads();
    const float i0 = 1.f / (RED2[r0] + RED2[64 + r0]);
    const float i1 = 1.f / (RED2[r0 + 8] + RED2[64 + r0 + 8]);

    // P hi (single fp16) from registers into K region (ldmatrix layout, row=640B)
    {
        const uint32_t sw0 = (r0 & 7) << 4;
        const uint32_t sw1 = ((r0 + 8) & 7) << 4;
#pragma unroll
        for (int ni = 0; ni < 20; ni++) {
            const int col = n_base + ni * 8 + qp * 2;
            const uint32_t ub = (col >> 3) * 16;
            const uint32_t off0 = r0 * 640 + (ub ^ sw0) + (col & 7) * 2;
            const uint32_t off1 = (r0 + 8) * 640 + (ub ^ sw1) + (col & 7) * 2;
            *(__half2*)(smc + AT_KH + off0) =
                __halves2half2(__float2half_rn(C[ni][0] * i0), __float2half_rn(C[ni][1] * i0));
            *(__half2*)(smc + AT_KH + off1) =
                __halves2half2(__float2half_rn(C[ni][2] * i1), __float2half_rn(C[ni][3] * i1));
        }
    }
    CP_WAIT0();
    __syncthreads();

    // ---- P @ V (2-term: P_h * (V_h + V_l)) ----
    const int wnv = wid >> 2;
    const int mv_base = (wid & 3) * 16;
    const int nv_base = wnv * 32;
    const int ntc = wnv ? 3 : 4;
    const int p_row = mv_base + (lane & 7) + ((lane >> 3) & 1) * 8;
    const int p_unit = lane >> 4;
    const int v_koff = (lane & 7) + ((lane >> 3) & 1) * 8;

    float O[4][4];
#pragma unroll
    for (int i = 0; i < 4; i++)
#pragma unroll
        for (int j = 0; j < 4; j++) O[i][j] = 0.f;

    for (int ks = 0; ks < 20; ks++) {
        uint32_t ph4[4];
        const uint32_t poff = p_row * 640 + (((ks * 2 + p_unit) * 16) ^ ((p_row & 7) << 4));
        ldsm4(ph4, sb + AT_KH + poff);
        const int krow = ks * 16 + v_koff;
        const uint32_t swk = (krow & 7) << 4;
#pragma unroll
        for (int nt = 0; nt < 4; nt++) {
            if (nt >= ntc) break;
            const int ncol = nv_base + nt * 8;
            const uint32_t voff = krow * 128 + ((ncol * 2) ^ swk);
            uint32_t vh2[2], vl2[2];
            ldsm2t(vh2, sb + AT_VH + voff);
            ldsm2t(vl2, sb + AT_VL + voff);
            mma16816(O[nt], ph4, vh2);
            mma16816(O[nt], ph4, vl2);
        }
    }

    // O (scale 32) -> fp16 hi/lo for out projection
#pragma unroll
    for (int nt = 0; nt < 4; nt++) {
        if (nt >= ntc) break;
        const int d = nv_base + nt * 8 + qp * 2;
        if (d >= 50) continue;
#pragma unroll
        for (int hf = 0; hf < 2; hf++) {
            const int r = mv_base + g + hf * 8;
            const float o0 = O[nt][hf * 2 + 0];
            const float o1 = O[nt][hf * 2 + 1];
            const __half h0 = __float2half_rn(o0), h1 = __float2half_rn(o1);
            const size_t idx = ((size_t)b * 64 + r) * 200 + h * 50 + d;
            *(__half2*)(g_oh + idx) = __halves2half2(h0, h1);
            *(__half2*)(g_ol + idx) =
                __halves2half2(__float2half_rn(o0 - __half2float(h0)),
                               __float2half_rn(o1 - __half2float(h1)));
        }
    }
}

// =====================================================================
// Out projection HMMA: per b, M=64, N=256(pad 200), K=208, fp32 out
// B chunks double-buffered via cp.async
// =====================================================================
__global__ __launch_bounds__(256) void out_mma(const float* __restrict__ ob,
                                               float* __restrict__ outp)
{
    extern __shared__ char smc[];
    const uint32_t sb = smem_u32(smc);
    const int tid = threadIdx.x, lane = tid & 31, wid = tid >> 5;
    const int b = blockIdx.x;
    const int wm = wid & 1, wn = wid >> 1;
    const int m_base = wm * 32;

    for (int i = tid; i < 896; i += 256) {
        const int a = i / 448, rem = i % 448;
        const int r = rem / 7, u = 1 + rem % 7;
        const uint32_t off = (a ? QM_AL : QM_AH) + 3 * 8192 + r * 128 + ((u * 16) ^ ((r & 7) << 4));
        *(uint4*)(smc + off) = make_uint4(0, 0, 0, 0);
    }

    auto load_B = [&](int ck, int p) {
        const uint32_t so = sb + QM_B + p * 65536;
        for (int i = tid; i < 4096; i += 256) {
            const int a = i >> 11, rem = i & 2047;
            const int r = rem >> 3, u = rem & 7;
            const __half* src = (a ? g_wol : g_woh) + (size_t)r * 256 + ck * 64 + u * 8;
            cp16(so + a * 32768 + r * 128 + ((u * 16) ^ ((r & 7) << 4)), src);
        }
    };

    const size_t abase = (size_t)b * 64 * 200;
    for (int i = tid; i < 3200; i += 256) {
        const int a = i / 1600, rem = i % 1600;
        const int r = rem / 25, cu = rem % 25, ch = cu >> 3, u = cu & 7;
        const __half* src = (a ? g_ol : g_oh) + abase + (size_t)r * 200 + ch * 64 + u * 8;
        cp16(sb + (a ? QM_AL : QM_AH) + ch * 8192 + r * 128 + ((u * 16) ^ ((r & 7) << 4)), src);
    }
    load_B(0, 0);
    CP_COMMIT();
    load_B(1, 1);
    CP_COMMIT();

    const int a_row  = (lane & 7) + ((lane >> 3) & 1) * 8;
    const int a_koff = (lane >> 4) * 16;
    const int b_row  = lane & 7;
    const int b_koff = ((lane >> 3) & 1) * 16;

    float C[2][8][4];
#pragma unroll
    for (int a = 0; a < 2; a++)
#pragma unroll
        for (int n = 0; n < 8; n++)
#pragma unroll
            for (int c = 0; c < 4; c++) C[a][n][c] = 0.f;

    for (int ck = 0; ck < 4; ck++) {
        const int p = ck & 1;
        if (ck < 3) CP_WAIT1(); else CP_WAIT0();
        __syncthreads();
        const uint32_t soB = sb + QM_B + p * 65536;
        const int nks = (ck < 3) ? 4 : 1;
        for (int ks = 0; ks < nks; ks++) {
            uint32_t bhf[8][2], blf[8][2];
#pragma unroll
            for (int ni = 0; ni < 8; ni++) {
                const int nr = wn * 64 + ni * 8 + b_row;
                const uint32_t ad = soB + nr * 128 + ((ks * 32 + b_koff) ^ ((nr & 7) << 4));
                ldsm2(bhf[ni], ad);
                ldsm2(blf[ni], ad + 32768);
            }
#pragma unroll
            for (int mi = 0; mi < 2; mi++) {
                const int ar = m_base + mi * 16 + a_row;
                uint32_t ah[4], al[4];
                const uint32_t aa = sb + QM_AH + ck * 8192 + ar * 128 + ((ks * 32 + a_koff) ^ ((ar & 7) << 4));
                ldsm4(ah, aa);
                ldsm4(al, aa + 32768);
#pragma unroll
                for (int ni = 0; ni < 8; ni++) {
                    mma16816(C[mi][ni], ah, bhf[ni]);
                    mma16816(C[mi][ni], ah, blf[ni]);
                    mma16816(C[mi][ni], al, bhf[ni]);
                }
            }
        }
        __syncthreads();
        if (ck + 2 < 4) { load_B(ck + 2, p); CP_COMMIT(); }
    }

    const int g = lane >> 2, qp = lane & 3;
    const float invS = 1.f / 8192.f;
#pragma unroll
    for (int mi = 0; mi < 2; mi++) {
#pragma unroll
        for (int ni = 0; ni < 8; ni++) {
            const int jj = wn * 64 + ni * 8 + qp * 2;
            if (jj >= 200) continue;
            const float b0 = __ldg(ob + jj), b1 = __ldg(ob + jj + 1);
#pragma unroll
            for (int hf = 0; hf < 2; hf++) {
                const int r = m_base + mi * 16 + g + hf * 8;
                *(float2*)(outp + ((size_t)b * 64 + r) * 200 + jj) =
                    make_float2(C[mi][ni][hf * 2 + 0] * invS + b0,
                                C[mi][ni][hf * 2 + 1] * invS + b1);
            }
        }
    }
}

// =====================================================================
// launch
// =====================================================================
extern "C" void kernel_launch(void* const* d_in, const int* in_sizes, int n_in,
                              void* d_out, int out_size)
{
    const float* bands = (const float*)d_in[0];
    const float* w1    = (const float*)d_in[1];
    const float* b1    = (const float*)d_in[2];
    const float* w2    = (const float*)d_in[3];
    const float* b2    = (const float*)d_in[4];
    const float* ipw   = (const float*)d_in[5];
    const float* ipb   = (const float*)d_in[6];
    const float* ow    = (const float*)d_in[7];
    const float* ob    = (const float*)d_in[8];
    float* outp = (float*)d_out;

    cudaFuncSetAttribute(router_mma, cudaFuncAttributeMaxDynamicSharedMemorySize, R_SMEM);
    cudaFuncSetAttribute(kv_mma, cudaFuncAttributeMaxDynamicSharedMemorySize, KV_SMEM);
    cudaFuncSetAttribute(q_mma, cudaFuncAttributeMaxDynamicSharedMemorySize, QM_SMEM);
    cudaFuncSetAttribute(out_mma, cudaFuncAttributeMaxDynamicSharedMemorySize, QM_SMEM);
    cudaFuncSetAttribute(attn_mma, cudaFuncAttributeMaxDynamicSharedMemorySize, AT_SMEM);

    __half *bh, *blp, *w1h, *w1l;
    cudaGetSymbolAddress((void**)&bh,  g_bh);
    cudaGetSymbolAddress((void**)&blp, g_bl);
    cudaGetSymbolAddress((void**)&w1h, g_w1h);
    cudaGetSymbolAddress((void**)&w1l, g_w1l);
    __half *wqh, *wql, *woh, *wol;
    cudaGetSymbolAddress((void**)&wqh, g_wqh);
    cudaGetSymbolAddress((void**)&wql, g_wql);
    cudaGetSymbolAddress((void**)&woh, g_woh);
    cudaGetSymbolAddress((void**)&wol, g_wol);

    const int n4 = (NB * (int)BAND_STRIDE) / 4;
    conv_split<<<(n4 + 255) / 256, 256>>>(bands, bh,  blp, n4, 4.f);
    conv_split<<<(n4 + 255) / 256, 256>>>(w1,    w1h, w1l, n4, 256.f);
    conv_wkv_k<<<448, 256>>>(ipw);
    conv_w256 <<<256, 256>>>(ipw, wqh, wql);
    conv_w256 <<<256, 256>>>(ow, woh, wol);

    router_mma   <<<dim3(4, 4, R_NSPLIT), 256, R_SMEM>>>();
    router_select<<<BATCH, 128>>>(b1, w2, b2);
    q_mma        <<<BATCH, 256, QM_SMEM>>>(ipb);
    kv_mma       <<<dim3(NB, BATCH / 2), 256, KV_SMEM>>>(ipb);
    attn_mma     <<<dim3(HEADS, BATCH), 256, AT_SMEM>>>();
    out_mma      <<<BATCH, 256, QM_SMEM>>>(ob, outp);
}

// round 12
// speedup vs baseline: 1.0387x; 1.0387x over previous
#include <cuda_runtime.h>
#include <cuda_fp16.h>
#include <cstdint>
#include <math.h>

// ---------------- problem constants ----------------
#define NB 5
#define BATCH 512
#define KQ 64
#define D 200
#define HEADS 4
#define HD 50
#define TKV 320
#define HID 512
#define FIN 64000
#define BAND_STRIDE 6553600ull   // BATCH*KQ*D (elements)
#define ROW_STRIDE 12800         // KQ*D
#define R_NSPLIT 9

// ---------------- scratch ----------------
__device__ float  g_hpart[(size_t)R_NSPLIT * BATCH * HID];
__device__ int    g_sel[BATCH];
__device__ __half g_bh [(size_t)NB * BAND_STRIDE];   // bands * 4, hi
__device__ __half g_bl [(size_t)NB * BAND_STRIDE];   // bands * 4, lo
__device__ __half g_w1h[(size_t)HID * FIN];          // w1 * 256, hi
__device__ __half g_w1l[(size_t)HID * FIN];          // w1 * 256, lo
__device__ __half g_wkvh[448 * 256];                 // wk|wv * 256 padded, hi
__device__ __half g_wkvl[448 * 256];                 // lo
__device__ __half g_wqh[256 * 256];                  // wq * 256 padded, hi
__device__ __half g_wql[256 * 256];                  // lo
__device__ __half g_woh[256 * 256];                  // out_w * 256 padded, hi
__device__ __half g_wol[256 * 256];                  // lo
// head-split padded layouts, values scaled *32, pad cols 50..55 zero
__device__ __half g_qh[(size_t)BATCH * HEADS * 64 * 56];
__device__ __half g_ql[(size_t)BATCH * HEADS * 64 * 56];
__device__ __half g_kh[(size_t)BATCH * HEADS * 320 * 56];
__device__ __half g_kl[(size_t)BATCH * HEADS * 320 * 56];
__device__ __half g_vh[(size_t)BATCH * HEADS * 320 * 56];
__device__ __half g_vl[(size_t)BATCH * HEADS * 320 * 56];
// attention output, scaled *32, [b*64][200]
__device__ __half g_oh[(size_t)BATCH * KQ * D];
__device__ __half g_ol[(size_t)BATCH * KQ * D];

// =====================================================================
// helpers
// =====================================================================
__device__ __forceinline__ uint32_t smem_u32(const void* p) {
    uint32_t a;
    asm("{ .reg .u64 t; cvta.to.shared.u64 t, %1; cvt.u32.u64 %0, t; }" : "=r"(a) : "l"(p));
    return a;
}
__device__ __forceinline__ void cp16(uint32_t dst, const void* src) {
    asm volatile("cp.async.cg.shared.global [%0], [%1], 16;" :: "r"(dst), "l"(src));
}
#define CP_COMMIT() asm volatile("cp.async.commit_group;" ::: "memory")
#define CP_WAIT1()  asm volatile("cp.async.wait_group 1;" ::: "memory")
#define CP_WAIT0()  asm volatile("cp.async.wait_group 0;" ::: "memory")

__device__ __forceinline__ void ldsm4(uint32_t* r, uint32_t a) {
    asm volatile("ldmatrix.sync.aligned.m8n8.x4.shared.b16 {%0,%1,%2,%3}, [%4];"
        : "=r"(r[0]), "=r"(r[1]), "=r"(r[2]), "=r"(r[3]) : "r"(a));
}
__device__ __forceinline__ void ldsm2(uint32_t* r, uint32_t a) {
    asm volatile("ldmatrix.sync.aligned.m8n8.x2.shared.b16 {%0,%1}, [%2];"
        : "=r"(r[0]), "=r"(r[1]) : "r"(a));
}
__device__ __forceinline__ void ldsm2t(uint32_t* r, uint32_t a) {
    asm volatile("ldmatrix.sync.aligned.m8n8.x2.trans.shared.b16 {%0,%1}, [%2];"
        : "=r"(r[0]), "=r"(r[1]) : "r"(a));
}
__device__ __forceinline__ void mma16816(float* c, const uint32_t* a, const uint32_t* b) {
    asm volatile("mma.sync.aligned.m16n8k16.row.col.f32.f16.f16.f32 "
        "{%0,%1,%2,%3}, {%4,%5,%6,%7}, {%8,%9}, {%0,%1,%2,%3};"
        : "+f"(c[0]), "+f"(c[1]), "+f"(c[2]), "+f"(c[3])
        : "r"(a[0]), "r"(a[1]), "r"(a[2]), "r"(a[3]), "r"(b[0]), "r"(b[1]));
}

// =====================================================================
// Conversion kernels
// =====================================================================
__global__ __launch_bounds__(256) void conv_split(const float* __restrict__ src,
                                                  __half* __restrict__ dh,
                                                  __half* __restrict__ dl,
                                                  int n4, float s)
{
    int i = blockIdx.x * blockDim.x + threadIdx.x;
    if (i >= n4) return;
    float4 v = ((const float4*)src)[i];
    float x0 = v.x * s, x1 = v.y * s, x2 = v.z * s, x3 = v.w * s;
    __half h0 = __float2half_rn(x0), h1 = __float2half_rn(x1);
    __half h2 = __float2half_rn(x2), h3 = __float2half_rn(x3);
    __half l0 = __float2half_rn(x0 - __half2float(h0));
    __half l1 = __float2half_rn(x1 - __half2float(h1));
    __half l2 = __float2half_rn(x2 - __half2float(h2));
    __half l3 = __float2half_rn(x3 - __half2float(h3));
    ((__half2*)dh)[2 * i]     = __halves2half2(h0, h1);
    ((__half2*)dh)[2 * i + 1] = __halves2half2(h2, h3);
    ((__half2*)dl)[2 * i]     = __halves2half2(l0, l1);
    ((__half2*)dl)[2 * i + 1] = __halves2half2(l2, l3);
}

__global__ __launch_bounds__(256) void conv_wkv_k(const float* __restrict__ ipw)
{
    const int row = blockIdx.x;
    const int col = threadIdx.x;
    float v = 0.f;
    if (row < 400 && col < 200) v = ipw[(size_t)(200 + row) * 200 + col] * 256.f;
    __half h = __float2half_rn(v);
    __half l = __float2half_rn(v - __half2float(h));
    g_wkvh[row * 256 + col] = h;
    g_wkvl[row * 256 + col] = l;
}

// generic 200x200 -> padded 256x256 hi/lo (for wq and out_w)
__global__ __launch_bounds__(256) void conv_w256(const float* __restrict__ W,
                                                 __half* __restrict__ dh,
                                                 __half* __restrict__ dl)
{
    const int row = blockIdx.x;
    const int col = threadIdx.x;
    float v = 0.f;
    if (row < 200 && col < 200) v = W[(size_t)row * 200 + col] * 256.f;
    __half h = __float2half_rn(v);
    __half l = __float2half_rn(v - __half2float(h));
    dh[row * 256 + col] = h;
    dl[row * 256 + col] = l;
}

// =====================================================================
// Router GEMM: 3-stage cp.async pipeline, M=128, N=128, kc=64, splitK=9
// =====================================================================
#define R_SMEM (3 * 65536)
__global__ __launch_bounds__(256) void router_mma(void)
{
    extern __shared__ char smc[];
    const uint32_t sb = smem_u32(smc);
    const int tid = threadIdx.x, lane = tid & 31, wid = tid >> 5;
    const int jt = blockIdx.x, mt = blockIdx.y, sp = blockIdx.z;
    const int b0 = mt * 128, j0 = jt * 128;
    const int wm = wid & 1, wn = wid >> 1;
    const int m_base = wm * 64, n_base = wn * 32;

    const int a_row  = (lane & 7) + ((lane >> 3) & 1) * 8;
    const int a_koff = (lane >> 4) * 16;
    const int bl_    = lane & 15;
    const int b_row  = bl_ & 7;
    const int b_koff = (bl_ >> 3) * 16;
    int rowbyteA[4], rowbyteB[4];
#pragma unroll
    for (int mi = 0; mi < 4; mi++) rowbyteA[mi] = (m_base + mi * 16 + a_row) * 128;
#pragma unroll
    for (int ni = 0; ni < 4; ni++) rowbyteB[ni] = (n_base + ni * 8 + b_row) * 128;
    const int swzA = (lane & 7) << 4;
    const int swzB = b_row << 4;

    float C[4][4][4];
#pragma unroll
    for (int a = 0; a < 4; a++)
#pragma unroll
        for (int b = 0; b < 4; b++)
#pragma unroll
            for (int c = 0; c < 4; c++) C[a][b][c] = 0.f;

    const int cbeg = sp * 111 + (sp > 0 ? 1 : 0);
    const int cnt  = 111 + (sp == 0 ? 1 : 0);

    auto issue_chunk = [&](int c, int p) {
        const int n = c / 200;
        const int rr = (c - n * 200) * 64;
        const __half* Ah = g_bh + (size_t)n * BAND_STRIDE + (size_t)b0 * ROW_STRIDE + rr;
        const __half* Al = g_bl + (size_t)n * BAND_STRIDE + (size_t)b0 * ROW_STRIDE + rr;
        const size_t f0 = (size_t)c * 64;
        const uint32_t so = sb + p * 65536;
#pragma unroll
        for (int j = 0; j < 4; j++) {
            const int u = tid + j * 256;
            const int row = u >> 3, uu = u & 7;
            const uint32_t d = row * 128 + ((uu * 16) ^ ((row & 7) << 4));
            cp16(so + d,         Ah + (size_t)row * ROW_STRIDE + uu * 8);
            cp16(so + 16384 + d, Al + (size_t)row * ROW_STRIDE + uu * 8);
            const __half* Bh = g_w1h + (size_t)(j0 + row) * FIN + f0 + uu * 8;
            const __half* Bl = g_w1l + (size_t)(j0 + row) * FIN + f0 + uu * 8;
            cp16(so + 32768 + d, Bh);
            cp16(so + 49152 + d, Bl);
        }
    };

    issue_chunk(cbeg, 0);     CP_COMMIT();
    issue_chunk(cbeg + 1, 1); CP_COMMIT();

    for (int c = 0; c < cnt; c++) {
        const int p = c % 3;
        if (c + 1 < cnt) CP_WAIT1(); else CP_WAIT0();
        __syncthreads();
        if (c + 2 < cnt) { issue_chunk(cbeg + c + 2, (c + 2) % 3); CP_COMMIT(); }
        const uint32_t so = sb + p * 65536;
#pragma unroll
        for (int ks = 0; ks < 4; ks++) {
            uint32_t bhf[4][2], blf[4][2];
#pragma unroll
            for (int ni = 0; ni < 4; ni++) {
                const uint32_t ad = so + 32768 + rowbyteB[ni] + ((ks * 32 + b_koff) ^ swzB);
                ldsm2(bhf[ni], ad);
                ldsm2(blf[ni], ad + 16384);
            }
#pragma unroll
            for (int mi = 0; mi < 4; mi++) {
                uint32_t ah[4], al[4];
                const uint32_t aa = so + rowbyteA[mi] + ((ks * 32 + a_koff) ^ swzA);
                ldsm4(ah, aa);
                ldsm4(al, aa + 16384);
#pragma unroll
                for (int ni = 0; ni < 4; ni++) {
                    mma16816(C[mi][ni], ah, bhf[ni]);
                    mma16816(C[mi][ni], ah, blf[ni]);
                    mma16816(C[mi][ni], al, bhf[ni]);
                }
            }
        }
    }

    const float invS = 1.f / 1024.f;
    float* outp = g_hpart + (size_t)sp * (BATCH * HID);
    const int g = lane >> 2, qp = lane & 3;
#pragma unroll
    for (int mi = 0; mi < 4; mi++) {
#pragma unroll
        for (int ni = 0; ni < 4; ni++) {
            const int row = b0 + m_base + mi * 16 + g;
            const int col = j0 + n_base + ni * 8 + qp * 2;
            *(float2*)(outp + (size_t)row * HID + col) =
                make_float2(C[mi][ni][0] * invS, C[mi][ni][1] * invS);
            *(float2*)(outp + (size_t)(row + 8) * HID + col) =
                make_float2(C[mi][ni][2] * invS, C[mi][ni][3] * invS);
        }
    }
}

// =====================================================================
// Router select
// =====================================================================
__global__ __launch_bounds__(128) void router_select(const float* __restrict__ b1,
                                                     const float* __restrict__ w2,
                                                     const float* __restrict__ b2)
{
    const int b = blockIdx.x, tid = threadIdx.x;
    float acc[NB] = {0.f, 0.f, 0.f, 0.f, 0.f};
    for (int j = tid; j < HID; j += 128) {
        float hv = b1[j];
#pragma unroll
        for (int s = 0; s < R_NSPLIT; s++)
            hv += g_hpart[(size_t)s * BATCH * HID + (size_t)b * HID + j];
        hv = fmaxf(hv, 0.f);
#pragma unroll
        for (int n = 0; n < NB; n++) acc[n] += hv * w2[n * HID + j];
    }
    __shared__ float red[NB][128];
#pragma unroll
    for (int n = 0; n < NB; n++) red[n][tid] = acc[n];
    __syncthreads();
    for (int s = 64; s > 0; s >>= 1) {
        if (tid < s) {
#pragma unroll
            for (int n = 0; n < NB; n++) red[n][tid] += red[n][tid + s];
        }
        __syncthreads();
    }
    if (tid == 0) {
        int best = 0;
        float bv = red[0][0] + b2[0];
        for (int n = 1; n < NB; n++) {
            float v = red[n][0] + b2[n];
            if (v > bv) { bv = v; best = n; }
        }
        g_sel[b] = best;
    }
}

// =====================================================================
// Q projection HMMA: per b, M=64, N=256(pad of 200), K=208 -> g_qh/g_ql
// =====================================================================
#define QM_AH 0
#define QM_AL 32768
#define QM_BH 65536
#define QM_BL 98304
#define QM_SMEM 131072
__global__ __launch_bounds__(256) void q_mma(const float* __restrict__ ipb)
{
    extern __shared__ char smc[];
    const uint32_t sb = smem_u32(smc);
    const int tid = threadIdx.x, lane = tid & 31, wid = tid >> 5;
    const int b = blockIdx.x;
    const int wm = wid & 1, wn = wid >> 1;
    const int m_base = wm * 32;

    for (int i = tid; i < 896; i += 256) {
        const int a = i / 448, rem = i % 448;
        const int r = rem / 7, u = 1 + rem % 7;
        const uint32_t off = (a ? QM_AL : QM_AH) + 3 * 8192 + r * 128 + ((u * 16) ^ ((r & 7) << 4));
        *(uint4*)(smc + off) = make_uint4(0, 0, 0, 0);
    }
    const size_t abase = (size_t)g_sel[b] * BAND_STRIDE + (size_t)b * ROW_STRIDE;
    for (int i = tid; i < 3200; i += 256) {
        const int a = i / 1600, rem = i % 1600;
        const int r = rem / 25, cu = rem % 25, ch = cu >> 3, u = cu & 7;
        const __half* src = (a ? g_bl : g_bh) + abase + (size_t)r * 200 + ch * 64 + u * 8;
        cp16(sb + (a ? QM_AL : QM_AH) + ch * 8192 + r * 128 + ((u * 16) ^ ((r & 7) << 4)), src);
    }
    CP_COMMIT();
    CP_WAIT0();

    const int a_row  = (lane & 7) + ((lane >> 3) & 1) * 8;
    const int a_koff = (lane >> 4) * 16;
    const int b_row  = lane & 7;
    const int b_koff = ((lane >> 3) & 1) * 16;

    float C[2][8][4];
#pragma unroll
    for (int a = 0; a < 2; a++)
#pragma unroll
        for (int n = 0; n < 8; n++)
#pragma unroll
            for (int c = 0; c < 4; c++) C[a][n][c] = 0.f;

    for (int ck = 0; ck < 4; ck++) {
        __syncthreads();
        for (int i = tid; i < 4096; i += 256) {
            const int a = i / 2048, rem = i % 2048;
            const int r = rem >> 3, u = rem & 7;
            const __half* src = (a ? g_wql : g_wqh) + (size_t)r * 256 + ck * 64 + u * 8;
            cp16(sb + (a ? QM_BL : QM_BH) + r * 128 + ((u * 16) ^ ((r & 7) << 4)), src);
        }
        CP_COMMIT();
        CP_WAIT0();
        __syncthreads();
        const int nks = (ck < 3) ? 4 : 1;
        for (int ks = 0; ks < nks; ks++) {
            uint32_t bhf[8][2], blf[8][2];
#pragma unroll
            for (int ni = 0; ni < 8; ni++) {
                const int nr = wn * 64 + ni * 8 + b_row;
                const uint32_t ad = sb + QM_BH + nr * 128 + ((ks * 32 + b_koff) ^ ((nr & 7) << 4));
                ldsm2(bhf[ni], ad);
                ldsm2(blf[ni], ad + 32768);
            }
#pragma unroll
            for (int mi = 0; mi < 2; mi++) {
                const int ar = m_base + mi * 16 + a_row;
                uint32_t ah[4], al[4];
                const uint32_t aa = sb + QM_AH + ck * 8192 + ar * 128 + ((ks * 32 + a_koff) ^ ((ar & 7) << 4));
                ldsm4(ah, aa);
                ldsm4(al, aa + 32768);
#pragma unroll
                for (int ni = 0; ni < 8; ni++) {
                    mma16816(C[mi][ni], ah, bhf[ni]);
                    mma16816(C[mi][ni], ah, blf[ni]);
                    mma16816(C[mi][ni], al, bhf[ni]);
                }
            }
        }
    }

    const int g = lane >> 2, qp = lane & 3;
    const float invS = 1.f / 1024.f;
#pragma unroll
    for (int mi = 0; mi < 2; mi++) {
#pragma unroll
        for (int ni = 0; ni < 8; ni++) {
            const int j = wn * 64 + ni * 8 + qp * 2;
#pragma unroll
            for (int e = 0; e < 2; e++) {
                const int jj = j + e;
                if (jj >= 200) continue;
                const int hh = jj / 50, dd = jj % 50;
                const float bia = __ldg(ipb + jj);
#pragma unroll
                for (int hf = 0; hf < 2; hf++) {
                    const int r = m_base + mi * 16 + g + hf * 8;
                    const float v = C[mi][ni][hf * 2 + e] * invS + bia;
                    const float v32 = v * 32.f;
                    const __half ph = __float2half_rn(v32);
                    const __half pl = __float2half_rn(v32 - __half2float(ph));
                    const size_t idx = ((size_t)(b * 4 + hh) * 64 + r) * 56 + dd;
                    g_qh[idx] = ph;
                    g_ql[idx] = pl;
                }
            }
        }
    }
    for (int i = tid; i < 1536; i += 256) {
        const int a = i / 768, rem = i % 768;
        const int hh = rem / 192, rem2 = rem % 192;
        const int t = rem2 / 3, uo = rem2 % 3;
        __half* base = a ? g_ql : g_qh;
        *((uint32_t*)(base + ((size_t)(b * 4 + hh) * 64 + t) * 56 + 50) + uo) = 0u;
    }
}

// =====================================================================
// K/V projection HMMA -> fp16 hi/lo head-split layout (R9 version)
// =====================================================================
#define KV_AH 0
#define KV_AL 65536
#define KV_BH 131072
#define KV_BL 163840
#define KV_BIAS 196608
#define KV_SMEM (196608 + 1664)
__global__ __launch_bounds__(256) void kv_mma(const float* __restrict__ ipb)
{
    extern __shared__ char smc[];
    const uint32_t sb = smem_u32(smc);
    const int tid = threadIdx.x, lane = tid & 31, wid = tid >> 5;
    const int n = blockIdx.x, bp = blockIdx.y;
    const int wm = wid & 1, wn = wid >> 1;
    const int m_base = wm * 64;

    float* bias = (float*)(smc + KV_BIAS);
    for (int i = tid; i < 400; i += 256) bias[i] = ipb[200 + i];

#pragma unroll
    for (int j = 0; j < 4; j++) {
        const int u = tid + j * 256;
        if (u < 896) {
            const int row = u / 7, uu = 1 + (u % 7);
            const uint32_t d = 3 * 16384 + row * 128 + ((uu * 16) ^ ((row & 7) << 4));
            *(uint4*)(smc + KV_AH + d) = make_uint4(0, 0, 0, 0);
            *(uint4*)(smc + KV_AL + d) = make_uint4(0, 0, 0, 0);
        }
    }
    {
        const size_t abase = (size_t)n * BAND_STRIDE + (size_t)(bp * 128) * 200;
#pragma unroll
        for (int j = 0; j < 13; j++) {
            const int u = tid + j * 256;
            if (u < 3200) {
                const int row = u / 25;
                const int rem = u - row * 25;
                const int ch = rem >> 3, uu = rem & 7;
                const uint32_t d = ch * 16384 + row * 128 + ((uu * 16) ^ ((row & 7) << 4));
                const size_t srow = abase + (size_t)row * 200 + ch * 64 + uu * 8;
                cp16(sb + KV_AH + d, g_bh + srow);
                cp16(sb + KV_AL + d, g_bl + srow);
            }
        }
        CP_COMMIT();
        CP_WAIT0();
    }
    __syncthreads();

    const int a_row  = (lane & 7) + ((lane >> 3) & 1) * 8;
    const int a_koff = (lane >> 4) * 16;
    const int bl_    = lane & 15;
    const int b_row  = bl_ & 7;
    const int b_koff = (bl_ >> 3) * 16;
    int rowbyteA[4], rowbyteB[2];
#pragma unroll
    for (int mi = 0; mi < 4; mi++) rowbyteA[mi] = (m_base + mi * 16 + a_row) * 128;
#pragma unroll
    for (int ni = 0; ni < 2; ni++) rowbyteB[ni] = (wn * 16 + ni * 8 + b_row) * 128;
    const int swzA = (lane & 7) << 4;
    const int swzB = b_row << 4;
    const int g = lane >> 2, qp = lane & 3;
    const float invS = 1.f / 1024.f;

    for (int nt = 0; nt < 7; nt++) {
        __syncthreads();
#pragma unroll
        for (int j = 0; j < 8; j++) {
            const int u = tid + j * 256;
            const int lr = u >> 5;
            const int rem = u & 31;
            const int ch = rem >> 3, uu = rem & 7;
            const int nr = nt * 64 + lr;
            const uint4 vh = *(const uint4*)(g_wkvh + (size_t)nr * 256 + ch * 64 + uu * 8);
            const uint4 vl = *(const uint4*)(g_wkvl + (size_t)nr * 256 + ch * 64 + uu * 8);
            const uint32_t d = ch * 8192 + lr * 128 + ((uu * 16) ^ ((lr & 7) << 4));
            *(uint4*)(smc + KV_BH + d) = vh;
            *(uint4*)(smc + KV_BL + d) = vl;
        }
        __syncthreads();

        float C[4][2][4];
#pragma unroll
        for (int a = 0; a < 4; a++)
#pragma unroll
            for (int b = 0; b < 2; b++)
#pragma unroll
                for (int c = 0; c < 4; c++) C[a][b][c] = 0.f;

        for (int ks = 0; ks < 13; ks++) {
            const int ch = ks >> 2, ki = ks & 3;
            uint32_t bhf[2][2], blf[2][2];
#pragma unroll
            for (int ni = 0; ni < 2; ni++) {
                const uint32_t ad = sb + KV_BH + ch * 8192 + rowbyteB[ni] + ((ki * 32 + b_koff) ^ swzB);
                ldsm2(bhf[ni], ad);
                ldsm2(blf[ni], ad + 32768);
            }
#pragma unroll
            for (int mi = 0; mi < 4; mi++) {
                uint32_t ah[4], al[4];
                const uint32_t aa = sb + KV_AH + ch * 16384 + rowbyteA[mi] + ((ki * 32 + a_koff) ^ swzA);
                ldsm4(ah, aa);
                ldsm4(al, aa + 65536);
#pragma unroll
                for (int ni = 0; ni < 2; ni++) {
                    mma16816(C[mi][ni], ah, bhf[ni]);
                    mma16816(C[mi][ni], ah, blf[ni]);
                    mma16816(C[mi][ni], al, bhf[ni]);
                }
            }
        }

#pragma unroll
        for (int mi = 0; mi < 4; mi++) {
#pragma unroll
            for (int ni = 0; ni < 2; ni++) {
                const int col = nt * 64 + wn * 16 + ni * 8 + qp * 2;
#pragma unroll
                for (int e = 0; e < 2; e++) {
                    const int ce = col + e;
                    if (ce >= 400) continue;
                    const float bia = bias[ce];
                    const int isV = (ce >= 200);
                    const int c2 = isV ? (ce - 200) : ce;
                    const int hh = c2 / 50, dd = c2 % 50;
                    __half* dsth = isV ? g_vh : g_kh;
                    __half* dstl = isV ? g_vl : g_kl;
#pragma unroll
                    for (int hf = 0; hf < 2; hf++) {
                        const int r = m_base + mi * 16 + g + hf * 8;
                        const int b = 2 * bp + (r >> 6);
                        const int tloc = n * 64 + (r & 63);
                        const float v = C[mi][ni][hf * 2 + e] * invS + bia;
                        const float v32 = v * 32.f;
                        const __half ph = __float2half_rn(v32);
                        const __half pl = __float2half_rn(v32 - __half2float(ph));
                        const size_t idx = ((size_t)(b * 4 + hh) * 320 + tloc) * 56 + dd;
                        dsth[idx] = ph;
                        dstl[idx] = pl;
                    }
                }
            }
        }
    }
    for (int i = tid; i < 6144; i += 256) {
        const int a = i / 1536, rem = i % 1536;
        const int bb = rem / 768, rem2 = rem % 768;
        const int hh = rem2 / 192, rem3 = rem2 % 192;
        const int tt = rem3 / 3, uo = rem3 % 3;
        const int bg = 2 * bp + bb;
        const int t = n * 64 + tt;
        __half* base = (a == 0) ? g_kh : (a == 1) ? g_kl : (a == 2) ? g_vh : g_vl;
        *((uint32_t*)(base + ((size_t)(bg * 4 + hh) * 320 + t) * 56 + 50) + uo) = 0u;
    }
}

// =====================================================================
// Attention HMMA v2: full prefetch (Q,K group + V group), register softmax
// (R9 version — P stored hi/lo, 3-term PV)
// =====================================================================
#define AT_QH 0
#define AT_QL 8192
#define AT_KH 16384      // later P hi
#define AT_KL 57344      // later P lo
#define AT_VH 98304
#define AT_VL 139264
#define AT_RED  180224   // 128 floats
#define AT_RED2 180736   // 128 floats
#define AT_SMEM 181248
__global__ __launch_bounds__(256) void attn_mma()
{
    extern __shared__ char smc[];
    const uint32_t sb = smem_u32(smc);
    const int tid = threadIdx.x, lane = tid & 31, wid = tid >> 5;
    const int h = blockIdx.x, b = blockIdx.y;
    const size_t kvbase = ((size_t)b * 4 + h) * 320;
    const size_t qbase  = ((size_t)b * 4 + h) * 64;

    for (int i = tid; i < 768; i += 256) {
        uint32_t base; int row;
        if (i < 64)       { base = AT_QH; row = i; }
        else if (i < 128) { base = AT_QL; row = i - 64; }
        else if (i < 448) { base = AT_KH; row = i - 128; }
        else              { base = AT_KL; row = i - 448; }
        *(uint4*)(smc + base + row * 128 + (112 ^ ((row & 7) << 4))) = make_uint4(0, 0, 0, 0);
    }
    for (int i = tid; i < 896; i += 256) {
        const int a = i / 448, rem = i % 448;
        const int r = rem / 7, u = rem % 7;
        const __half* src = (a ? g_ql : g_qh) + (qbase + r) * 56 + u * 8;
        cp16(sb + (a ? AT_QL : AT_QH) + r * 128 + ((u * 16) ^ ((r & 7) << 4)), src);
    }
    for (int i = tid; i < 4480; i += 256) {
        const int a = i / 2240, rem = i % 2240;
        const int r = rem / 7, u = rem % 7;
        const __half* src = (a ? g_kl : g_kh) + (kvbase + r) * 56 + u * 8;
        cp16(sb + (a ? AT_KL : AT_KH) + r * 128 + ((u * 16) ^ ((r & 7) << 4)), src);
    }
    CP_COMMIT();
    for (int i = tid; i < 4480; i += 256) {
        const int a = i / 2240, rem = i % 2240;
        const int r = rem / 7, u = rem % 7;
        const __half* src = (a ? g_vl : g_vh) + (kvbase + r) * 56 + u * 8;
        cp16(sb + (a ? AT_VL : AT_VH) + r * 128 + ((u * 16) ^ ((r & 7) << 4)), src);
    }
    CP_COMMIT();
    CP_WAIT1();
    __syncthreads();

    // ---- QK^T ----
    const int wm = wid & 3, wn = wid >> 2;
    const int m_base = wm * 16, n_base = wn * 160;
    const int a_row  = m_base + (lane & 7) + ((lane >> 3) & 1) * 8;
    const int a_koff = (lane >> 4) * 16;
    const int b_row  = lane & 7;
    const int b_koff = ((lane >> 3) & 1) * 16;
    const int g = lane >> 2, qp = lane & 3;

    float C[20][4];
#pragma unroll
    for (int i = 0; i < 20; i++)
#pragma unroll
        for (int j = 0; j < 4; j++) C[i][j] = 0.f;

#pragma unroll
    for (int ks = 0; ks < 4; ks++) {
        uint32_t qh4[4], ql4[4];
        const uint32_t aoff = a_row * 128 + ((ks * 32 + a_koff) ^ ((a_row & 7) << 4));
        ldsm4(qh4, sb + AT_QH + aoff);
        ldsm4(ql4, sb + AT_QL + aoff);
#pragma unroll
        for (int ni = 0; ni < 20; ni++) {
            const int trow = n_base + ni * 8 + b_row;
            const uint32_t boff = trow * 128 + ((ks * 32 + b_koff) ^ ((trow & 7) << 4));
            uint32_t kh2[2], kl2[2];
            ldsm2(kh2, sb + AT_KH + boff);
            ldsm2(kl2, sb + AT_KL + boff);
            mma16816(C[ni], qh4, kh2);
            mma16816(C[ni], qh4, kl2);
            mma16816(C[ni], ql4, kh2);
        }
    }

    // ---- register softmax ----
    const float sc = 0.14142135623730951f / 1024.f;
#pragma unroll
    for (int ni = 0; ni < 20; ni++)
#pragma unroll
        for (int j = 0; j < 4; j++) C[ni][j] *= sc;

    float* RED1 = (float*)(smc + AT_RED);
    float* RED2 = (float*)(smc + AT_RED2);
    const int r0 = m_base + g;

    float m0 = -1e30f, m1 = -1e30f;
#pragma unroll
    for (int ni = 0; ni < 20; ni++) {
        m0 = fmaxf(m0, fmaxf(C[ni][0], C[ni][1]));
        m1 = fmaxf(m1, fmaxf(C[ni][2], C[ni][3]));
    }
    m0 = fmaxf(m0, __shfl_xor_sync(0xffffffffu, m0, 1));
    m0 = fmaxf(m0, __shfl_xor_sync(0xffffffffu, m0, 2));
    m1 = fmaxf(m1, __shfl_xor_sync(0xffffffffu, m1, 1));
    m1 = fmaxf(m1, __shfl_xor_sync(0xffffffffu, m1, 2));
    if (qp == 0) { RED1[wn * 64 + r0] = m0; RED1[wn * 64 + r0 + 8] = m1; }
    __syncthreads();
    const float M0 = fmaxf(RED1[r0], RED1[64 + r0]);
    const float M1 = fmaxf(RED1[r0 + 8], RED1[64 + r0 + 8]);

    float s0 = 0.f, s1 = 0.f;
#pragma unroll
    for (int ni = 0; ni < 20; ni++) {
        C[ni][0] = __expf(C[ni][0] - M0); s0 += C[ni][0];
        C[ni][1] = __expf(C[ni][1] - M0); s0 += C[ni][1];
        C[ni][2] = __expf(C[ni][2] - M1); s1 += C[ni][2];
        C[ni][3] = __expf(C[ni][3] - M1); s1 += C[ni][3];
    }
    s0 += __shfl_xor_sync(0xffffffffu, s0, 1);
    s0 += __shfl_xor_sync(0xffffffffu, s0, 2);
    s1 += __shfl_xor_sync(0xffffffffu, s1, 1);
    s1 += __shfl_xor_sync(0xffffffffu, s1, 2);
    if (qp == 0) { RED2[wn * 64 + r0] = s0; RED2[wn * 64 + r0 + 8] = s1; }
    __syncthreads();
    const float i0 = 1.f / (RED2[r0] + RED2[64 + r0]);
    const float i1 = 1.f / (RED2[r0 + 8] + RED2[64 + r0 + 8]);

    // P hi/lo directly from registers into K region (ldmatrix layout, row=640B)
    {
        const uint32_t sw0 = (r0 & 7) << 4;
        const uint32_t sw1 = ((r0 + 8) & 7) << 4;
#pragma unroll
        for (int ni = 0; ni < 20; ni++) {
            const int col = n_base + ni * 8 + qp * 2;
            const uint32_t ub = (col >> 3) * 16;
            const uint32_t off0 = r0 * 640 + (ub ^ sw0) + (col & 7) * 2;
            const uint32_t off1 = (r0 + 8) * 640 + (ub ^ sw1) + (col & 7) * 2;
            const float p0 = C[ni][0] * i0, p1 = C[ni][1] * i0;
            const float p2 = C[ni][2] * i1, p3 = C[ni][3] * i1;
            const __half h0 = __float2half_rn(p0), h1 = __float2half_rn(p1);
            const __half h2 = __float2half_rn(p2), h3 = __float2half_rn(p3);
            *(__half2*)(smc + AT_KH + off0) = __halves2half2(h0, h1);
            *(__half2*)(smc + AT_KL + off0) =
                __halves2half2(__float2half_rn(p0 - __half2float(h0)),
                               __float2half_rn(p1 - __half2float(h1)));
            *(__half2*)(smc + AT_KH + off1) = __halves2half2(h2, h3);
            *(__half2*)(smc + AT_KL + off1) =
                __halves2half2(__float2half_rn(p2 - __half2float(h2)),
                               __float2half_rn(p3 - __half2float(h3)));
        }
    }
    CP_WAIT0();
    __syncthreads();

    // ---- P @ V ----
    const int wnv = wid >> 2;
    const int mv_base = (wid & 3) * 16;
    const int nv_base = wnv * 32;
    const int ntc = wnv ? 3 : 4;
    const int p_row = mv_base + (lane & 7) + ((lane >> 3) & 1) * 8;
    const int p_unit = lane >> 4;
    const int v_koff = (lane & 7) + ((lane >> 3) & 1) * 8;

    float O[4][4];
#pragma unroll
    for (int i = 0; i < 4; i++)
#pragma unroll
        for (int j = 0; j < 4; j++) O[i][j] = 0.f;

    for (int ks = 0; ks < 20; ks++) {
        uint32_t ph4[4], pl4[4];
        const uint32_t poff = p_row * 640 + (((ks * 2 + p_unit) * 16) ^ ((p_row & 7) << 4));
        ldsm4(ph4, sb + AT_KH + poff);
        ldsm4(pl4, sb + AT_KL + poff);
        const int krow = ks * 16 + v_koff;
        const uint32_t swk = (krow & 7) << 4;
#pragma unroll
        for (int nt = 0; nt < 4; nt++) {
            if (nt >= ntc) break;
            const int ncol = nv_base + nt * 8;
            const uint32_t voff = krow * 128 + ((ncol * 2) ^ swk);
            uint32_t vh2[2], vl2[2];
            ldsm2t(vh2, sb + AT_VH + voff);
            ldsm2t(vl2, sb + AT_VL + voff);
            mma16816(O[nt], ph4, vh2);
            mma16816(O[nt], ph4, vl2);
            mma16816(O[nt], pl4, vh2);
        }
    }

    // O (scale 32) -> fp16 hi/lo for out projection
#pragma unroll
    for (int nt = 0; nt < 4; nt++) {
        if (nt >= ntc) break;
        const int d = nv_base + nt * 8 + qp * 2;
        if (d >= 50) continue;
#pragma unroll
        for (int hf = 0; hf < 2; hf++) {
            const int r = mv_base + g + hf * 8;
            const float o0 = O[nt][hf * 2 + 0];
            const float o1 = O[nt][hf * 2 + 1];
            const __half h0 = __float2half_rn(o0), h1 = __float2half_rn(o1);
            const size_t idx = ((size_t)b * 64 + r) * 200 + h * 50 + d;
            *(__half2*)(g_oh + idx) = __halves2half2(h0, h1);
            *(__half2*)(g_ol + idx) =
                __halves2half2(__float2half_rn(o0 - __half2float(h0)),
                               __float2half_rn(o1 - __half2float(h1)));
        }
    }
}

// =====================================================================
// Out projection HMMA: per b, M=64, N=256(pad 200), K=208, fp32 out
// =====================================================================
__global__ __launch_bounds__(256) void out_mma(const float* __restrict__ ob,
                                               float* __restrict__ outp)
{
    extern __shared__ char smc[];
    const uint32_t sb = smem_u32(smc);
    const int tid = threadIdx.x, lane = tid & 31, wid = tid >> 5;
    const int b = blockIdx.x;
    const int wm = wid & 1, wn = wid >> 1;
    const int m_base = wm * 32;

    for (int i = tid; i < 896; i += 256) {
        const int a = i / 448, rem = i % 448;
        const int r = rem / 7, u = 1 + rem % 7;
        const uint32_t off = (a ? QM_AL : QM_AH) + 3 * 8192 + r * 128 + ((u * 16) ^ ((r & 7) << 4));
        *(uint4*)(smc + off) = make_uint4(0, 0, 0, 0);
    }
    const size_t abase = (size_t)b * 64 * 200;
    for (int i = tid; i < 3200; i += 256) {
        const int a = i / 1600, rem = i % 1600;
        const int r = rem / 25, cu = rem % 25, ch = cu >> 3, u = cu & 7;
        const __half* src = (a ? g_ol : g_oh) + abase + (size_t)r * 200 + ch * 64 + u * 8;
        cp16(sb + (a ? QM_AL : QM_AH) + ch * 8192 + r * 128 + ((u * 16) ^ ((r & 7) << 4)), src);
    }
    CP_COMMIT();
    CP_WAIT0();

    const int a_row  = (lane & 7) + ((lane >> 3) & 1) * 8;
    const int a_koff = (lane >> 4) * 16;
    const int b_row  = lane & 7;
    const int b_koff = ((lane >> 3) & 1) * 16;

    float C[2][8][4];
#pragma unroll
    for (int a = 0; a < 2; a++)
#pragma unroll
        for (int n = 0; n < 8; n++)
#pragma unroll
            for (int c = 0; c < 4; c++) C[a][n][c] = 0.f;

    for (int ck = 0; ck < 4; ck++) {
        __syncthreads();
        for (int i = tid; i < 4096; i += 256) {
            const int a = i / 2048, rem = i % 2048;
            const int r = rem >> 3, u = rem & 7;
            const __half* src = (a ? g_wol : g_woh) + (size_t)r * 256 + ck * 64 + u * 8;
            cp16(sb + (a ? QM_BL : QM_BH) + r * 128 + ((u * 16) ^ ((r & 7) << 4)), src);
        }
        CP_COMMIT();
        CP_WAIT0();
        __syncthreads();
        const int nks = (ck < 3) ? 4 : 1;
        for (int ks = 0; ks < nks; ks++) {
            uint32_t bhf[8][2], blf[8][2];
#pragma unroll
            for (int ni = 0; ni < 8; ni++) {
                const int nr = wn * 64 + ni * 8 + b_row;
                const uint32_t ad = sb + QM_BH + nr * 128 + ((ks * 32 + b_koff) ^ ((nr & 7) << 4));
                ldsm2(bhf[ni], ad);
                ldsm2(blf[ni], ad + 32768);
            }
#pragma unroll
            for (int mi = 0; mi < 2; mi++) {
                const int ar = m_base + mi * 16 + a_row;
                uint32_t ah[4], al[4];
                const uint32_t aa = sb + QM_AH + ck * 8192 + ar * 128 + ((ks * 32 + a_koff) ^ ((ar & 7) << 4));
                ldsm4(ah, aa);
                ldsm4(al, aa + 32768);
#pragma unroll
                for (int ni = 0; ni < 8; ni++) {
                    mma16816(C[mi][ni], ah, bhf[ni]);
                    mma16816(C[mi][ni], ah, blf[ni]);
                    mma16816(C[mi][ni], al, bhf[ni]);
                }
            }
        }
    }

    const int g = lane >> 2, qp = lane & 3;
    const float invS = 1.f / 8192.f;
#pragma unroll
    for (int mi = 0; mi < 2; mi++) {
#pragma unroll
        for (int ni = 0; ni < 8; ni++) {
            const int jj = wn * 64 + ni * 8 + qp * 2;
            if (jj >= 200) continue;
            const float b0 = __ldg(ob + jj), b1 = __ldg(ob + jj + 1);
#pragma unroll
            for (int hf = 0; hf < 2; hf++) {
                const int r = m_base + mi * 16 + g + hf * 8;
                *(float2*)(outp + ((size_t)b * 64 + r) * 200 + jj) =
                    make_float2(C[mi][ni][hf * 2 + 0] * invS + b0,
                                C[mi][ni][hf * 2 + 1] * invS + b1);
            }
        }
    }
}

// =====================================================================
// launch: fork kv-chain and w1-conversion onto side streams
// =====================================================================
struct LaunchRes {
    cudaStream_t s1, s2;
    cudaEvent_t e0, eA, eW1, eKV;
    LaunchRes() {
        cudaStreamCreateWithFlags(&s1, cudaStreamNonBlocking);
        cudaStreamCreateWithFlags(&s2, cudaStreamNonBlocking);
        cudaEventCreateWithFlags(&e0,  cudaEventDisableTiming);
        cudaEventCreateWithFlags(&eA,  cudaEventDisableTiming);
        cudaEventCreateWithFlags(&eW1, cudaEventDisableTiming);
        cudaEventCreateWithFlags(&eKV, cudaEventDisableTiming);
    }
};

extern "C" void kernel_launch(void* const* d_in, const int* in_sizes, int n_in,
                              void* d_out, int out_size)
{
    const float* bands = (const float*)d_in[0];
    const float* w1    = (const float*)d_in[1];
    const float* b1    = (const float*)d_in[2];
    const float* w2    = (const float*)d_in[3];
    const float* b2    = (const float*)d_in[4];
    const float* ipw   = (const float*)d_in[5];
    const float* ipb   = (const float*)d_in[6];
    const float* ow    = (const float*)d_in[7];
    const float* ob    = (const float*)d_in[8];
    float* outp = (float*)d_out;

    static LaunchRes R;   // streams/events created once (host-side only)

    cudaFuncSetAttribute(router_mma, cudaFuncAttributeMaxDynamicSharedMemorySize, R_SMEM);
    cudaFuncSetAttribute(kv_mma, cudaFuncAttributeMaxDynamicSharedMemorySize, KV_SMEM);
    cudaFuncSetAttribute(q_mma, cudaFuncAttributeMaxDynamicSharedMemorySize, QM_SMEM);
    cudaFuncSetAttribute(out_mma, cudaFuncAttributeMaxDynamicSharedMemorySize, QM_SMEM);
    cudaFuncSetAttribute(attn_mma, cudaFuncAttributeMaxDynamicSharedMemorySize, AT_SMEM);

    __half *bh, *blp, *w1h, *w1l, *wqh, *wql, *woh, *wol;
    cudaGetSymbolAddress((void**)&bh,  g_bh);
    cudaGetSymbolAddress((void**)&blp, g_bl);
    cudaGetSymbolAddress((void**)&w1h, g_w1h);
    cudaGetSymbolAddress((void**)&w1l, g_w1l);
    cudaGetSymbolAddress((void**)&wqh, g_wqh);
    cudaGetSymbolAddress((void**)&wql, g_wql);
    cudaGetSymbolAddress((void**)&woh, g_woh);
    cudaGetSymbolAddress((void**)&wol, g_wol);

    const int n4 = (NB * (int)BAND_STRIDE) / 4;

    // fork point
    cudaEventRecord(R.e0, 0);
    cudaStreamWaitEvent(R.s1, R.e0, 0);
    cudaStreamWaitEvent(R.s2, R.e0, 0);

    // s2: w1 conversion (independent of bands)
    conv_split<<<(n4 + 255) / 256, 256, 0, R.s2>>>(w1, w1h, w1l, n4, 256.f);
    cudaEventRecord(R.eW1, R.s2);

    // s1: kv weight conversion (needs only ipw)
    conv_wkv_k<<<448, 256, 0, R.s1>>>(ipw);

    // default: bands conversion + small weight convs
    conv_split<<<(n4 + 255) / 256, 256>>>(bands, bh, blp, n4, 4.f);
    cudaEventRecord(R.eA, 0);
    conv_w256<<<256, 256>>>(ipw, wqh, wql);
    conv_w256<<<256, 256>>>(ow, woh, wol);

    // s1: kv projection once bands fp16 is ready
    cudaStreamWaitEvent(R.s1, R.eA, 0);
    kv_mma<<<dim3(NB, BATCH / 2), 256, KV_SMEM, R.s1>>>(ipb);
    cudaEventRecord(R.eKV, R.s1);

    // default: router chain (needs w1 conversion from s2)
    cudaStreamWaitEvent(0, R.eW1, 0);
    router_mma   <<<dim3(4, 4, R_NSPLIT), 256, R_SMEM>>>();
    router_select<<<BATCH, 128>>>(b1, w2, b2);
    q_mma        <<<BATCH, 256, QM_SMEM>>>(ipb);

    // join kv chain, then attention + output
    cudaStreamWaitEvent(0, R.eKV, 0);
    attn_mma<<<dim3(HEADS, BATCH), 256, AT_SMEM>>>();
    out_mma <<<BATCH, 256, QM_SMEM>>>(ob, outp);
}

// round 13
// speedup vs baseline: 1.5079x; 1.4518x over previous
#include <cuda_runtime.h>
#include <cuda_fp16.h>
#include <cstdint>
#include <math.h>

// ---------------- problem constants ----------------
#define NB 5
#define BATCH 512
#define KQ 64
#define D 200
#define HEADS 4
#define HD 50
#define TKV 320
#define HID 512
#define FIN 64000
#define BAND_STRIDE 6553600ull   // BATCH*KQ*D (elements)
#define ROW_STRIDE 12800         // KQ*D
#define R_NSPLIT 9

// ---------------- scratch ----------------
__device__ float  g_hpart[(size_t)R_NSPLIT * BATCH * HID];
__device__ int    g_sel[BATCH];
__device__ __half g_bh [(size_t)NB * BAND_STRIDE];   // bands * 4, hi
__device__ __half g_bl [(size_t)NB * BAND_STRIDE];   // bands * 4, lo
__device__ __half g_w1h[(size_t)HID * FIN];          // w1 * 256, hi
__device__ __half g_w1l[(size_t)HID * FIN];          // w1 * 256, lo
__device__ __half g_wkvh[448 * 256];                 // wk|wv * 256 padded, hi
__device__ __half g_wkvl[448 * 256];                 // lo
__device__ __half g_wqh[256 * 256];                  // wq * 256 padded, hi
__device__ __half g_wql[256 * 256];                  // lo
__device__ __half g_woh[256 * 256];                  // out_w * 256 padded, hi
__device__ __half g_wol[256 * 256];                  // lo
// head-split padded layouts, values scaled *32, pad cols 50..55 zero (single fp16)
__device__ __half g_qh[(size_t)BATCH * HEADS * 64 * 56];
__device__ __half g_kh[(size_t)BATCH * HEADS * 320 * 56];
__device__ __half g_vh[(size_t)BATCH * HEADS * 320 * 56];
// attention output, scaled *32, [b*64][200], hi/lo
__device__ __half g_oh[(size_t)BATCH * KQ * D];
__device__ __half g_ol[(size_t)BATCH * KQ * D];

// =====================================================================
// helpers
// =====================================================================
__device__ __forceinline__ uint32_t smem_u32(const void* p) {
    uint32_t a;
    asm("{ .reg .u64 t; cvta.to.shared.u64 t, %1; cvt.u32.u64 %0, t; }" : "=r"(a) : "l"(p));
    return a;
}
__device__ __forceinline__ void cp16(uint32_t dst, const void* src) {
    asm volatile("cp.async.cg.shared.global [%0], [%1], 16;" :: "r"(dst), "l"(src));
}
#define CP_COMMIT() asm volatile("cp.async.commit_group;" ::: "memory")
#define CP_WAIT1()  asm volatile("cp.async.wait_group 1;" ::: "memory")
#define CP_WAIT0()  asm volatile("cp.async.wait_group 0;" ::: "memory")

__device__ __forceinline__ void ldsm4(uint32_t* r, uint32_t a) {
    asm volatile("ldmatrix.sync.aligned.m8n8.x4.shared.b16 {%0,%1,%2,%3}, [%4];"
        : "=r"(r[0]), "=r"(r[1]), "=r"(r[2]), "=r"(r[3]) : "r"(a));
}
__device__ __forceinline__ void ldsm2(uint32_t* r, uint32_t a) {
    asm volatile("ldmatrix.sync.aligned.m8n8.x2.shared.b16 {%0,%1}, [%2];"
        : "=r"(r[0]), "=r"(r[1]) : "r"(a));
}
__device__ __forceinline__ void ldsm2t(uint32_t* r, uint32_t a) {
    asm volatile("ldmatrix.sync.aligned.m8n8.x2.trans.shared.b16 {%0,%1}, [%2];"
        : "=r"(r[0]), "=r"(r[1]) : "r"(a));
}
__device__ __forceinline__ void mma16816(float* c, const uint32_t* a, const uint32_t* b) {
    asm volatile("mma.sync.aligned.m16n8k16.row.col.f32.f16.f16.f32 "
        "{%0,%1,%2,%3}, {%4,%5,%6,%7}, {%8,%9}, {%0,%1,%2,%3};"
        : "+f"(c[0]), "+f"(c[1]), "+f"(c[2]), "+f"(c[3])
        : "r"(a[0]), "r"(a[1]), "r"(a[2]), "r"(a[3]), "r"(b[0]), "r"(b[1]));
}

// =====================================================================
// Conversion kernels
// =====================================================================
__global__ __launch_bounds__(256) void conv_split(const float* __restrict__ src,
                                                  __half* __restrict__ dh,
                                                  __half* __restrict__ dl,
                                                  int n4, float s)
{
    int i = blockIdx.x * blockDim.x + threadIdx.x;
    if (i >= n4) return;
    float4 v = ((const float4*)src)[i];
    float x0 = v.x * s, x1 = v.y * s, x2 = v.z * s, x3 = v.w * s;
    __half h0 = __float2half_rn(x0), h1 = __float2half_rn(x1);
    __half h2 = __float2half_rn(x2), h3 = __float2half_rn(x3);
    __half l0 = __float2half_rn(x0 - __half2float(h0));
    __half l1 = __float2half_rn(x1 - __half2float(h1));
    __half l2 = __float2half_rn(x2 - __half2float(h2));
    __half l3 = __float2half_rn(x3 - __half2float(h3));
    ((__half2*)dh)[2 * i]     = __halves2half2(h0, h1);
    ((__half2*)dh)[2 * i + 1] = __halves2half2(h2, h3);
    ((__half2*)dl)[2 * i]     = __halves2half2(l0, l1);
    ((__half2*)dl)[2 * i + 1] = __halves2half2(l2, l3);
}

__global__ __launch_bounds__(256) void conv_wkv_k(const float* __restrict__ ipw)
{
    const int row = blockIdx.x;
    const int col = threadIdx.x;
    float v = 0.f;
    if (row < 400 && col < 200) v = ipw[(size_t)(200 + row) * 200 + col] * 256.f;
    __half h = __float2half_rn(v);
    __half l = __float2half_rn(v - __half2float(h));
    g_wkvh[row * 256 + col] = h;
    g_wkvl[row * 256 + col] = l;
}

__global__ __launch_bounds__(256) void conv_w256(const float* __restrict__ W,
                                                 __half* __restrict__ dh,
                                                 __half* __restrict__ dl)
{
    const int row = blockIdx.x;
    const int col = threadIdx.x;
    float v = 0.f;
    if (row < 200 && col < 200) v = W[(size_t)row * 200 + col] * 256.f;
    __half h = __float2half_rn(v);
    __half l = __float2half_rn(v - __half2float(h));
    dh[row * 256 + col] = h;
    dl[row * 256 + col] = l;
}

// =====================================================================
// Router GEMM: 3-stage cp.async pipeline, M=128, N=128, kc=64, splitK=9
// (full 3-term split — argmax precision is critical)
// =====================================================================
#define R_SMEM (3 * 65536)
__global__ __launch_bounds__(256) void router_mma(void)
{
    extern __shared__ char smc[];
    const uint32_t sb = smem_u32(smc);
    const int tid = threadIdx.x, lane = tid & 31, wid = tid >> 5;
    const int jt = blockIdx.x, mt = blockIdx.y, sp = blockIdx.z;
    const int b0 = mt * 128, j0 = jt * 128;
    const int wm = wid & 1, wn = wid >> 1;
    const int m_base = wm * 64, n_base = wn * 32;

    const int a_row  = (lane & 7) + ((lane >> 3) & 1) * 8;
    const int a_koff = (lane >> 4) * 16;
    const int bl_    = lane & 15;
    const int b_row  = bl_ & 7;
    const int b_koff = (bl_ >> 3) * 16;
    int rowbyteA[4], rowbyteB[4];
#pragma unroll
    for (int mi = 0; mi < 4; mi++) rowbyteA[mi] = (m_base + mi * 16 + a_row) * 128;
#pragma unroll
    for (int ni = 0; ni < 4; ni++) rowbyteB[ni] = (n_base + ni * 8 + b_row) * 128;
    const int swzA = (lane & 7) << 4;
    const int swzB = b_row << 4;

    float C[4][4][4];
#pragma unroll
    for (int a = 0; a < 4; a++)
#pragma unroll
        for (int b = 0; b < 4; b++)
#pragma unroll
            for (int c = 0; c < 4; c++) C[a][b][c] = 0.f;

    const int cbeg = sp * 111 + (sp > 0 ? 1 : 0);
    const int cnt  = 111 + (sp == 0 ? 1 : 0);

    auto issue_chunk = [&](int c, int p) {
        const int n = c / 200;
        const int rr = (c - n * 200) * 64;
        const __half* Ah = g_bh + (size_t)n * BAND_STRIDE + (size_t)b0 * ROW_STRIDE + rr;
        const __half* Al = g_bl + (size_t)n * BAND_STRIDE + (size_t)b0 * ROW_STRIDE + rr;
        const size_t f0 = (size_t)c * 64;
        const uint32_t so = sb + p * 65536;
#pragma unroll
        for (int j = 0; j < 4; j++) {
            const int u = tid + j * 256;
            const int row = u >> 3, uu = u & 7;
            const uint32_t d = row * 128 + ((uu * 16) ^ ((row & 7) << 4));
            cp16(so + d,         Ah + (size_t)row * ROW_STRIDE + uu * 8);
            cp16(so + 16384 + d, Al + (size_t)row * ROW_STRIDE + uu * 8);
            const __half* Bh = g_w1h + (size_t)(j0 + row) * FIN + f0 + uu * 8;
            const __half* Bl = g_w1l + (size_t)(j0 + row) * FIN + f0 + uu * 8;
            cp16(so + 32768 + d, Bh);
            cp16(so + 49152 + d, Bl);
        }
    };

    issue_chunk(cbeg, 0);     CP_COMMIT();
    issue_chunk(cbeg + 1, 1); CP_COMMIT();

    for (int c = 0; c < cnt; c++) {
        const int p = c % 3;
        if (c + 1 < cnt) CP_WAIT1(); else CP_WAIT0();
        __syncthreads();
        if (c + 2 < cnt) { issue_chunk(cbeg + c + 2, (c + 2) % 3); CP_COMMIT(); }
        const uint32_t so = sb + p * 65536;
#pragma unroll
        for (int ks = 0; ks < 4; ks++) {
            uint32_t bhf[4][2], blf[4][2];
#pragma unroll
            for (int ni = 0; ni < 4; ni++) {
                const uint32_t ad = so + 32768 + rowbyteB[ni] + ((ks * 32 + b_koff) ^ swzB);
                ldsm2(bhf[ni], ad);
                ldsm2(blf[ni], ad + 16384);
            }
#pragma unroll
            for (int mi = 0; mi < 4; mi++) {
                uint32_t ah[4], al[4];
                const uint32_t aa = so + rowbyteA[mi] + ((ks * 32 + a_koff) ^ swzA);
                ldsm4(ah, aa);
                ldsm4(al, aa + 16384);
#pragma unroll
                for (int ni = 0; ni < 4; ni++) {
                    mma16816(C[mi][ni], ah, bhf[ni]);
                    mma16816(C[mi][ni], ah, blf[ni]);
                    mma16816(C[mi][ni], al, bhf[ni]);
                }
            }
        }
    }

    const float invS = 1.f / 1024.f;
    float* outp = g_hpart + (size_t)sp * (BATCH * HID);
    const int g = lane >> 2, qp = lane & 3;
#pragma unroll
    for (int mi = 0; mi < 4; mi++) {
#pragma unroll
        for (int ni = 0; ni < 4; ni++) {
            const int row = b0 + m_base + mi * 16 + g;
            const int col = j0 + n_base + ni * 8 + qp * 2;
            *(float2*)(outp + (size_t)row * HID + col) =
                make_float2(C[mi][ni][0] * invS, C[mi][ni][1] * invS);
            *(float2*)(outp + (size_t)(row + 8) * HID + col) =
                make_float2(C[mi][ni][2] * invS, C[mi][ni][3] * invS);
        }
    }
}

// =====================================================================
// Router select
// =====================================================================
__global__ __launch_bounds__(128) void router_select(const float* __restrict__ b1,
                                                     const float* __restrict__ w2,
                                                     const float* __restrict__ b2)
{
    const int b = blockIdx.x, tid = threadIdx.x;
    float acc[NB] = {0.f, 0.f, 0.f, 0.f, 0.f};
    for (int j = tid; j < HID; j += 128) {
        float hv = b1[j];
#pragma unroll
        for (int s = 0; s < R_NSPLIT; s++)
            hv += g_hpart[(size_t)s * BATCH * HID + (size_t)b * HID + j];
        hv = fmaxf(hv, 0.f);
#pragma unroll
        for (int n = 0; n < NB; n++) acc[n] += hv * w2[n * HID + j];
    }
    __shared__ float red[NB][128];
#pragma unroll
    for (int n = 0; n < NB; n++) red[n][tid] = acc[n];
    __syncthreads();
    for (int s = 64; s > 0; s >>= 1) {
        if (tid < s) {
#pragma unroll
            for (int n = 0; n < NB; n++) red[n][tid] += red[n][tid + s];
        }
        __syncthreads();
    }
    if (tid == 0) {
        int best = 0;
        float bv = red[0][0] + b2[0];
        for (int n = 1; n < NB; n++) {
            float v = red[n][0] + b2[n];
            if (v > bv) { bv = v; best = n; }
        }
        g_sel[b] = best;
    }
}

// =====================================================================
// Q projection HMMA (2-term: ah*bh + ah*bl), single-fp16 Q output
// smem: A hi 32K @0, B hi 32K @32768, B lo 32K @65536
// =====================================================================
#define QM_AH 0
#define QM_BH 32768
#define QM_BL 65536
#define QM_SMEM 98304
__global__ __launch_bounds__(256) void q_mma(const float* __restrict__ ipb)
{
    extern __shared__ char smc[];
    const uint32_t sb = smem_u32(smc);
    const int tid = threadIdx.x, lane = tid & 31, wid = tid >> 5;
    const int b = blockIdx.x;
    const int wm = wid & 1, wn = wid >> 1;
    const int m_base = wm * 32;

    // zero A pad (chunk 3, units 1..7), hi only
    for (int i = tid; i < 448; i += 256) {
        const int r = i / 7, u = 1 + i % 7;
        const uint32_t off = QM_AH + 3 * 8192 + r * 128 + ((u * 16) ^ ((r & 7) << 4));
        *(uint4*)(smc + off) = make_uint4(0, 0, 0, 0);
    }
    const size_t abase = (size_t)g_sel[b] * BAND_STRIDE + (size_t)b * ROW_STRIDE;
    for (int i = tid; i < 1600; i += 256) {
        const int r = i / 25, cu = i % 25, ch = cu >> 3, u = cu & 7;
        const __half* src = g_bh + abase + (size_t)r * 200 + ch * 64 + u * 8;
        cp16(sb + QM_AH + ch * 8192 + r * 128 + ((u * 16) ^ ((r & 7) << 4)), src);
    }
    CP_COMMIT();
    CP_WAIT0();

    const int a_row  = (lane & 7) + ((lane >> 3) & 1) * 8;
    const int a_koff = (lane >> 4) * 16;
    const int b_row  = lane & 7;
    const int b_koff = ((lane >> 3) & 1) * 16;

    float C[2][8][4];
#pragma unroll
    for (int a = 0; a < 2; a++)
#pragma unroll
        for (int n = 0; n < 8; n++)
#pragma unroll
            for (int c = 0; c < 4; c++) C[a][n][c] = 0.f;

    for (int ck = 0; ck < 4; ck++) {
        __syncthreads();
        for (int i = tid; i < 4096; i += 256) {
            const int a = i / 2048, rem = i % 2048;
            const int r = rem >> 3, u = rem & 7;
            const __half* src = (a ? g_wql : g_wqh) + (size_t)r * 256 + ck * 64 + u * 8;
            cp16(sb + (a ? QM_BL : QM_BH) + r * 128 + ((u * 16) ^ ((r & 7) << 4)), src);
        }
        CP_COMMIT();
        CP_WAIT0();
        __syncthreads();
        const int nks = (ck < 3) ? 4 : 1;
        for (int ks = 0; ks < nks; ks++) {
            uint32_t bhf[8][2], blf[8][2];
#pragma unroll
            for (int ni = 0; ni < 8; ni++) {
                const int nr = wn * 64 + ni * 8 + b_row;
                const uint32_t ad = sb + QM_BH + nr * 128 + ((ks * 32 + b_koff) ^ ((nr & 7) << 4));
                ldsm2(bhf[ni], ad);
                ldsm2(blf[ni], ad + 32768);
            }
#pragma unroll
            for (int mi = 0; mi < 2; mi++) {
                const int ar = m_base + mi * 16 + a_row;
                uint32_t ah[4];
                const uint32_t aa = sb + QM_AH + ck * 8192 + ar * 128 + ((ks * 32 + a_koff) ^ ((ar & 7) << 4));
                ldsm4(ah, aa);
#pragma unroll
                for (int ni = 0; ni < 8; ni++) {
                    mma16816(C[mi][ni], ah, bhf[ni]);
                    mma16816(C[mi][ni], ah, blf[ni]);
                }
            }
        }
    }

    const int g = lane >> 2, qp = lane & 3;
    const float invS = 1.f / 1024.f;
#pragma unroll
    for (int mi = 0; mi < 2; mi++) {
#pragma unroll
        for (int ni = 0; ni < 8; ni++) {
            const int j = wn * 64 + ni * 8 + qp * 2;
#pragma unroll
            for (int e = 0; e < 2; e++) {
                const int jj = j + e;
                if (jj >= 200) continue;
                const int hh = jj / 50, dd = jj % 50;
                const float bia = __ldg(ipb + jj);
#pragma unroll
                for (int hf = 0; hf < 2; hf++) {
                    const int r = m_base + mi * 16 + g + hf * 8;
                    const float v = C[mi][ni][hf * 2 + e] * invS + bia;
                    const size_t idx = ((size_t)(b * 4 + hh) * 64 + r) * 56 + dd;
                    g_qh[idx] = __float2half_rn(v * 32.f);
                }
            }
        }
    }
    // zero pad cols 50..55
    for (int i = tid; i < 768; i += 256) {
        const int hh = i / 192, rem2 = i % 192;
        const int t = rem2 / 3, uo = rem2 % 3;
        *((uint32_t*)(g_qh + ((size_t)(b * 4 + hh) * 64 + t) * 56 + 50) + uo) = 0u;
    }
}

// =====================================================================
// K/V projection HMMA (2-term: ah*bh + ah*bl), single-fp16 K/V output
// smem: A hi 64K @0, B hi 32K @65536, B lo 32K @98304, bias @131072
// =====================================================================
#define KV_AH 0
#define KV_BH 65536
#define KV_BL 98304
#define KV_BIAS 131072
#define KV_SMEM (131072 + 1664)
__global__ __launch_bounds__(256) void kv_mma(const float* __restrict__ ipb)
{
    extern __shared__ char smc[];
    const uint32_t sb = smem_u32(smc);
    const int tid = threadIdx.x, lane = tid & 31, wid = tid >> 5;
    const int n = blockIdx.x, bp = blockIdx.y;
    const int wm = wid & 1, wn = wid >> 1;
    const int m_base = wm * 64;

    float* bias = (float*)(smc + KV_BIAS);
    for (int i = tid; i < 400; i += 256) bias[i] = ipb[200 + i];

    // zero A pad (chunk 3, units 1..7), hi only
#pragma unroll
    for (int j = 0; j < 4; j++) {
        const int u = tid + j * 256;
        if (u < 896) {
            const int row = u / 7, uu = 1 + (u % 7);
            const uint32_t d = 3 * 16384 + row * 128 + ((uu * 16) ^ ((row & 7) << 4));
            *(uint4*)(smc + KV_AH + d) = make_uint4(0, 0, 0, 0);
        }
    }
    {
        const size_t abase = (size_t)n * BAND_STRIDE + (size_t)(bp * 128) * 200;
#pragma unroll
        for (int j = 0; j < 13; j++) {
            const int u = tid + j * 256;
            if (u < 3200) {
                const int row = u / 25;
                const int rem = u - row * 25;
                const int ch = rem >> 3, uu = rem & 7;
                const uint32_t d = ch * 16384 + row * 128 + ((uu * 16) ^ ((row & 7) << 4));
                cp16(sb + KV_AH + d, g_bh + abase + (size_t)row * 200 + ch * 64 + uu * 8);
            }
        }
        CP_COMMIT();
        CP_WAIT0();
    }
    __syncthreads();

    const int a_row  = (lane & 7) + ((lane >> 3) & 1) * 8;
    const int a_koff = (lane >> 4) * 16;
    const int bl_    = lane & 15;
    const int b_row  = bl_ & 7;
    const int b_koff = (bl_ >> 3) * 16;
    int rowbyteA[4], rowbyteB[2];
#pragma unroll
    for (int mi = 0; mi < 4; mi++) rowbyteA[mi] = (m_base + mi * 16 + a_row) * 128;
#pragma unroll
    for (int ni = 0; ni < 2; ni++) rowbyteB[ni] = (wn * 16 + ni * 8 + b_row) * 128;
    const int swzA = (lane & 7) << 4;
    const int swzB = b_row << 4;
    const int g = lane >> 2, qp = lane & 3;
    const float invS = 1.f / 1024.f;

    for (int nt = 0; nt < 7; nt++) {
        __syncthreads();
#pragma unroll
        for (int j = 0; j < 8; j++) {
            const int u = tid + j * 256;
            const int lr = u >> 5;
            const int rem = u & 31;
            const int ch = rem >> 3, uu = rem & 7;
            const int nr = nt * 64 + lr;
            const uint4 vh = *(const uint4*)(g_wkvh + (size_t)nr * 256 + ch * 64 + uu * 8);
            const uint4 vl = *(const uint4*)(g_wkvl + (size_t)nr * 256 + ch * 64 + uu * 8);
            const uint32_t d = ch * 8192 + lr * 128 + ((uu * 16) ^ ((lr & 7) << 4));
            *(uint4*)(smc + KV_BH + d) = vh;
            *(uint4*)(smc + KV_BL + d) = vl;
        }
        __syncthreads();

        float C[4][2][4];
#pragma unroll
        for (int a = 0; a < 4; a++)
#pragma unroll
            for (int b = 0; b < 2; b++)
#pragma unroll
                for (int c = 0; c < 4; c++) C[a][b][c] = 0.f;

        for (int ks = 0; ks < 13; ks++) {
            const int ch = ks >> 2, ki = ks & 3;
            uint32_t bhf[2][2], blf[2][2];
#pragma unroll
            for (int ni = 0; ni < 2; ni++) {
                const uint32_t ad = sb + KV_BH + ch * 8192 + rowbyteB[ni] + ((ki * 32 + b_koff) ^ swzB);
                ldsm2(bhf[ni], ad);
                ldsm2(blf[ni], ad + 32768);
            }
#pragma unroll
            for (int mi = 0; mi < 4; mi++) {
                uint32_t ah[4];
                const uint32_t aa = sb + KV_AH + ch * 16384 + rowbyteA[mi] + ((ki * 32 + a_koff) ^ swzA);
                ldsm4(ah, aa);
#pragma unroll
                for (int ni = 0; ni < 2; ni++) {
                    mma16816(C[mi][ni], ah, bhf[ni]);
                    mma16816(C[mi][ni], ah, blf[ni]);
                }
            }
        }

#pragma unroll
        for (int mi = 0; mi < 4; mi++) {
#pragma unroll
            for (int ni = 0; ni < 2; ni++) {
                const int col = nt * 64 + wn * 16 + ni * 8 + qp * 2;
#pragma unroll
                for (int e = 0; e < 2; e++) {
                    const int ce = col + e;
                    if (ce >= 400) continue;
                    const float bia = bias[ce];
                    const int isV = (ce >= 200);
                    const int c2 = isV ? (ce - 200) : ce;
                    const int hh = c2 / 50, dd = c2 % 50;
                    __half* dsth = isV ? g_vh : g_kh;
#pragma unroll
                    for (int hf = 0; hf < 2; hf++) {
                        const int r = m_base + mi * 16 + g + hf * 8;
                        const int b = 2 * bp + (r >> 6);
                        const int tloc = n * 64 + (r & 63);
                        const float v = C[mi][ni][hf * 2 + e] * invS + bia;
                        const size_t idx = ((size_t)(b * 4 + hh) * 320 + tloc) * 56 + dd;
                        dsth[idx] = __float2half_rn(v * 32.f);
                    }
                }
            }
        }
    }
    // zero pad cols 50..55 for this CTA's range (kh, vh)
    for (int i = tid; i < 3072; i += 256) {
        const int a = i / 1536, rem = i % 1536;
        const int bb = rem / 768, rem2 = rem % 768;
        const int hh = rem2 / 192, rem3 = rem2 % 192;
        const int tt = rem3 / 3, uo = rem3 % 3;
        const int bg = 2 * bp + bb;
        const int t = n * 64 + tt;
        __half* base = (a == 0) ? g_kh : g_vh;
        *((uint32_t*)(base + ((size_t)(bg * 4 + hh) * 320 + t) * 56 + 50) + uo) = 0u;
    }
}

// =====================================================================
// Attention HMMA: single-fp16 Q/K/V, 1-term QK^T and PV, register softmax,
// 89KB smem -> 2 CTAs/SM. V prefetched in 2nd cp.async group.
// =====================================================================
#define AT_Q  0          // 8K
#define AT_K  8192       // 40K (later P, rows of 640B)
#define AT_V  49152      // 40K
#define AT_RED  90112    // 128 floats
#define AT_RED2 90624    // 128 floats
#define AT_SMEM 91136
__global__ __launch_bounds__(256, 2) void attn_mma()
{
    extern __shared__ char smc[];
    const uint32_t sb = smem_u32(smc);
    const int tid = threadIdx.x, lane = tid & 31, wid = tid >> 5;
    const int h = blockIdx.x, b = blockIdx.y;
    const size_t kvbase = ((size_t)b * 4 + h) * 320;
    const size_t qbase  = ((size_t)b * 4 + h) * 64;

    // zero unit 7 (k-dim pad) of Q (64 rows), K (320), V (320)
    for (int i = tid; i < 704; i += 256) {
        uint32_t base; int row;
        if (i < 64)       { base = AT_Q; row = i; }
        else if (i < 384) { base = AT_K; row = i - 64; }
        else              { base = AT_V; row = i - 384; }
        *(uint4*)(smc + base + row * 128 + (112 ^ ((row & 7) << 4))) = make_uint4(0, 0, 0, 0);
    }
    // group A: Q + K
    for (int i = tid; i < 448; i += 256) {
        const int r = i / 7, u = i % 7;
        cp16(sb + AT_Q + r * 128 + ((u * 16) ^ ((r & 7) << 4)),
             g_qh + (qbase + r) * 56 + u * 8);
    }
    for (int i = tid; i < 2240; i += 256) {
        const int r = i / 7, u = i % 7;
        cp16(sb + AT_K + r * 128 + ((u * 16) ^ ((r & 7) << 4)),
             g_kh + (kvbase + r) * 56 + u * 8);
    }
    CP_COMMIT();
    // group B: V prefetch (waited before PV)
    for (int i = tid; i < 2240; i += 256) {
        const int r = i / 7, u = i % 7;
        cp16(sb + AT_V + r * 128 + ((u * 16) ^ ((r & 7) << 4)),
             g_vh + (kvbase + r) * 56 + u * 8);
    }
    CP_COMMIT();
    CP_WAIT1();
    __syncthreads();

    // ---- QK^T (1-term) ----
    const int wm = wid & 3, wn = wid >> 2;
    const int m_base = wm * 16, n_base = wn * 160;
    const int a_row  = m_base + (lane & 7) + ((lane >> 3) & 1) * 8;
    const int a_koff = (lane >> 4) * 16;
    const int b_row  = lane & 7;
    const int b_koff = ((lane >> 3) & 1) * 16;
    const int g = lane >> 2, qp = lane & 3;

    float C[20][4];
#pragma unroll
    for (int i = 0; i < 20; i++)
#pragma unroll
        for (int j = 0; j < 4; j++) C[i][j] = 0.f;

#pragma unroll
    for (int ks = 0; ks < 4; ks++) {
        uint32_t q4[4];
        ldsm4(q4, sb + AT_Q + a_row * 128 + ((ks * 32 + a_koff) ^ ((a_row & 7) << 4)));
#pragma unroll
        for (int ni = 0; ni < 20; ni++) {
            const int trow = n_base + ni * 8 + b_row;
            uint32_t k2[2];
            ldsm2(k2, sb + AT_K + trow * 128 + ((ks * 32 + b_koff) ^ ((trow & 7) << 4)));
            mma16816(C[ni], q4, k2);
        }
    }

    // ---- register softmax ----
    const float sc = 0.14142135623730951f / 1024.f;
#pragma unroll
    for (int ni = 0; ni < 20; ni++)
#pragma unroll
        for (int j = 0; j < 4; j++) C[ni][j] *= sc;

    float* RED1 = (float*)(smc + AT_RED);
    float* RED2 = (float*)(smc + AT_RED2);
    const int r0 = m_base + g;

    float m0 = -1e30f, m1 = -1e30f;
#pragma unroll
    for (int ni = 0; ni < 20; ni++) {
        m0 = fmaxf(m0, fmaxf(C[ni][0], C[ni][1]));
        m1 = fmaxf(m1, fmaxf(C[ni][2], C[ni][3]));
    }
    m0 = fmaxf(m0, __shfl_xor_sync(0xffffffffu, m0, 1));
    m0 = fmaxf(m0, __shfl_xor_sync(0xffffffffu, m0, 2));
    m1 = fmaxf(m1, __shfl_xor_sync(0xffffffffu, m1, 1));
    m1 = fmaxf(m1, __shfl_xor_sync(0xffffffffu, m1, 2));
    if (qp == 0) { RED1[wn * 64 + r0] = m0; RED1[wn * 64 + r0 + 8] = m1; }
    __syncthreads();   // also: all warps done reading K (P overwrites K region)
    const float M0 = fmaxf(RED1[r0], RED1[64 + r0]);
    const float M1 = fmaxf(RED1[r0 + 8], RED1[64 + r0 + 8]);

    float s0 = 0.f, s1 = 0.f;
#pragma unroll
    for (int ni = 0; ni < 20; ni++) {
        C[ni][0] = __expf(C[ni][0] - M0); s0 += C[ni][0];
        C[ni][1] = __expf(C[ni][1] - M0); s0 += C[ni][1];
        C[ni][2] = __expf(C[ni][2] - M1); s1 += C[ni][2];
        C[ni][3] = __expf(C[ni][3] - M1); s1 += C[ni][3];
    }
    s0 += __shfl_xor_sync(0xffffffffu, s0, 1);
    s0 += __shfl_xor_sync(0xffffffffu, s0, 2);
    s1 += __shfl_xor_sync(0xffffffffu, s1, 1);
    s1 += __shfl_xor_sync(0xffffffffu, s1, 2);
    if (qp == 0) { RED2[wn * 64 + r0] = s0; RED2[wn * 64 + r0 + 8] = s1; }
    __syncthreads();
    const float i0 = 1.f / (RED2[r0] + RED2[64 + r0]);
    const float i1 = 1.f / (RED2[r0 + 8] + RED2[64 + r0 + 8]);

    // P (single fp16) from registers into K region (ldmatrix layout, row=640B)
    {
        const uint32_t sw0 = (r0 & 7) << 4;
        const uint32_t sw1 = ((r0 + 8) & 7) << 4;
#pragma unroll
        for (int ni = 0; ni < 20; ni++) {
            const int col = n_base + ni * 8 + qp * 2;
            const uint32_t ub = (col >> 3) * 16;
            const uint32_t off0 = r0 * 640 + (ub ^ sw0) + (col & 7) * 2;
            const uint32_t off1 = (r0 + 8) * 640 + (ub ^ sw1) + (col & 7) * 2;
            *(__half2*)(smc + AT_K + off0) =
                __halves2half2(__float2half_rn(C[ni][0] * i0), __float2half_rn(C[ni][1] * i0));
            *(__half2*)(smc + AT_K + off1) =
                __halves2half2(__float2half_rn(C[ni][2] * i1), __float2half_rn(C[ni][3] * i1));
        }
    }
    CP_WAIT0();        // V arrived
    __syncthreads();   // P visible to all warps

    // ---- P @ V (1-term) ----
    const int wnv = wid >> 2;
    const int mv_base = (wid & 3) * 16;
    const int nv_base = wnv * 32;
    const int ntc = wnv ? 3 : 4;
    const int p_row = mv_base + (lane & 7) + ((lane >> 3) & 1) * 8;
    const int p_unit = lane >> 4;
    const int v_koff = (lane & 7) + ((lane >> 3) & 1) * 8;

    float O[4][4];
#pragma unroll
    for (int i = 0; i < 4; i++)
#pragma unroll
        for (int j = 0; j < 4; j++) O[i][j] = 0.f;

    for (int ks = 0; ks < 20; ks++) {
        uint32_t p4[4];
        ldsm4(p4, sb + AT_K + p_row * 640 + (((ks * 2 + p_unit) * 16) ^ ((p_row & 7) << 4)));
        const int krow = ks * 16 + v_koff;
        const uint32_t swk = (krow & 7) << 4;
#pragma unroll
        for (int nt = 0; nt < 4; nt++) {
            if (nt >= ntc) break;
            const int ncol = nv_base + nt * 8;
            uint32_t v2[2];
            ldsm2t(v2, sb + AT_V + krow * 128 + ((ncol * 2) ^ swk));
            mma16816(O[nt], p4, v2);
        }
    }

    // O (scale 32) -> fp16 hi/lo for out projection
#pragma unroll
    for (int nt = 0; nt < 4; nt++) {
        if (nt >= ntc) break;
        const int d = nv_base + nt * 8 + qp * 2;
        if (d >= 50) continue;
#pragma unroll
        for (int hf = 0; hf < 2; hf++) {
            const int r = mv_base + g + hf * 8;
            const float o0 = O[nt][hf * 2 + 0];
            const float o1 = O[nt][hf * 2 + 1];
            const __half h0 = __float2half_rn(o0), h1 = __float2half_rn(o1);
            const size_t idx = ((size_t)b * 64 + r) * 200 + h * 50 + d;
            *(__half2*)(g_oh + idx) = __halves2half2(h0, h1);
            *(__half2*)(g_ol + idx) =
                __halves2half2(__float2half_rn(o0 - __half2float(h0)),
                               __float2half_rn(o1 - __half2float(h1)));
        }
    }
}

// =====================================================================
// Out projection HMMA: 3-term, A = O hi/lo, fp32 out
// smem: A hi 32K @0, A lo 32K @32768, B hi 32K @65536, B lo 32K @98304
// =====================================================================
#define OM_AH 0
#define OM_AL 32768
#define OM_BH 65536
#define OM_BL 98304
#define OM_SMEM 131072
__global__ __launch_bounds__(256) void out_mma(const float* __restrict__ ob,
                                               float* __restrict__ outp)
{
    extern __shared__ char smc[];
    const uint32_t sb = smem_u32(smc);
    const int tid = threadIdx.x, lane = tid & 31, wid = tid >> 5;
    const int b = blockIdx.x;
    const int wm = wid & 1, wn = wid >> 1;
    const int m_base = wm * 32;

    for (int i = tid; i < 896; i += 256) {
        const int a = i / 448, rem = i % 448;
        const int r = rem / 7, u = 1 + rem % 7;
        const uint32_t off = (a ? OM_AL : OM_AH) + 3 * 8192 + r * 128 + ((u * 16) ^ ((r & 7) << 4));
        *(uint4*)(smc + off) = make_uint4(0, 0, 0, 0);
    }
    const size_t abase = (size_t)b * 64 * 200;
    for (int i = tid; i < 3200; i += 256) {
        const int a = i / 1600, rem = i % 1600;
        const int r = rem / 25, cu = rem % 25, ch = cu >> 3, u = cu & 7;
        const __half* src = (a ? g_ol : g_oh) + abase + (size_t)r * 200 + ch * 64 + u * 8;
        cp16(sb + (a ? OM_AL : OM_AH) + ch * 8192 + r * 128 + ((u * 16) ^ ((r & 7) << 4)), src);
    }
    CP_COMMIT();
    CP_WAIT0();

    const int a_row  = (lane & 7) + ((lane >> 3) & 1) * 8;
    const int a_koff = (lane >> 4) * 16;
    const int b_row  = lane & 7;
    const int b_koff = ((lane >> 3) & 1) * 16;

    float C[2][8][4];
#pragma unroll
    for (int a = 0; a < 2; a++)
#pragma unroll
        for (int n = 0; n < 8; n++)
#pragma unroll
            for (int c = 0; c < 4; c++) C[a][n][c] = 0.f;

    for (int ck = 0; ck < 4; ck++) {
        __syncthreads();
        for (int i = tid; i < 4096; i += 256) {
            const int a = i / 2048, rem = i % 2048;
            const int r = rem >> 3, u = rem & 7;
            const __half* src = (a ? g_wol : g_woh) + (size_t)r * 256 + ck * 64 + u * 8;
            cp16(sb + (a ? OM_BL : OM_BH) + r * 128 + ((u * 16) ^ ((r & 7) << 4)), src);
        }
        CP_COMMIT();
        CP_WAIT0();
        __syncthreads();
        const int nks = (ck < 3) ? 4 : 1;
        for (int ks = 0; ks < nks; ks++) {
            uint32_t bhf[8][2], blf[8][2];
#pragma unroll
            for (int ni = 0; ni < 8; ni++) {
                const int nr = wn * 64 + ni * 8 + b_row;
                const uint32_t ad = sb + OM_BH + nr * 128 + ((ks * 32 + b_koff) ^ ((nr & 7) << 4));
                ldsm2(bhf[ni], ad);
                ldsm2(blf[ni], ad + 32768);
            }
#pragma unroll
            for (int mi = 0; mi < 2; mi++) {
                const int ar = m_base + mi * 16 + a_row;
                uint32_t ah[4], al[4];
                const uint32_t aa = sb + OM_AH + ck * 8192 + ar * 128 + ((ks * 32 + a_koff) ^ ((ar & 7) << 4));
                ldsm4(ah, aa);
                ldsm4(al, aa + 32768);
#pragma unroll
                for (int ni = 0; ni < 8; ni++) {
                    mma16816(C[mi][ni], ah, bhf[ni]);
                    mma16816(C[mi][ni], ah, blf[ni]);
                    mma16816(C[mi][ni], al, bhf[ni]);
                }
            }
        }
    }

    const int g = lane >> 2, qp = lane & 3;
    const float invS = 1.f / 8192.f;
#pragma unroll
    for (int mi = 0; mi < 2; mi++) {
#pragma unroll
        for (int ni = 0; ni < 8; ni++) {
            const int jj = wn * 64 + ni * 8 + qp * 2;
            if (jj >= 200) continue;
            const float b0 = __ldg(ob + jj), b1 = __ldg(ob + jj + 1);
#pragma unroll
            for (int hf = 0; hf < 2; hf++) {
                const int r = m_base + mi * 16 + g + hf * 8;
                *(float2*)(outp + ((size_t)b * 64 + r) * 200 + jj) =
                    make_float2(C[mi][ni][hf * 2 + 0] * invS + b0,
                                C[mi][ni][hf * 2 + 1] * invS + b1);
            }
        }
    }
}

// =====================================================================
// launch: fork kv-chain and w1-conversion onto side streams
// =====================================================================
struct LaunchRes {
    cudaStream_t s1, s2;
    cudaEvent_t e0, eA, eW1, eKV;
    LaunchRes() {
        cudaStreamCreateWithFlags(&s1, cudaStreamNonBlocking);
        cudaStreamCreateWithFlags(&s2, cudaStreamNonBlocking);
        cudaEventCreateWithFlags(&e0,  cudaEventDisableTiming);
        cudaEventCreateWithFlags(&eA,  cudaEventDisableTiming);
        cudaEventCreateWithFlags(&eW1, cudaEventDisableTiming);
        cudaEventCreateWithFlags(&eKV, cudaEventDisableTiming);
    }
};

extern "C" void kernel_launch(void* const* d_in, const int* in_sizes, int n_in,
                              void* d_out, int out_size)
{
    const float* bands = (const float*)d_in[0];
    const float* w1    = (const float*)d_in[1];
    const float* b1    = (const float*)d_in[2];
    const float* w2    = (const float*)d_in[3];
    const float* b2    = (const float*)d_in[4];
    const float* ipw   = (const float*)d_in[5];
    const float* ipb   = (const float*)d_in[6];
    const float* ow    = (const float*)d_in[7];
    const float* ob    = (const float*)d_in[8];
    float* outp = (float*)d_out;

    static LaunchRes R;

    cudaFuncSetAttribute(router_mma, cudaFuncAttributeMaxDynamicSharedMemorySize, R_SMEM);
    cudaFuncSetAttribute(kv_mma, cudaFuncAttributeMaxDynamicSharedMemorySize, KV_SMEM);
    cudaFuncSetAttribute(q_mma, cudaFuncAttributeMaxDynamicSharedMemorySize, QM_SMEM);
    cudaFuncSetAttribute(out_mma, cudaFuncAttributeMaxDynamicSharedMemorySize, OM_SMEM);
    cudaFuncSetAttribute(attn_mma, cudaFuncAttributeMaxDynamicSharedMemorySize, AT_SMEM);

    __half *bh, *blp, *w1h, *w1l, *wqh, *wql, *woh, *wol;
    cudaGetSymbolAddress((void**)&bh,  g_bh);
    cudaGetSymbolAddress((void**)&blp, g_bl);
    cudaGetSymbolAddress((void**)&w1h, g_w1h);
    cudaGetSymbolAddress((void**)&w1l, g_w1l);
    cudaGetSymbolAddress((void**)&wqh, g_wqh);
    cudaGetSymbolAddress((void**)&wql, g_wql);
    cudaGetSymbolAddress((void**)&woh, g_woh);
    cudaGetSymbolAddress((void**)&wol, g_wol);

    const int n4 = (NB * (int)BAND_STRIDE) / 4;

    // fork point
    cudaEventRecord(R.e0, 0);
    cudaStreamWaitEvent(R.s1, R.e0, 0);
    cudaStreamWaitEvent(R.s2, R.e0, 0);

    // s2: w1 conversion (independent of bands)
    conv_split<<<(n4 + 255) / 256, 256, 0, R.s2>>>(w1, w1h, w1l, n4, 256.f);
    cudaEventRecord(R.eW1, R.s2);

    // s1: kv weight conversion (needs only ipw)
    conv_wkv_k<<<448, 256, 0, R.s1>>>(ipw);

    // default: bands conversion + small weight convs
    conv_split<<<(n4 + 255) / 256, 256>>>(bands, bh, blp, n4, 4.f);
    cudaEventRecord(R.eA, 0);
    conv_w256<<<256, 256>>>(ipw, wqh, wql);
    conv_w256<<<256, 256>>>(ow, woh, wol);

    // s1: kv projection once bands fp16 is ready
    cudaStreamWaitEvent(R.s1, R.eA, 0);
    kv_mma<<<dim3(NB, BATCH / 2), 256, KV_SMEM, R.s1>>>(ipb);
    cudaEventRecord(R.eKV, R.s1);

    // default: router chain (needs w1 conversion from s2)
    cudaStreamWaitEvent(0, R.eW1, 0);
    router_mma   <<<dim3(4, 4, R_NSPLIT), 256, R_SMEM>>>();
    router_select<<<BATCH, 128>>>(b1, w2, b2);
    q_mma        <<<BATCH, 256, QM_SMEM>>>(ipb);

    // join kv chain, then attention + output
    cudaStreamWaitEvent(0, R.eKV, 0);
    attn_mma<<<dim3(HEADS, BATCH), 256, AT_SMEM>>>();
    out_mma <<<BATCH, 256, OM_SMEM>>>(ob, outp);
}

// round 14
// speedup vs baseline: 1.6097x; 1.0675x over previous
#include <cuda_runtime.h>
#include <cuda_fp16.h>
#include <cstdint>
#include <math.h>

// ---------------- problem constants ----------------
#define NB 5
#define BATCH 512
#define KQ 64
#define D 200
#define HEADS 4
#define HD 50
#define TKV 320
#define HID 512
#define FIN 64000
#define BAND_STRIDE 6553600ull   // BATCH*KQ*D (elements)
#define ROW_STRIDE 12800         // KQ*D
#define R_NSPLIT 9

// ---------------- scratch ----------------
__device__ float  g_hpart[(size_t)R_NSPLIT * BATCH * HID];
__device__ int    g_sel[BATCH];
__device__ __half g_bh [(size_t)NB * BAND_STRIDE];   // bands * 4, hi
__device__ __half g_bl [(size_t)NB * BAND_STRIDE];   // bands * 4, lo
__device__ __half g_w1h[(size_t)HID * FIN];          // w1 * 256, hi
__device__ __half g_w1l[(size_t)HID * FIN];          // w1 * 256, lo
__device__ __half g_wkvh[448 * 256];                 // wk|wv * 256 padded, hi
__device__ __half g_wkvl[448 * 256];                 // lo
__device__ __half g_wqh[256 * 256];                  // wq * 256 padded, hi
__device__ __half g_wql[256 * 256];                  // lo
__device__ __half g_woh[256 * 256];                  // out_w * 256 padded, hi
__device__ __half g_wol[256 * 256];                  // lo
// head-split padded layouts, values scaled *32, pad cols 50..55 zero (single fp16)
__device__ __half g_qh[(size_t)BATCH * HEADS * 64 * 56];
__device__ __half g_kh[(size_t)BATCH * HEADS * 320 * 56];
__device__ __half g_vh[(size_t)BATCH * HEADS * 320 * 56];
// attention output, scaled *32, [b*64][200], hi/lo
__device__ __half g_oh[(size_t)BATCH * KQ * D];
__device__ __half g_ol[(size_t)BATCH * KQ * D];

// =====================================================================
// helpers
// =====================================================================
__device__ __forceinline__ uint32_t smem_u32(const void* p) {
    uint32_t a;
    asm("{ .reg .u64 t; cvta.to.shared.u64 t, %1; cvt.u32.u64 %0, t; }" : "=r"(a) : "l"(p));
    return a;
}
__device__ __forceinline__ void cp16(uint32_t dst, const void* src) {
    asm volatile("cp.async.cg.shared.global [%0], [%1], 16;" :: "r"(dst), "l"(src));
}
#define CP_COMMIT() asm volatile("cp.async.commit_group;" ::: "memory")
#define CP_WAIT2()  asm volatile("cp.async.wait_group 2;" ::: "memory")
#define CP_WAIT1()  asm volatile("cp.async.wait_group 1;" ::: "memory")
#define CP_WAIT0()  asm volatile("cp.async.wait_group 0;" ::: "memory")

__device__ __forceinline__ void ldsm4(uint32_t* r, uint32_t a) {
    asm volatile("ldmatrix.sync.aligned.m8n8.x4.shared.b16 {%0,%1,%2,%3}, [%4];"
        : "=r"(r[0]), "=r"(r[1]), "=r"(r[2]), "=r"(r[3]) : "r"(a));
}
__device__ __forceinline__ void ldsm2(uint32_t* r, uint32_t a) {
    asm volatile("ldmatrix.sync.aligned.m8n8.x2.shared.b16 {%0,%1}, [%2];"
        : "=r"(r[0]), "=r"(r[1]) : "r"(a));
}
__device__ __forceinline__ void ldsm2t(uint32_t* r, uint32_t a) {
    asm volatile("ldmatrix.sync.aligned.m8n8.x2.trans.shared.b16 {%0,%1}, [%2];"
        : "=r"(r[0]), "=r"(r[1]) : "r"(a));
}
__device__ __forceinline__ void mma16816(float* c, const uint32_t* a, const uint32_t* b) {
    asm volatile("mma.sync.aligned.m16n8k16.row.col.f32.f16.f16.f32 "
        "{%0,%1,%2,%3}, {%4,%5,%6,%7}, {%8,%9}, {%0,%1,%2,%3};"
        : "+f"(c[0]), "+f"(c[1]), "+f"(c[2]), "+f"(c[3])
        : "r"(a[0]), "r"(a[1]), "r"(a[2]), "r"(a[3]), "r"(b[0]), "r"(b[1]));
}

// =====================================================================
// Conversion kernels
// =====================================================================
__global__ __launch_bounds__(256) void conv_split(const float* __restrict__ src,
                                                  __half* __restrict__ dh,
                                                  __half* __restrict__ dl,
                                                  int n4, float s)
{
    int i = blockIdx.x * blockDim.x + threadIdx.x;
    if (i >= n4) return;
    float4 v = ((const float4*)src)[i];
    float x0 = v.x * s, x1 = v.y * s, x2 = v.z * s, x3 = v.w * s;
    __half h0 = __float2half_rn(x0), h1 = __float2half_rn(x1);
    __half h2 = __float2half_rn(x2), h3 = __float2half_rn(x3);
    __half l0 = __float2half_rn(x0 - __half2float(h0));
    __half l1 = __float2half_rn(x1 - __half2float(h1));
    __half l2 = __float2half_rn(x2 - __half2float(h2));
    __half l3 = __float2half_rn(x3 - __half2float(h3));
    ((__half2*)dh)[2 * i]     = __halves2half2(h0, h1);
    ((__half2*)dh)[2 * i + 1] = __halves2half2(h2, h3);
    ((__half2*)dl)[2 * i]     = __halves2half2(l0, l1);
    ((__half2*)dl)[2 * i + 1] = __halves2half2(l2, l3);
}

__global__ __launch_bounds__(256) void conv_wkv_k(const float* __restrict__ ipw)
{
    const int row = blockIdx.x;
    const int col = threadIdx.x;
    float v = 0.f;
    if (row < 400 && col < 200) v = ipw[(size_t)(200 + row) * 200 + col] * 256.f;
    __half h = __float2half_rn(v);
    __half l = __float2half_rn(v - __half2float(h));
    g_wkvh[row * 256 + col] = h;
    g_wkvl[row * 256 + col] = l;
}

__global__ __launch_bounds__(256) void conv_w256(const float* __restrict__ W,
                                                 __half* __restrict__ dh,
                                                 __half* __restrict__ dl)
{
    const int row = blockIdx.x;
    const int col = threadIdx.x;
    float v = 0.f;
    if (row < 200 && col < 200) v = W[(size_t)row * 200 + col] * 256.f;
    __half h = __float2half_rn(v);
    __half l = __float2half_rn(v - __half2float(h));
    dh[row * 256 + col] = h;
    dl[row * 256 + col] = l;
}

// =====================================================================
// Router GEMM: M=128, N=64, kc=64, splitK=9, 2-stage cp.async,
// 2 CTAs/SM (96KB smem, 288 CTAs = one resident wave). Full 3-term split.
// stage (48KB): Ah@0(16K), Al@16K, Bh@32K(8K), Bl@40K
// =====================================================================
#define R_STAGE 49152
#define R_SMEM (2 * R_STAGE)
__global__ __launch_bounds__(256, 2) void router_mma(void)
{
    extern __shared__ char smc[];
    const uint32_t sb = smem_u32(smc);
    const int tid = threadIdx.x, lane = tid & 31, wid = tid >> 5;
    const int jt = blockIdx.x, mt = blockIdx.y, sp = blockIdx.z;
    const int b0 = mt * 128, j0 = jt * 64;
    const int wm = wid & 1, wn = wid >> 1;       // 2(M x64) x 4(N x16)
    const int m_base = wm * 64;

    const int a_row  = (lane & 7) + ((lane >> 3) & 1) * 8;
    const int a_koff = (lane >> 4) * 16;
    const int bl_    = lane & 15;
    const int b_row  = bl_ & 7;
    const int b_koff = (bl_ >> 3) * 16;
    int rowbyteA[4], rowbyteB[2];
#pragma unroll
    for (int mi = 0; mi < 4; mi++) rowbyteA[mi] = (m_base + mi * 16 + a_row) * 128;
#pragma unroll
    for (int ni = 0; ni < 2; ni++) rowbyteB[ni] = (wn * 16 + ni * 8 + b_row) * 128;
    const int swzA = (lane & 7) << 4;
    const int swzB = b_row << 4;

    float C[4][2][4];
#pragma unroll
    for (int a = 0; a < 4; a++)
#pragma unroll
        for (int b = 0; b < 2; b++)
#pragma unroll
            for (int c = 0; c < 4; c++) C[a][b][c] = 0.f;

    const int cbeg = sp * 111 + (sp > 0 ? 1 : 0);
    const int cnt  = 111 + (sp == 0 ? 1 : 0);

    auto issue_chunk = [&](int c, int p) {
        const int n = c / 200;
        const int rr = (c - n * 200) * 64;
        const __half* Ah = g_bh + (size_t)n * BAND_STRIDE + (size_t)b0 * ROW_STRIDE + rr;
        const __half* Al = g_bl + (size_t)n * BAND_STRIDE + (size_t)b0 * ROW_STRIDE + rr;
        const size_t f0 = (size_t)c * 64;
        const uint32_t so = sb + p * R_STAGE;
#pragma unroll
        for (int j = 0; j < 4; j++) {
            const int u = tid + j * 256;          // 0..1023
            const int row = u >> 3, uu = u & 7;
            const uint32_t d = row * 128 + ((uu * 16) ^ ((row & 7) << 4));
            cp16(so + d,         Ah + (size_t)row * ROW_STRIDE + uu * 8);
            cp16(so + 16384 + d, Al + (size_t)row * ROW_STRIDE + uu * 8);
        }
#pragma unroll
        for (int j = 0; j < 2; j++) {
            const int u = tid + j * 256;          // 0..511
            const int row = u >> 3, uu = u & 7;   // row 0..63
            const uint32_t d = row * 128 + ((uu * 16) ^ ((row & 7) << 4));
            cp16(so + 32768 + d, g_w1h + (size_t)(j0 + row) * FIN + f0 + uu * 8);
            cp16(so + 40960 + d, g_w1l + (size_t)(j0 + row) * FIN + f0 + uu * 8);
        }
    };

    issue_chunk(cbeg, 0);
    CP_COMMIT();
    if (cnt > 1) { issue_chunk(cbeg + 1, 1); CP_COMMIT(); }

    for (int c = 0; c < cnt; c++) {
        const int p = c & 1;
        if (c + 1 < cnt) CP_WAIT1(); else CP_WAIT0();
        __syncthreads();
        const uint32_t so = sb + p * R_STAGE;
#pragma unroll
        for (int ks = 0; ks < 4; ks++) {
            uint32_t bhf[2][2], blf[2][2];
#pragma unroll
            for (int ni = 0; ni < 2; ni++) {
                const uint32_t ad = so + 32768 + rowbyteB[ni] + ((ks * 32 + b_koff) ^ swzB);
                ldsm2(bhf[ni], ad);
                ldsm2(blf[ni], ad + 8192);
            }
#pragma unroll
            for (int mi = 0; mi < 4; mi++) {
                uint32_t ah[4], al[4];
                const uint32_t aa = so + rowbyteA[mi] + ((ks * 32 + a_koff) ^ swzA);
                ldsm4(ah, aa);
                ldsm4(al, aa + 16384);
#pragma unroll
                for (int ni = 0; ni < 2; ni++) {
                    mma16816(C[mi][ni], ah, bhf[ni]);
                    mma16816(C[mi][ni], ah, blf[ni]);
                    mma16816(C[mi][ni], al, bhf[ni]);
                }
            }
        }
        __syncthreads();
        if (c + 2 < cnt) { issue_chunk(cbeg + c + 2, p); CP_COMMIT(); }
    }

    const float invS = 1.f / 1024.f;
    float* outp = g_hpart + (size_t)sp * (BATCH * HID);
    const int g = lane >> 2, qp = lane & 3;
#pragma unroll
    for (int mi = 0; mi < 4; mi++) {
#pragma unroll
        for (int ni = 0; ni < 2; ni++) {
            const int row = b0 + m_base + mi * 16 + g;
            const int col = j0 + wn * 16 + ni * 8 + qp * 2;
            *(float2*)(outp + (size_t)row * HID + col) =
                make_float2(C[mi][ni][0] * invS, C[mi][ni][1] * invS);
            *(float2*)(outp + (size_t)(row + 8) * HID + col) =
                make_float2(C[mi][ni][2] * invS, C[mi][ni][3] * invS);
        }
    }
}

// =====================================================================
// Router select
// =====================================================================
__global__ __launch_bounds__(128) void router_select(const float* __restrict__ b1,
                                                     const float* __restrict__ w2,
                                                     const float* __restrict__ b2)
{
    const int b = blockIdx.x, tid = threadIdx.x;
    float acc[NB] = {0.f, 0.f, 0.f, 0.f, 0.f};
    for (int j = tid; j < HID; j += 128) {
        float hv = b1[j];
#pragma unroll
        for (int s = 0; s < R_NSPLIT; s++)
            hv += g_hpart[(size_t)s * BATCH * HID + (size_t)b * HID + j];
        hv = fmaxf(hv, 0.f);
#pragma unroll
        for (int n = 0; n < NB; n++) acc[n] += hv * w2[n * HID + j];
    }
    __shared__ float red[NB][128];
#pragma unroll
    for (int n = 0; n < NB; n++) red[n][tid] = acc[n];
    __syncthreads();
    for (int s = 64; s > 0; s >>= 1) {
        if (tid < s) {
#pragma unroll
            for (int n = 0; n < NB; n++) red[n][tid] += red[n][tid + s];
        }
        __syncthreads();
    }
    if (tid == 0) {
        int best = 0;
        float bv = red[0][0] + b2[0];
        for (int n = 1; n < NB; n++) {
            float v = red[n][0] + b2[n];
            if (v > bv) { bv = v; best = n; }
        }
        g_sel[b] = best;
    }
}

// =====================================================================
// Q projection HMMA (2-term), single-fp16 Q output
// =====================================================================
#define QM_AH 0
#define QM_BH 32768
#define QM_BL 65536
#define QM_SMEM 98304
__global__ __launch_bounds__(256) void q_mma(const float* __restrict__ ipb)
{
    extern __shared__ char smc[];
    const uint32_t sb = smem_u32(smc);
    const int tid = threadIdx.x, lane = tid & 31, wid = tid >> 5;
    const int b = blockIdx.x;
    const int wm = wid & 1, wn = wid >> 1;
    const int m_base = wm * 32;

    for (int i = tid; i < 448; i += 256) {
        const int r = i / 7, u = 1 + i % 7;
        const uint32_t off = QM_AH + 3 * 8192 + r * 128 + ((u * 16) ^ ((r & 7) << 4));
        *(uint4*)(smc + off) = make_uint4(0, 0, 0, 0);
    }
    const size_t abase = (size_t)g_sel[b] * BAND_STRIDE + (size_t)b * ROW_STRIDE;
    for (int i = tid; i < 1600; i += 256) {
        const int r = i / 25, cu = i % 25, ch = cu >> 3, u = cu & 7;
        const __half* src = g_bh + abase + (size_t)r * 200 + ch * 64 + u * 8;
        cp16(sb + QM_AH + ch * 8192 + r * 128 + ((u * 16) ^ ((r & 7) << 4)), src);
    }
    CP_COMMIT();
    CP_WAIT0();

    const int a_row  = (lane & 7) + ((lane >> 3) & 1) * 8;
    const int a_koff = (lane >> 4) * 16;
    const int b_row  = lane & 7;
    const int b_koff = ((lane >> 3) & 1) * 16;

    float C[2][8][4];
#pragma unroll
    for (int a = 0; a < 2; a++)
#pragma unroll
        for (int n = 0; n < 8; n++)
#pragma unroll
            for (int c = 0; c < 4; c++) C[a][n][c] = 0.f;

    for (int ck = 0; ck < 4; ck++) {
        __syncthreads();
        for (int i = tid; i < 4096; i += 256) {
            const int a = i / 2048, rem = i % 2048;
            const int r = rem >> 3, u = rem & 7;
            const __half* src = (a ? g_wql : g_wqh) + (size_t)r * 256 + ck * 64 + u * 8;
            cp16(sb + (a ? QM_BL : QM_BH) + r * 128 + ((u * 16) ^ ((r & 7) << 4)), src);
        }
        CP_COMMIT();
        CP_WAIT0();
        __syncthreads();
        const int nks = (ck < 3) ? 4 : 1;
        for (int ks = 0; ks < nks; ks++) {
            uint32_t bhf[8][2], blf[8][2];
#pragma unroll
            for (int ni = 0; ni < 8; ni++) {
                const int nr = wn * 64 + ni * 8 + b_row;
                const uint32_t ad = sb + QM_BH + nr * 128 + ((ks * 32 + b_koff) ^ ((nr & 7) << 4));
                ldsm2(bhf[ni], ad);
                ldsm2(blf[ni], ad + 32768);
            }
#pragma unroll
            for (int mi = 0; mi < 2; mi++) {
                const int ar = m_base + mi * 16 + a_row;
                uint32_t ah[4];
                const uint32_t aa = sb + QM_AH + ck * 8192 + ar * 128 + ((ks * 32 + a_koff) ^ ((ar & 7) << 4));
                ldsm4(ah, aa);
#pragma unroll
                for (int ni = 0; ni < 8; ni++) {
                    mma16816(C[mi][ni], ah, bhf[ni]);
                    mma16816(C[mi][ni], ah, blf[ni]);
                }
            }
        }
    }

    const int g = lane >> 2, qp = lane & 3;
    const float invS = 1.f / 1024.f;
#pragma unroll
    for (int mi = 0; mi < 2; mi++) {
#pragma unroll
        for (int ni = 0; ni < 8; ni++) {
            const int j = wn * 64 + ni * 8 + qp * 2;
#pragma unroll
            for (int e = 0; e < 2; e++) {
                const int jj = j + e;
                if (jj >= 200) continue;
                const int hh = jj / 50, dd = jj % 50;
                const float bia = __ldg(ipb + jj);
#pragma unroll
                for (int hf = 0; hf < 2; hf++) {
                    const int r = m_base + mi * 16 + g + hf * 8;
                    const float v = C[mi][ni][hf * 2 + e] * invS + bia;
                    const size_t idx = ((size_t)(b * 4 + hh) * 64 + r) * 56 + dd;
                    g_qh[idx] = __float2half_rn(v * 32.f);
                }
            }
        }
    }
    for (int i = tid; i < 768; i += 256) {
        const int hh = i / 192, rem2 = i % 192;
        const int t = rem2 / 3, uo = rem2 % 3;
        *((uint32_t*)(g_qh + ((size_t)(b * 4 + hh) * 64 + t) * 56 + 50) + uo) = 0u;
    }
}

// =====================================================================
// K/V projection HMMA (2-term), single-fp16 K/V, B tiles double-buffered
// smem: A hi 64K @0; B stage p @65536+p*65536 (hi 32K, lo 32K); bias @196608
// =====================================================================
#define KV_AH 0
#define KV_B  65536
#define KV_BIAS 196608
#define KV_SMEM (196608 + 1664)
#define KV_NT 7
__global__ __launch_bounds__(256) void kv_mma(const float* __restrict__ ipb, int bp0)
{
    extern __shared__ char smc[];
    const uint32_t sb = smem_u32(smc);
    const int tid = threadIdx.x, lane = tid & 31, wid = tid >> 5;
    const int n = blockIdx.x, bp = blockIdx.y + bp0;
    const int wm = wid & 1, wn = wid >> 1;
    const int m_base = wm * 64;

    float* bias = (float*)(smc + KV_BIAS);
    for (int i = tid; i < 400; i += 256) bias[i] = ipb[200 + i];

    // zero A pad (chunk 3, units 1..7)
#pragma unroll
    for (int j = 0; j < 4; j++) {
        const int u = tid + j * 256;
        if (u < 896) {
            const int row = u / 7, uu = 1 + (u % 7);
            const uint32_t d = 3 * 16384 + row * 128 + ((uu * 16) ^ ((row & 7) << 4));
            *(uint4*)(smc + KV_AH + d) = make_uint4(0, 0, 0, 0);
        }
    }

    auto load_B = [&](int nt, int p) {
        const uint32_t so = sb + KV_B + p * 65536;
#pragma unroll
        for (int j = 0; j < 8; j++) {
            const int u = tid + j * 256;
            const int lr = u >> 5;
            const int rem = u & 31;
            const int ch = rem >> 3, uu = rem & 7;
            const int nr = nt * 64 + lr;
            const uint32_t d = ch * 8192 + lr * 128 + ((uu * 16) ^ ((lr & 7) << 4));
            cp16(so + d,         g_wkvh + (size_t)nr * 256 + ch * 64 + uu * 8);
            cp16(so + 32768 + d, g_wkvl + (size_t)nr * 256 + ch * 64 + uu * 8);
        }
    };

    // group A: A tile; groups B0, B1
    {
        const size_t abase = (size_t)n * BAND_STRIDE + (size_t)(bp * 128) * 200;
#pragma unroll
        for (int j = 0; j < 13; j++) {
            const int u = tid + j * 256;
            if (u < 3200) {
                const int row = u / 25;
                const int rem = u - row * 25;
                const int ch = rem >> 3, uu = rem & 7;
                const uint32_t d = ch * 16384 + row * 128 + ((uu * 16) ^ ((row & 7) << 4));
                cp16(sb + KV_AH + d, g_bh + abase + (size_t)row * 200 + ch * 64 + uu * 8);
            }
        }
    }
    CP_COMMIT();
    load_B(0, 0); CP_COMMIT();
    load_B(1, 1); CP_COMMIT();
    CP_WAIT2();          // A done
    __syncthreads();

    const int a_row  = (lane & 7) + ((lane >> 3) & 1) * 8;
    const int a_koff = (lane >> 4) * 16;
    const int bl_    = lane & 15;
    const int b_row  = bl_ & 7;
    const int b_koff = (bl_ >> 3) * 16;
    int rowbyteA[4], rowbyteB[2];
#pragma unroll
    for (int mi = 0; mi < 4; mi++) rowbyteA[mi] = (m_base + mi * 16 + a_row) * 128;
#pragma unroll
    for (int ni = 0; ni < 2; ni++) rowbyteB[ni] = (wn * 16 + ni * 8 + b_row) * 128;
    const int swzA = (lane & 7) << 4;
    const int swzB = b_row << 4;
    const int g = lane >> 2, qp = lane & 3;
    const float invS = 1.f / 1024.f;

    for (int nt = 0; nt < KV_NT; nt++) {
        const int p = nt & 1;
        if (nt + 1 < KV_NT) CP_WAIT1(); else CP_WAIT0();
        __syncthreads();
        const uint32_t soB = sb + KV_B + p * 65536;

        float C[4][2][4];
#pragma unroll
        for (int a = 0; a < 4; a++)
#pragma unroll
            for (int b = 0; b < 2; b++)
#pragma unroll
                for (int c = 0; c < 4; c++) C[a][b][c] = 0.f;

        for (int ks = 0; ks < 13; ks++) {
            const int ch = ks >> 2, ki = ks & 3;
            uint32_t bhf[2][2], blf[2][2];
#pragma unroll
            for (int ni = 0; ni < 2; ni++) {
                const uint32_t ad = soB + ch * 8192 + rowbyteB[ni] + ((ki * 32 + b_koff) ^ swzB);
                ldsm2(bhf[ni], ad);
                ldsm2(blf[ni], ad + 32768);
            }
#pragma unroll
            for (int mi = 0; mi < 4; mi++) {
                uint32_t ah[4];
                const uint32_t aa = sb + KV_AH + ch * 16384 + rowbyteA[mi] + ((ki * 32 + a_koff) ^ swzA);
                ldsm4(ah, aa);
#pragma unroll
                for (int ni = 0; ni < 2; ni++) {
                    mma16816(C[mi][ni], ah, bhf[ni]);
                    mma16816(C[mi][ni], ah, blf[ni]);
                }
            }
        }
        __syncthreads();
        if (nt + 2 < KV_NT) { load_B(nt + 2, p); CP_COMMIT(); }

#pragma unroll
        for (int mi = 0; mi < 4; mi++) {
#pragma unroll
            for (int ni = 0; ni < 2; ni++) {
                const int col = nt * 64 + wn * 16 + ni * 8 + qp * 2;
#pragma unroll
                for (int e = 0; e < 2; e++) {
                    const int ce = col + e;
                    if (ce >= 400) continue;
                    const float bia = bias[ce];
                    const int isV = (ce >= 200);
                    const int c2 = isV ? (ce - 200) : ce;
                    const int hh = c2 / 50, dd = c2 % 50;
                    __half* dsth = isV ? g_vh : g_kh;
#pragma unroll
                    for (int hf = 0; hf < 2; hf++) {
                        const int r = m_base + mi * 16 + g + hf * 8;
                        const int b = 2 * bp + (r >> 6);
                        const int tloc = n * 64 + (r & 63);
                        const float v = C[mi][ni][hf * 2 + e] * invS + bia;
                        const size_t idx = ((size_t)(b * 4 + hh) * 320 + tloc) * 56 + dd;
                        dsth[idx] = __float2half_rn(v * 32.f);
                    }
                }
            }
        }
    }
    // zero pad cols 50..55 (kh, vh)
    for (int i = tid; i < 3072; i += 256) {
        const int a = i / 1536, rem = i % 1536;
        const int bb = rem / 768, rem2 = rem % 768;
        const int hh = rem2 / 192, rem3 = rem2 % 192;
        const int tt = rem3 / 3, uo = rem3 % 3;
        const int bg = 2 * bp + bb;
        const int t = n * 64 + tt;
        __half* base = (a == 0) ? g_kh : g_vh;
        *((uint32_t*)(base + ((size_t)(bg * 4 + hh) * 320 + t) * 56 + 50) + uo) = 0u;
    }
}

// =====================================================================
// Attention HMMA: single-fp16 Q/K/V, 1-term QK^T and PV, 2 CTAs/SM
// =====================================================================
#define AT_Q  0
#define AT_K  8192
#define AT_V  49152
#define AT_RED  90112
#define AT_RED2 90624
#define AT_SMEM 91136
__global__ __launch_bounds__(256, 2) void attn_mma(int b0arg)
{
    extern __shared__ char smc[];
    const uint32_t sb = smem_u32(smc);
    const int tid = threadIdx.x, lane = tid & 31, wid = tid >> 5;
    const int h = blockIdx.x, b = blockIdx.y + b0arg;
    const size_t kvbase = ((size_t)b * 4 + h) * 320;
    const size_t qbase  = ((size_t)b * 4 + h) * 64;

    for (int i = tid; i < 704; i += 256) {
        uint32_t base; int row;
        if (i < 64)       { base = AT_Q; row = i; }
        else if (i < 384) { base = AT_K; row = i - 64; }
        else              { base = AT_V; row = i - 384; }
        *(uint4*)(smc + base + row * 128 + (112 ^ ((row & 7) << 4))) = make_uint4(0, 0, 0, 0);
    }
    for (int i = tid; i < 448; i += 256) {
        const int r = i / 7, u = i % 7;
        cp16(sb + AT_Q + r * 128 + ((u * 16) ^ ((r & 7) << 4)),
             g_qh + (qbase + r) * 56 + u * 8);
    }
    for (int i = tid; i < 2240; i += 256) {
        const int r = i / 7, u = i % 7;
        cp16(sb + AT_K + r * 128 + ((u * 16) ^ ((r & 7) << 4)),
             g_kh + (kvbase + r) * 56 + u * 8);
    }
    CP_COMMIT();
    for (int i = tid; i < 2240; i += 256) {
        const int r = i / 7, u = i % 7;
        cp16(sb + AT_V + r * 128 + ((u * 16) ^ ((r & 7) << 4)),
             g_vh + (kvbase + r) * 56 + u * 8);
    }
    CP_COMMIT();
    CP_WAIT1();
    __syncthreads();

    // ---- QK^T (1-term) ----
    const int wm = wid & 3, wn = wid >> 2;
    const int m_base = wm * 16, n_base = wn * 160;
    const int a_row  = m_base + (lane & 7) + ((lane >> 3) & 1) * 8;
    const int a_koff = (lane >> 4) * 16;
    const int b_row  = lane & 7;
    const int b_koff = ((lane >> 3) & 1) * 16;
    const int g = lane >> 2, qp = lane & 3;

    float C[20][4];
#pragma unroll
    for (int i = 0; i < 20; i++)
#pragma unroll
        for (int j = 0; j < 4; j++) C[i][j] = 0.f;

#pragma unroll
    for (int ks = 0; ks < 4; ks++) {
        uint32_t q4[4];
        ldsm4(q4, sb + AT_Q + a_row * 128 + ((ks * 32 + a_koff) ^ ((a_row & 7) << 4)));
#pragma unroll
        for (int ni = 0; ni < 20; ni++) {
            const int trow = n_base + ni * 8 + b_row;
            uint32_t k2[2];
            ldsm2(k2, sb + AT_K + trow * 128 + ((ks * 32 + b_koff) ^ ((trow & 7) << 4)));
            mma16816(C[ni], q4, k2);
        }
    }

    // ---- register softmax ----
    const float sc = 0.14142135623730951f / 1024.f;
#pragma unroll
    for (int ni = 0; ni < 20; ni++)
#pragma unroll
        for (int j = 0; j < 4; j++) C[ni][j] *= sc;

    float* RED1 = (float*)(smc + AT_RED);
    float* RED2 = (float*)(smc + AT_RED2);
    const int r0 = m_base + g;

    float m0 = -1e30f, m1 = -1e30f;
#pragma unroll
    for (int ni = 0; ni < 20; ni++) {
        m0 = fmaxf(m0, fmaxf(C[ni][0], C[ni][1]));
        m1 = fmaxf(m1, fmaxf(C[ni][2], C[ni][3]));
    }
    m0 = fmaxf(m0, __shfl_xor_sync(0xffffffffu, m0, 1));
    m0 = fmaxf(m0, __shfl_xor_sync(0xffffffffu, m0, 2));
    m1 = fmaxf(m1, __shfl_xor_sync(0xffffffffu, m1, 1));
    m1 = fmaxf(m1, __shfl_xor_sync(0xffffffffu, m1, 2));
    if (qp == 0) { RED1[wn * 64 + r0] = m0; RED1[wn * 64 + r0 + 8] = m1; }
    __syncthreads();
    const float M0 = fmaxf(RED1[r0], RED1[64 + r0]);
    const float M1 = fmaxf(RED1[r0 + 8], RED1[64 + r0 + 8]);

    float s0 = 0.f, s1 = 0.f;
#pragma unroll
    for (int ni = 0; ni < 20; ni++) {
        C[ni][0] = __expf(C[ni][0] - M0); s0 += C[ni][0];
        C[ni][1] = __expf(C[ni][1] - M0); s0 += C[ni][1];
        C[ni][2] = __expf(C[ni][2] - M1); s1 += C[ni][2];
        C[ni][3] = __expf(C[ni][3] - M1); s1 += C[ni][3];
    }
    s0 += __shfl_xor_sync(0xffffffffu, s0, 1);
    s0 += __shfl_xor_sync(0xffffffffu, s0, 2);
    s1 += __shfl_xor_sync(0xffffffffu, s1, 1);
    s1 += __shfl_xor_sync(0xffffffffu, s1, 2);
    if (qp == 0) { RED2[wn * 64 + r0] = s0; RED2[wn * 64 + r0 + 8] = s1; }
    __syncthreads();
    const float i0 = 1.f / (RED2[r0] + RED2[64 + r0]);
    const float i1 = 1.f / (RED2[r0 + 8] + RED2[64 + r0 + 8]);

    {
        const uint32_t sw0 = (r0 & 7) << 4;
        const uint32_t sw1 = ((r0 + 8) & 7) << 4;
#pragma unroll
        for (int ni = 0; ni < 20; ni++) {
            const int col = n_base + ni * 8 + qp * 2;
            const uint32_t ub = (col >> 3) * 16;
            const uint32_t off0 = r0 * 640 + (ub ^ sw0) + (col & 7) * 2;
            const uint32_t off1 = (r0 + 8) * 640 + (ub ^ sw1) + (col & 7) * 2;
            *(__half2*)(smc + AT_K + off0) =
                __halves2half2(__float2half_rn(C[ni][0] * i0), __float2half_rn(C[ni][1] * i0));
            *(__half2*)(smc + AT_K + off1) =
                __halves2half2(__float2half_rn(C[ni][2] * i1), __float2half_rn(C[ni][3] * i1));
        }
    }
    CP_WAIT0();
    __syncthreads();

    // ---- P @ V (1-term) ----
    const int wnv = wid >> 2;
    const int mv_base = (wid & 3) * 16;
    const int nv_base = wnv * 32;
    const int ntc = wnv ? 3 : 4;
    const int p_row = mv_base + (lane & 7) + ((lane >> 3) & 1) * 8;
    const int p_unit = lane >> 4;
    const int v_koff = (lane & 7) + ((lane >> 3) & 1) * 8;

    float O[4][4];
#pragma unroll
    for (int i = 0; i < 4; i++)
#pragma unroll
        for (int j = 0; j < 4; j++) O[i][j] = 0.f;

    for (int ks = 0; ks < 20; ks++) {
        uint32_t p4[4];
        ldsm4(p4, sb + AT_K + p_row * 640 + (((ks * 2 + p_unit) * 16) ^ ((p_row & 7) << 4)));
        const int krow = ks * 16 + v_koff;
        const uint32_t swk = (krow & 7) << 4;
#pragma unroll
        for (int nt = 0; nt < 4; nt++) {
            if (nt >= ntc) break;
            const int ncol = nv_base + nt * 8;
            uint32_t v2[2];
            ldsm2t(v2, sb + AT_V + krow * 128 + ((ncol * 2) ^ swk));
            mma16816(O[nt], p4, v2);
        }
    }

#pragma unroll
    for (int nt = 0; nt < 4; nt++) {
        if (nt >= ntc) break;
        const int d = nv_base + nt * 8 + qp * 2;
        if (d >= 50) continue;
#pragma unroll
        for (int hf = 0; hf < 2; hf++) {
            const int r = mv_base + g + hf * 8;
            const float o0 = O[nt][hf * 2 + 0];
            const float o1 = O[nt][hf * 2 + 1];
            const __half h0 = __float2half_rn(o0), h1 = __float2half_rn(o1);
            const size_t idx = ((size_t)b * 64 + r) * 200 + h * 50 + d;
            *(__half2*)(g_oh + idx) = __halves2half2(h0, h1);
            *(__half2*)(g_ol + idx) =
                __halves2half2(__float2half_rn(o0 - __half2float(h0)),
                               __float2half_rn(o1 - __half2float(h1)));
        }
    }
}

// =====================================================================
// Out projection HMMA: 3-term, A = O hi/lo, fp32 out
// =====================================================================
#define OM_AH 0
#define OM_AL 32768
#define OM_BH 65536
#define OM_BL 98304
#define OM_SMEM 131072
__global__ __launch_bounds__(256) void out_mma(const float* __restrict__ ob,
                                               float* __restrict__ outp, int b0arg)
{
    extern __shared__ char smc[];
    const uint32_t sb = smem_u32(smc);
    const int tid = threadIdx.x, lane = tid & 31, wid = tid >> 5;
    const int b = blockIdx.x + b0arg;
    const int wm = wid & 1, wn = wid >> 1;
    const int m_base = wm * 32;

    for (int i = tid; i < 896; i += 256) {
        const int a = i / 448, rem = i % 448;
        const int r = rem / 7, u = 1 + rem % 7;
        const uint32_t off = (a ? OM_AL : OM_AH) + 3 * 8192 + r * 128 + ((u * 16) ^ ((r & 7) << 4));
        *(uint4*)(smc + off) = make_uint4(0, 0, 0, 0);
    }
    const size_t abase = (size_t)b * 64 * 200;
    for (int i = tid; i < 3200; i += 256) {
        const int a = i / 1600, rem = i % 1600;
        const int r = rem / 25, cu = rem % 25, ch = cu >> 3, u = cu & 7;
        const __half* src = (a ? g_ol : g_oh) + abase + (size_t)r * 200 + ch * 64 + u * 8;
        cp16(sb + (a ? OM_AL : OM_AH) + ch * 8192 + r * 128 + ((u * 16) ^ ((r & 7) << 4)), src);
    }
    CP_COMMIT();
    CP_WAIT0();

    const int a_row  = (lane & 7) + ((lane >> 3) & 1) * 8;
    const int a_koff = (lane >> 4) * 16;
    const int b_row  = lane & 7;
    const int b_koff = ((lane >> 3) & 1) * 16;

    float C[2][8][4];
#pragma unroll
    for (int a = 0; a < 2; a++)
#pragma unroll
        for (int n = 0; n < 8; n++)
#pragma unroll
            for (int c = 0; c < 4; c++) C[a][n][c] = 0.f;

    for (int ck = 0; ck < 4; ck++) {
        __syncthreads();
        for (int i = tid; i < 4096; i += 256) {
            const int a = i / 2048, rem = i % 2048;
            const int r = rem >> 3, u = rem & 7;
            const __half* src = (a ? g_wol : g_woh) + (size_t)r * 256 + ck * 64 + u * 8;
            cp16(sb + (a ? OM_BL : OM_BH) + r * 128 + ((u * 16) ^ ((r & 7) << 4)), src);
        }
        CP_COMMIT();
        CP_WAIT0();
        __syncthreads();
        const int nks = (ck < 3) ? 4 : 1;
        for (int ks = 0; ks < nks; ks++) {
            uint32_t bhf[8][2], blf[8][2];
#pragma unroll
            for (int ni = 0; ni < 8; ni++) {
                const int nr = wn * 64 + ni * 8 + b_row;
                const uint32_t ad = sb + OM_BH + nr * 128 + ((ks * 32 + b_koff) ^ ((nr & 7) << 4));
                ldsm2(bhf[ni], ad);
                ldsm2(blf[ni], ad + 32768);
            }
#pragma unroll
            for (int mi = 0; mi < 2; mi++) {
                const int ar = m_base + mi * 16 + a_row;
                uint32_t ah[4], al[4];
                const uint32_t aa = sb + OM_AH + ck * 8192 + ar * 128 + ((ks * 32 + a_koff) ^ ((ar & 7) << 4));
                ldsm4(ah, aa);
                ldsm4(al, aa + 32768);
#pragma unroll
                for (int ni = 0; ni < 8; ni++) {
                    mma16816(C[mi][ni], ah, bhf[ni]);
                    mma16816(C[mi][ni], ah, blf[ni]);
                    mma16816(C[mi][ni], al, bhf[ni]);
                }
            }
        }
    }

    const int g = lane >> 2, qp = lane & 3;
    const float invS = 1.f / 8192.f;
#pragma unroll
    for (int mi = 0; mi < 2; mi++) {
#pragma unroll
        for (int ni = 0; ni < 8; ni++) {
            const int jj = wn * 64 + ni * 8 + qp * 2;
            if (jj >= 200) continue;
            const float b0 = __ldg(ob + jj), b1 = __ldg(ob + jj + 1);
#pragma unroll
            for (int hf = 0; hf < 2; hf++) {
                const int r = m_base + mi * 16 + g + hf * 8;
                *(float2*)(outp + ((size_t)b * 64 + r) * 200 + jj) =
                    make_float2(C[mi][ni][hf * 2 + 0] * invS + b0,
                                C[mi][ni][hf * 2 + 1] * invS + b1);
            }
        }
    }
}

// =====================================================================
// launch: forked streams + split-batch tail pipelining
// =====================================================================
struct LaunchRes {
    cudaStream_t s1, s2;
    cudaEvent_t e0, eA, eW1, eKV0, eKV1, eQ, eT1;
    LaunchRes() {
        cudaStreamCreateWithFlags(&s1, cudaStreamNonBlocking);
        cudaStreamCreateWithFlags(&s2, cudaStreamNonBlocking);
        cudaEventCreateWithFlags(&e0,   cudaEventDisableTiming);
        cudaEventCreateWithFlags(&eA,   cudaEventDisableTiming);
        cudaEventCreateWithFlags(&eW1,  cudaEventDisableTiming);
        cudaEventCreateWithFlags(&eKV0, cudaEventDisableTiming);
        cudaEventCreateWithFlags(&eKV1, cudaEventDisableTiming);
        cudaEventCreateWithFlags(&eQ,   cudaEventDisableTiming);
        cudaEventCreateWithFlags(&eT1,  cudaEventDisableTiming);
    }
};

extern "C" void kernel_launch(void* const* d_in, const int* in_sizes, int n_in,
                              void* d_out, int out_size)
{
    const float* bands = (const float*)d_in[0];
    const float* w1    = (const float*)d_in[1];
    const float* b1    = (const float*)d_in[2];
    const float* w2    = (const float*)d_in[3];
    const float* b2    = (const float*)d_in[4];
    const float* ipw   = (const float*)d_in[5];
    const float* ipb   = (const float*)d_in[6];
    const float* ow    = (const float*)d_in[7];
    const float* ob    = (const float*)d_in[8];
    float* outp = (float*)d_out;

    static LaunchRes R;

    cudaFuncSetAttribute(router_mma, cudaFuncAttributeMaxDynamicSharedMemorySize, R_SMEM);
    cudaFuncSetAttribute(kv_mma, cudaFuncAttributeMaxDynamicSharedMemorySize, KV_SMEM);
    cudaFuncSetAttribute(q_mma, cudaFuncAttributeMaxDynamicSharedMemorySize, QM_SMEM);
    cudaFuncSetAttribute(out_mma, cudaFuncAttributeMaxDynamicSharedMemorySize, OM_SMEM);
    cudaFuncSetAttribute(attn_mma, cudaFuncAttributeMaxDynamicSharedMemorySize, AT_SMEM);

    __half *bh, *blp, *w1h, *w1l, *wqh, *wql, *woh, *wol;
    cudaGetSymbolAddress((void**)&bh,  g_bh);
    cudaGetSymbolAddress((void**)&blp, g_bl);
    cudaGetSymbolAddress((void**)&w1h, g_w1h);
    cudaGetSymbolAddress((void**)&w1l, g_w1l);
    cudaGetSymbolAddress((void**)&wqh, g_wqh);
    cudaGetSymbolAddress((void**)&wql, g_wql);
    cudaGetSymbolAddress((void**)&woh, g_woh);
    cudaGetSymbolAddress((void**)&wol, g_wol);

    const int n4 = (NB * (int)BAND_STRIDE) / 4;

    // fork
    cudaEventRecord(R.e0, 0);
    cudaStreamWaitEvent(R.s1, R.e0, 0);
    cudaStreamWaitEvent(R.s2, R.e0, 0);

    // s2: w1 conversion
    conv_split<<<(n4 + 255) / 256, 256, 0, R.s2>>>(w1, w1h, w1l, n4, 256.f);
    cudaEventRecord(R.eW1, R.s2);

    // s1: kv weight conversion
    conv_wkv_k<<<448, 256, 0, R.s1>>>(ipw);

    // default: bands conversion + small weight convs
    conv_split<<<(n4 + 255) / 256, 256>>>(bands, bh, blp, n4, 4.f);
    cudaEventRecord(R.eA, 0);
    conv_w256<<<256, 256>>>(ipw, wqh, wql);
    conv_w256<<<256, 256>>>(ow, woh, wol);

    // s1: kv projection in two batch-halves
    cudaStreamWaitEvent(R.s1, R.eA, 0);
    kv_mma<<<dim3(NB, 128), 256, KV_SMEM, R.s1>>>(ipb, 0);     // batches 0..255
    cudaEventRecord(R.eKV0, R.s1);
    kv_mma<<<dim3(NB, 128), 256, KV_SMEM, R.s1>>>(ipb, 128);   // batches 256..511
    cudaEventRecord(R.eKV1, R.s1);

    // default: router chain
    cudaStreamWaitEvent(0, R.eW1, 0);
    router_mma   <<<dim3(8, 4, R_NSPLIT), 256, R_SMEM>>>();
    router_select<<<BATCH, 128>>>(b1, w2, b2);
    q_mma        <<<BATCH, 256, QM_SMEM>>>(ipb);
    cudaEventRecord(R.eQ, 0);

    // half 1 (batches 256..511) on s1 after its kv + q
    cudaStreamWaitEvent(R.s1, R.eQ, 0);
    attn_mma<<<dim3(HEADS, 256), 256, AT_SMEM, R.s1>>>(256);
    out_mma <<<256, 256, OM_SMEM, R.s1>>>(ob, outp, 256);
    cudaEventRecord(R.eT1, R.s1);

    // half 0 on default
    cudaStreamWaitEvent(0, R.eKV0, 0);
    attn_mma<<<dim3(HEADS, 256), 256, AT_SMEM>>>(0);
    out_mma <<<256, 256, OM_SMEM>>>(ob, outp, 0);

    // join
    cudaStreamWaitEvent(0, R.eT1, 0);
}

// round 15
// speedup vs baseline: 1.6453x; 1.0222x over previous
#include <cuda_runtime.h>
#include <cuda_fp16.h>
#include <cstdint>
#include <math.h>

// ---------------- problem constants ----------------
#define NB 5
#define BATCH 512
#define KQ 64
#define D 200
#define HEADS 4
#define HD 50
#define TKV 320
#define HID 512
#define FIN 64000
#define BAND_STRIDE 6553600ull   // BATCH*KQ*D (elements)
#define ROW_STRIDE 12800         // KQ*D
#define R_NSPLIT 9

// ---------------- scratch ----------------
__device__ float  g_hpart[(size_t)R_NSPLIT * BATCH * HID];
__device__ int    g_sel[BATCH];
__device__ __half g_bh [(size_t)NB * BAND_STRIDE];   // bands * 4, hi
__device__ __half g_bl [(size_t)NB * BAND_STRIDE];   // bands * 4, lo
__device__ __half g_w1h[(size_t)HID * FIN];          // w1 * 256, hi
__device__ __half g_w1l[(size_t)HID * FIN];          // w1 * 256, lo
__device__ __half g_wkvh[448 * 256];                 // wk|wv * 256 padded, hi
__device__ __half g_wkvl[448 * 256];                 // lo
__device__ __half g_wqh[256 * 256];                  // wq * 256 padded, hi
__device__ __half g_wql[256 * 256];                  // lo
__device__ __half g_woh[256 * 256];                  // out_w * 256 padded, hi
__device__ __half g_wol[256 * 256];                  // lo
// head-split padded layouts, values scaled *32, pad cols 50..55 zero (single fp16)
__device__ __half g_qh[(size_t)BATCH * HEADS * 64 * 56];
__device__ __half g_kh[(size_t)BATCH * HEADS * 320 * 56];
__device__ __half g_vh[(size_t)BATCH * HEADS * 320 * 56];
// attention output, scaled *32, [b*64][200], single fp16
__device__ __half g_oh[(size_t)BATCH * KQ * D];

// =====================================================================
// helpers
// =====================================================================
__device__ __forceinline__ uint32_t smem_u32(const void* p) {
    uint32_t a;
    asm("{ .reg .u64 t; cvta.to.shared.u64 t, %1; cvt.u32.u64 %0, t; }" : "=r"(a) : "l"(p));
    return a;
}
__device__ __forceinline__ void cp16(uint32_t dst, const void* src) {
    asm volatile("cp.async.cg.shared.global [%0], [%1], 16;" :: "r"(dst), "l"(src));
}
#define CP_COMMIT() asm volatile("cp.async.commit_group;" ::: "memory")
#define CP_WAIT2()  asm volatile("cp.async.wait_group 2;" ::: "memory")
#define CP_WAIT1()  asm volatile("cp.async.wait_group 1;" ::: "memory")
#define CP_WAIT0()  asm volatile("cp.async.wait_group 0;" ::: "memory")

__device__ __forceinline__ void ldsm4(uint32_t* r, uint32_t a) {
    asm volatile("ldmatrix.sync.aligned.m8n8.x4.shared.b16 {%0,%1,%2,%3}, [%4];"
        : "=r"(r[0]), "=r"(r[1]), "=r"(r[2]), "=r"(r[3]) : "r"(a));
}
__device__ __forceinline__ void ldsm4t(uint32_t* r, uint32_t a) {
    asm volatile("ldmatrix.sync.aligned.m8n8.x4.trans.shared.b16 {%0,%1,%2,%3}, [%4];"
        : "=r"(r[0]), "=r"(r[1]), "=r"(r[2]), "=r"(r[3]) : "r"(a));
}
__device__ __forceinline__ void ldsm2(uint32_t* r, uint32_t a) {
    asm volatile("ldmatrix.sync.aligned.m8n8.x2.shared.b16 {%0,%1}, [%2];"
        : "=r"(r[0]), "=r"(r[1]) : "r"(a));
}
__device__ __forceinline__ void mma16816(float* c, const uint32_t* a, const uint32_t* b) {
    asm volatile("mma.sync.aligned.m16n8k16.row.col.f32.f16.f16.f32 "
        "{%0,%1,%2,%3}, {%4,%5,%6,%7}, {%8,%9}, {%0,%1,%2,%3};"
        : "+f"(c[0]), "+f"(c[1]), "+f"(c[2]), "+f"(c[3])
        : "r"(a[0]), "r"(a[1]), "r"(a[2]), "r"(a[3]), "r"(b[0]), "r"(b[1]));
}

// =====================================================================
// Conversion kernels
// =====================================================================
__global__ __launch_bounds__(256) void conv_split(const float* __restrict__ src,
                                                  __half* __restrict__ dh,
                                                  __half* __restrict__ dl,
                                                  int n4, float s)
{
    int i = blockIdx.x * blockDim.x + threadIdx.x;
    if (i >= n4) return;
    float4 v = ((const float4*)src)[i];
    float x0 = v.x * s, x1 = v.y * s, x2 = v.z * s, x3 = v.w * s;
    __half h0 = __float2half_rn(x0), h1 = __float2half_rn(x1);
    __half h2 = __float2half_rn(x2), h3 = __float2half_rn(x3);
    __half l0 = __float2half_rn(x0 - __half2float(h0));
    __half l1 = __float2half_rn(x1 - __half2float(h1));
    __half l2 = __float2half_rn(x2 - __half2float(h2));
    __half l3 = __float2half_rn(x3 - __half2float(h3));
    ((__half2*)dh)[2 * i]     = __halves2half2(h0, h1);
    ((__half2*)dh)[2 * i + 1] = __halves2half2(h2, h3);
    ((__half2*)dl)[2 * i]     = __halves2half2(l0, l1);
    ((__half2*)dl)[2 * i + 1] = __halves2half2(l2, l3);
}

__global__ __launch_bounds__(256) void conv_wkv_k(const float* __restrict__ ipw)
{
    const int row = blockIdx.x;
    const int col = threadIdx.x;
    float v = 0.f;
    if (row < 400 && col < 200) v = ipw[(size_t)(200 + row) * 200 + col] * 256.f;
    __half h = __float2half_rn(v);
    __half l = __float2half_rn(v - __half2float(h));
    g_wkvh[row * 256 + col] = h;
    g_wkvl[row * 256 + col] = l;
}

__global__ __launch_bounds__(256) void conv_w256(const float* __restrict__ W,
                                                 __half* __restrict__ dh,
                                                 __half* __restrict__ dl)
{
    const int row = blockIdx.x;
    const int col = threadIdx.x;
    float v = 0.f;
    if (row < 200 && col < 200) v = W[(size_t)row * 200 + col] * 256.f;
    __half h = __float2half_rn(v);
    __half l = __float2half_rn(v - __half2float(h));
    dh[row * 256 + col] = h;
    dl[row * 256 + col] = l;
}

// =====================================================================
// Router GEMM: M=128, N=64, kc=64, splitK=9, 2-stage cp.async, 2 CTAs/SM
// (unchanged from R14)
// =====================================================================
#define R_STAGE 49152
#define R_SMEM (2 * R_STAGE)
__global__ __launch_bounds__(256, 2) void router_mma(void)
{
    extern __shared__ char smc[];
    const uint32_t sb = smem_u32(smc);
    const int tid = threadIdx.x, lane = tid & 31, wid = tid >> 5;
    const int jt = blockIdx.x, mt = blockIdx.y, sp = blockIdx.z;
    const int b0 = mt * 128, j0 = jt * 64;
    const int wm = wid & 1, wn = wid >> 1;
    const int m_base = wm * 64;

    const int a_row  = (lane & 7) + ((lane >> 3) & 1) * 8;
    const int a_koff = (lane >> 4) * 16;
    const int bl_    = lane & 15;
    const int b_row  = bl_ & 7;
    const int b_koff = (bl_ >> 3) * 16;
    int rowbyteA[4], rowbyteB[2];
#pragma unroll
    for (int mi = 0; mi < 4; mi++) rowbyteA[mi] = (m_base + mi * 16 + a_row) * 128;
#pragma unroll
    for (int ni = 0; ni < 2; ni++) rowbyteB[ni] = (wn * 16 + ni * 8 + b_row) * 128;
    const int swzA = (lane & 7) << 4;
    const int swzB = b_row << 4;

    float C[4][2][4];
#pragma unroll
    for (int a = 0; a < 4; a++)
#pragma unroll
        for (int b = 0; b < 2; b++)
#pragma unroll
            for (int c = 0; c < 4; c++) C[a][b][c] = 0.f;

    const int cbeg = sp * 111 + (sp > 0 ? 1 : 0);
    const int cnt  = 111 + (sp == 0 ? 1 : 0);

    auto issue_chunk = [&](int c, int p) {
        const int n = c / 200;
        const int rr = (c - n * 200) * 64;
        const __half* Ah = g_bh + (size_t)n * BAND_STRIDE + (size_t)b0 * ROW_STRIDE + rr;
        const __half* Al = g_bl + (size_t)n * BAND_STRIDE + (size_t)b0 * ROW_STRIDE + rr;
        const size_t f0 = (size_t)c * 64;
        const uint32_t so = sb + p * R_STAGE;
#pragma unroll
        for (int j = 0; j < 4; j++) {
            const int u = tid + j * 256;
            const int row = u >> 3, uu = u & 7;
            const uint32_t d = row * 128 + ((uu * 16) ^ ((row & 7) << 4));
            cp16(so + d,         Ah + (size_t)row * ROW_STRIDE + uu * 8);
            cp16(so + 16384 + d, Al + (size_t)row * ROW_STRIDE + uu * 8);
        }
#pragma unroll
        for (int j = 0; j < 2; j++) {
            const int u = tid + j * 256;
            const int row = u >> 3, uu = u & 7;
            const uint32_t d = row * 128 + ((uu * 16) ^ ((row & 7) << 4));
            cp16(so + 32768 + d, g_w1h + (size_t)(j0 + row) * FIN + f0 + uu * 8);
            cp16(so + 40960 + d, g_w1l + (size_t)(j0 + row) * FIN + f0 + uu * 8);
        }
    };

    issue_chunk(cbeg, 0);
    CP_COMMIT();
    if (cnt > 1) { issue_chunk(cbeg + 1, 1); CP_COMMIT(); }

    for (int c = 0; c < cnt; c++) {
        const int p = c & 1;
        if (c + 1 < cnt) CP_WAIT1(); else CP_WAIT0();
        __syncthreads();
        const uint32_t so = sb + p * R_STAGE;
#pragma unroll
        for (int ks = 0; ks < 4; ks++) {
            uint32_t bhf[2][2], blf[2][2];
#pragma unroll
            for (int ni = 0; ni < 2; ni++) {
                const uint32_t ad = so + 32768 + rowbyteB[ni] + ((ks * 32 + b_koff) ^ swzB);
                ldsm2(bhf[ni], ad);
                ldsm2(blf[ni], ad + 8192);
            }
#pragma unroll
            for (int mi = 0; mi < 4; mi++) {
                uint32_t ah[4], al[4];
                const uint32_t aa = so + rowbyteA[mi] + ((ks * 32 + a_koff) ^ swzA);
                ldsm4(ah, aa);
                ldsm4(al, aa + 16384);
#pragma unroll
                for (int ni = 0; ni < 2; ni++) {
                    mma16816(C[mi][ni], ah, bhf[ni]);
                    mma16816(C[mi][ni], ah, blf[ni]);
                    mma16816(C[mi][ni], al, bhf[ni]);
                }
            }
        }
        __syncthreads();
        if (c + 2 < cnt) { issue_chunk(cbeg + c + 2, p); CP_COMMIT(); }
    }

    const float invS = 1.f / 1024.f;
    float* outp = g_hpart + (size_t)sp * (BATCH * HID);
    const int g = lane >> 2, qp = lane & 3;
#pragma unroll
    for (int mi = 0; mi < 4; mi++) {
#pragma unroll
        for (int ni = 0; ni < 2; ni++) {
            const int row = b0 + m_base + mi * 16 + g;
            const int col = j0 + wn * 16 + ni * 8 + qp * 2;
            *(float2*)(outp + (size_t)row * HID + col) =
                make_float2(C[mi][ni][0] * invS, C[mi][ni][1] * invS);
            *(float2*)(outp + (size_t)(row + 8) * HID + col) =
                make_float2(C[mi][ni][2] * invS, C[mi][ni][3] * invS);
        }
    }
}

// =====================================================================
// Router select
// =====================================================================
__global__ __launch_bounds__(128) void router_select(const float* __restrict__ b1,
                                                     const float* __restrict__ w2,
                                                     const float* __restrict__ b2)
{
    const int b = blockIdx.x, tid = threadIdx.x;
    float acc[NB] = {0.f, 0.f, 0.f, 0.f, 0.f};
    for (int j = tid; j < HID; j += 128) {
        float hv = b1[j];
#pragma unroll
        for (int s = 0; s < R_NSPLIT; s++)
            hv += g_hpart[(size_t)s * BATCH * HID + (size_t)b * HID + j];
        hv = fmaxf(hv, 0.f);
#pragma unroll
        for (int n = 0; n < NB; n++) acc[n] += hv * w2[n * HID + j];
    }
    __shared__ float red[NB][128];
#pragma unroll
    for (int n = 0; n < NB; n++) red[n][tid] = acc[n];
    __syncthreads();
    for (int s = 64; s > 0; s >>= 1) {
        if (tid < s) {
#pragma unroll
            for (int n = 0; n < NB; n++) red[n][tid] += red[n][tid + s];
        }
        __syncthreads();
    }
    if (tid == 0) {
        int best = 0;
        float bv = red[0][0] + b2[0];
        for (int n = 1; n < NB; n++) {
            float v = red[n][0] + b2[n];
            if (v > bv) { bv = v; best = n; }
        }
        g_sel[b] = best;
    }
}

// =====================================================================
// Q projection HMMA (2-term), single-fp16 Q output, 2 CTAs/SM
// =====================================================================
#define QM_AH 0
#define QM_BH 32768
#define QM_BL 65536
#define QM_SMEM 98304
__global__ __launch_bounds__(256, 2) void q_mma(const float* __restrict__ ipb)
{
    extern __shared__ char smc[];
    const uint32_t sb = smem_u32(smc);
    const int tid = threadIdx.x, lane = tid & 31, wid = tid >> 5;
    const int b = blockIdx.x;
    const int wm = wid & 1, wn = wid >> 1;
    const int m_base = wm * 32;

    for (int i = tid; i < 448; i += 256) {
        const int r = i / 7, u = 1 + i % 7;
        const uint32_t off = QM_AH + 3 * 8192 + r * 128 + ((u * 16) ^ ((r & 7) << 4));
        *(uint4*)(smc + off) = make_uint4(0, 0, 0, 0);
    }
    const size_t abase = (size_t)g_sel[b] * BAND_STRIDE + (size_t)b * ROW_STRIDE;
    for (int i = tid; i < 1600; i += 256) {
        const int r = i / 25, cu = i % 25, ch = cu >> 3, u = cu & 7;
        const __half* src = g_bh + abase + (size_t)r * 200 + ch * 64 + u * 8;
        cp16(sb + QM_AH + ch * 8192 + r * 128 + ((u * 16) ^ ((r & 7) << 4)), src);
    }
    CP_COMMIT();
    CP_WAIT0();

    const int a_row  = (lane & 7) + ((lane >> 3) & 1) * 8;
    const int a_koff = (lane >> 4) * 16;
    const int b_row  = lane & 7;
    const int b_koff = ((lane >> 3) & 1) * 16;

    float C[2][8][4];
#pragma unroll
    for (int a = 0; a < 2; a++)
#pragma unroll
        for (int n = 0; n < 8; n++)
#pragma unroll
            for (int c = 0; c < 4; c++) C[a][n][c] = 0.f;

    for (int ck = 0; ck < 4; ck++) {
        __syncthreads();
        for (int i = tid; i < 4096; i += 256) {
            const int a = i / 2048, rem = i % 2048;
            const int r = rem >> 3, u = rem & 7;
            const __half* src = (a ? g_wql : g_wqh) + (size_t)r * 256 + ck * 64 + u * 8;
            cp16(sb + (a ? QM_BL : QM_BH) + r * 128 + ((u * 16) ^ ((r & 7) << 4)), src);
        }
        CP_COMMIT();
        CP_WAIT0();
        __syncthreads();
        const int nks = (ck < 3) ? 4 : 1;
        for (int ks = 0; ks < nks; ks++) {
            uint32_t bhf[8][2], blf[8][2];
#pragma unroll
            for (int ni = 0; ni < 8; ni++) {
                const int nr = wn * 64 + ni * 8 + b_row;
                const uint32_t ad = sb + QM_BH + nr * 128 + ((ks * 32 + b_koff) ^ ((nr & 7) << 4));
                ldsm2(bhf[ni], ad);
                ldsm2(blf[ni], ad + 32768);
            }
#pragma unroll
            for (int mi = 0; mi < 2; mi++) {
                const int ar = m_base + mi * 16 + a_row;
                uint32_t ah[4];
                const uint32_t aa = sb + QM_AH + ck * 8192 + ar * 128 + ((ks * 32 + a_koff) ^ ((ar & 7) << 4));
                ldsm4(ah, aa);
#pragma unroll
                for (int ni = 0; ni < 8; ni++) {
                    mma16816(C[mi][ni], ah, bhf[ni]);
                    mma16816(C[mi][ni], ah, blf[ni]);
                }
            }
        }
    }

    const int g = lane >> 2, qp = lane & 3;
    const float invS = 1.f / 1024.f;
#pragma unroll
    for (int mi = 0; mi < 2; mi++) {
#pragma unroll
        for (int ni = 0; ni < 8; ni++) {
            const int j = wn * 64 + ni * 8 + qp * 2;
#pragma unroll
            for (int e = 0; e < 2; e++) {
                const int jj = j + e;
                if (jj >= 200) continue;
                const int hh = jj / 50, dd = jj % 50;
                const float bia = __ldg(ipb + jj);
#pragma unroll
                for (int hf = 0; hf < 2; hf++) {
                    const int r = m_base + mi * 16 + g + hf * 8;
                    const float v = C[mi][ni][hf * 2 + e] * invS + bia;
                    const size_t idx = ((size_t)(b * 4 + hh) * 64 + r) * 56 + dd;
                    g_qh[idx] = __float2half_rn(v * 32.f);
                }
            }
        }
    }
    for (int i = tid; i < 768; i += 256) {
        const int hh = i / 192, rem2 = i % 192;
        const int t = rem2 / 3, uo = rem2 % 3;
        *((uint32_t*)(g_qh + ((size_t)(b * 4 + hh) * 64 + t) * 56 + 50) + uo) = 0u;
    }
}

// =====================================================================
// K/V projection HMMA (2-term), single-fp16 K/V, B tiles double-buffered
// (unchanged from R14)
// =====================================================================
#define KV_AH 0
#define KV_B  65536
#define KV_BIAS 196608
#define KV_SMEM (196608 + 1664)
#define KV_NT 7
__global__ __launch_bounds__(256) void kv_mma(const float* __restrict__ ipb, int bp0)
{
    extern __shared__ char smc[];
    const uint32_t sb = smem_u32(smc);
    const int tid = threadIdx.x, lane = tid & 31, wid = tid >> 5;
    const int n = blockIdx.x, bp = blockIdx.y + bp0;
    const int wm = wid & 1, wn = wid >> 1;
    const int m_base = wm * 64;

    float* bias = (float*)(smc + KV_BIAS);
    for (int i = tid; i < 400; i += 256) bias[i] = ipb[200 + i];

#pragma unroll
    for (int j = 0; j < 4; j++) {
        const int u = tid + j * 256;
        if (u < 896) {
            const int row = u / 7, uu = 1 + (u % 7);
            const uint32_t d = 3 * 16384 + row * 128 + ((uu * 16) ^ ((row & 7) << 4));
            *(uint4*)(smc + KV_AH + d) = make_uint4(0, 0, 0, 0);
        }
    }

    auto load_B = [&](int nt, int p) {
        const uint32_t so = sb + KV_B + p * 65536;
#pragma unroll
        for (int j = 0; j < 8; j++) {
            const int u = tid + j * 256;
            const int lr = u >> 5;
            const int rem = u & 31;
            const int ch = rem >> 3, uu = rem & 7;
            const int nr = nt * 64 + lr;
            const uint32_t d = ch * 8192 + lr * 128 + ((uu * 16) ^ ((lr & 7) << 4));
            cp16(so + d,         g_wkvh + (size_t)nr * 256 + ch * 64 + uu * 8);
            cp16(so + 32768 + d, g_wkvl + (size_t)nr * 256 + ch * 64 + uu * 8);
        }
    };

    {
        const size_t abase = (size_t)n * BAND_STRIDE + (size_t)(bp * 128) * 200;
#pragma unroll
        for (int j = 0; j < 13; j++) {
            const int u = tid + j * 256;
            if (u < 3200) {
                const int row = u / 25;
                const int rem = u - row * 25;
                const int ch = rem >> 3, uu = rem & 7;
                const uint32_t d = ch * 16384 + row * 128 + ((uu * 16) ^ ((row & 7) << 4));
                cp16(sb + KV_AH + d, g_bh + abase + (size_t)row * 200 + ch * 64 + uu * 8);
            }
        }
    }
    CP_COMMIT();
    load_B(0, 0); CP_COMMIT();
    load_B(1, 1); CP_COMMIT();
    CP_WAIT2();
    __syncthreads();

    const int a_row  = (lane & 7) + ((lane >> 3) & 1) * 8;
    const int a_koff = (lane >> 4) * 16;
    const int bl_    = lane & 15;
    const int b_row  = bl_ & 7;
    const int b_koff = (bl_ >> 3) * 16;
    int rowbyteA[4], rowbyteB[2];
#pragma unroll
    for (int mi = 0; mi < 4; mi++) rowbyteA[mi] = (m_base + mi * 16 + a_row) * 128;
#pragma unroll
    for (int ni = 0; ni < 2; ni++) rowbyteB[ni] = (wn * 16 + ni * 8 + b_row) * 128;
    const int swzA = (lane & 7) << 4;
    const int swzB = b_row << 4;
    const int g = lane >> 2, qp = lane & 3;
    const float invS = 1.f / 1024.f;

    for (int nt = 0; nt < KV_NT; nt++) {
        const int p = nt & 1;
        if (nt + 1 < KV_NT) CP_WAIT1(); else CP_WAIT0();
        __syncthreads();
        const uint32_t soB = sb + KV_B + p * 65536;

        float C[4][2][4];
#pragma unroll
        for (int a = 0; a < 4; a++)
#pragma unroll
            for (int b = 0; b < 2; b++)
#pragma unroll
                for (int c = 0; c < 4; c++) C[a][b][c] = 0.f;

        for (int ks = 0; ks < 13; ks++) {
            const int ch = ks >> 2, ki = ks & 3;
            uint32_t bhf[2][2], blf[2][2];
#pragma unroll
            for (int ni = 0; ni < 2; ni++) {
                const uint32_t ad = soB + ch * 8192 + rowbyteB[ni] + ((ki * 32 + b_koff) ^ swzB);
                ldsm2(bhf[ni], ad);
                ldsm2(blf[ni], ad + 32768);
            }
#pragma unroll
            for (int mi = 0; mi < 4; mi++) {
                uint32_t ah[4];
                const uint32_t aa = sb + KV_AH + ch * 16384 + rowbyteA[mi] + ((ki * 32 + a_koff) ^ swzA);
                ldsm4(ah, aa);
#pragma unroll
                for (int ni = 0; ni < 2; ni++) {
                    mma16816(C[mi][ni], ah, bhf[ni]);
                    mma16816(C[mi][ni], ah, blf[ni]);
                }
            }
        }
        __syncthreads();
        if (nt + 2 < KV_NT) { load_B(nt + 2, p); CP_COMMIT(); }

#pragma unroll
        for (int mi = 0; mi < 4; mi++) {
#pragma unroll
            for (int ni = 0; ni < 2; ni++) {
                const int col = nt * 64 + wn * 16 + ni * 8 + qp * 2;
#pragma unroll
                for (int e = 0; e < 2; e++) {
                    const int ce = col + e;
                    if (ce >= 400) continue;
                    const float bia = bias[ce];
                    const int isV = (ce >= 200);
                    const int c2 = isV ? (ce - 200) : ce;
                    const int hh = c2 / 50, dd = c2 % 50;
                    __half* dsth = isV ? g_vh : g_kh;
#pragma unroll
                    for (int hf = 0; hf < 2; hf++) {
                        const int r = m_base + mi * 16 + g + hf * 8;
                        const int b = 2 * bp + (r >> 6);
                        const int tloc = n * 64 + (r & 63);
                        const float v = C[mi][ni][hf * 2 + e] * invS + bia;
                        const size_t idx = ((size_t)(b * 4 + hh) * 320 + tloc) * 56 + dd;
                        dsth[idx] = __float2half_rn(v * 32.f);
                    }
                }
            }
        }
    }
    for (int i = tid; i < 3072; i += 256) {
        const int a = i / 1536, rem = i % 1536;
        const int bb = rem / 768, rem2 = rem % 768;
        const int hh = rem2 / 192, rem3 = rem2 % 192;
        const int tt = rem3 / 3, uo = rem3 % 3;
        const int bg = 2 * bp + bb;
        const int t = n * 64 + tt;
        __half* base = (a == 0) ? g_kh : g_vh;
        *((uint32_t*)(base + ((size_t)(bg * 4 + hh) * 320 + t) * 56 + 50) + uo) = 0u;
    }
}

// =====================================================================
// Attention HMMA: single-fp16 Q/K/V, 1-term, paired ldsm4/x4.trans,
// register softmax, single-fp16 O output, 2 CTAs/SM
// =====================================================================
#define AT_Q  0
#define AT_K  8192
#define AT_V  49152
#define AT_RED  90112
#define AT_RED2 90624
#define AT_SMEM 91136
__global__ __launch_bounds__(256, 2) void attn_mma(int b0arg)
{
    extern __shared__ char smc[];
    const uint32_t sb = smem_u32(smc);
    const int tid = threadIdx.x, lane = tid & 31, wid = tid >> 5;
    const int h = blockIdx.x, b = blockIdx.y + b0arg;
    const size_t kvbase = ((size_t)b * 4 + h) * 320;
    const size_t qbase  = ((size_t)b * 4 + h) * 64;

    for (int i = tid; i < 704; i += 256) {
        uint32_t base; int row;
        if (i < 64)       { base = AT_Q; row = i; }
        else if (i < 384) { base = AT_K; row = i - 64; }
        else              { base = AT_V; row = i - 384; }
        *(uint4*)(smc + base + row * 128 + (112 ^ ((row & 7) << 4))) = make_uint4(0, 0, 0, 0);
    }
    for (int i = tid; i < 448; i += 256) {
        const int r = i / 7, u = i % 7;
        cp16(sb + AT_Q + r * 128 + ((u * 16) ^ ((r & 7) << 4)),
             g_qh + (qbase + r) * 56 + u * 8);
    }
    for (int i = tid; i < 2240; i += 256) {
        const int r = i / 7, u = i % 7;
        cp16(sb + AT_K + r * 128 + ((u * 16) ^ ((r & 7) << 4)),
             g_kh + (kvbase + r) * 56 + u * 8);
    }
    CP_COMMIT();
    for (int i = tid; i < 2240; i += 256) {
        const int r = i / 7, u = i % 7;
        cp16(sb + AT_V + r * 128 + ((u * 16) ^ ((r & 7) << 4)),
             g_vh + (kvbase + r) * 56 + u * 8);
    }
    CP_COMMIT();
    CP_WAIT1();
    __syncthreads();

    // ---- QK^T (1-term, paired ldsm4 for K) ----
    const int wm = wid & 3, wn = wid >> 2;
    const int m_base = wm * 16, n_base = wn * 160;
    const int a_row  = m_base + (lane & 7) + ((lane >> 3) & 1) * 8;
    const int a_koff = (lane >> 4) * 16;
    // paired-B lane geometry: groups 0,1 -> n-tile base (k0,k16); groups 2,3 -> +8 rows
    const int kb_row  = (lane & 7) + ((lane >> 4) << 3);
    const int kb_koff = ((lane >> 3) & 1) << 4;
    const int g = lane >> 2, qp = lane & 3;

    float C[20][4];
#pragma unroll
    for (int i = 0; i < 20; i++)
#pragma unroll
        for (int j = 0; j < 4; j++) C[i][j] = 0.f;

#pragma unroll
    for (int ks = 0; ks < 4; ks++) {
        uint32_t q4[4];
        ldsm4(q4, sb + AT_Q + a_row * 128 + ((ks * 32 + a_koff) ^ ((a_row & 7) << 4)));
#pragma unroll
        for (int nip = 0; nip < 10; nip++) {
            const int trow = n_base + nip * 16 + kb_row;
            uint32_t k4[4];
            ldsm4(k4, sb + AT_K + trow * 128 + ((ks * 32 + kb_koff) ^ ((trow & 7) << 4)));
            mma16816(C[2 * nip],     q4, k4);
            mma16816(C[2 * nip + 1], q4, k4 + 2);
        }
    }

    // ---- register softmax ----
    const float sc = 0.14142135623730951f / 1024.f;
#pragma unroll
    for (int ni = 0; ni < 20; ni++)
#pragma unroll
        for (int j = 0; j < 4; j++) C[ni][j] *= sc;

    float* RED1 = (float*)(smc + AT_RED);
    float* RED2 = (float*)(smc + AT_RED2);
    const int r0 = m_base + g;

    float m0 = -1e30f, m1 = -1e30f;
#pragma unroll
    for (int ni = 0; ni < 20; ni++) {
        m0 = fmaxf(m0, fmaxf(C[ni][0], C[ni][1]));
        m1 = fmaxf(m1, fmaxf(C[ni][2], C[ni][3]));
    }
    m0 = fmaxf(m0, __shfl_xor_sync(0xffffffffu, m0, 1));
    m0 = fmaxf(m0, __shfl_xor_sync(0xffffffffu, m0, 2));
    m1 = fmaxf(m1, __shfl_xor_sync(0xffffffffu, m1, 1));
    m1 = fmaxf(m1, __shfl_xor_sync(0xffffffffu, m1, 2));
    if (qp == 0) { RED1[wn * 64 + r0] = m0; RED1[wn * 64 + r0 + 8] = m1; }
    __syncthreads();   // also: all warps done reading K (P overwrites K region)
    const float M0 = fmaxf(RED1[r0], RED1[64 + r0]);
    const float M1 = fmaxf(RED1[r0 + 8], RED1[64 + r0 + 8]);

    float s0 = 0.f, s1 = 0.f;
#pragma unroll
    for (int ni = 0; ni < 20; ni++) {
        C[ni][0] = __expf(C[ni][0] - M0); s0 += C[ni][0];
        C[ni][1] = __expf(C[ni][1] - M0); s0 += C[ni][1];
        C[ni][2] = __expf(C[ni][2] - M1); s1 += C[ni][2];
        C[ni][3] = __expf(C[ni][3] - M1); s1 += C[ni][3];
    }
    s0 += __shfl_xor_sync(0xffffffffu, s0, 1);
    s0 += __shfl_xor_sync(0xffffffffu, s0, 2);
    s1 += __shfl_xor_sync(0xffffffffu, s1, 1);
    s1 += __shfl_xor_sync(0xffffffffu, s1, 2);
    if (qp == 0) { RED2[wn * 64 + r0] = s0; RED2[wn * 64 + r0 + 8] = s1; }
    __syncthreads();
    const float i0 = 1.f / (RED2[r0] + RED2[64 + r0]);
    const float i1 = 1.f / (RED2[r0 + 8] + RED2[64 + r0 + 8]);

    // P (single fp16) into K region (ldmatrix layout, row=640B)
    {
        const uint32_t sw0 = (r0 & 7) << 4;
        const uint32_t sw1 = ((r0 + 8) & 7) << 4;
#pragma unroll
        for (int ni = 0; ni < 20; ni++) {
            const int col = n_base + ni * 8 + qp * 2;
            const uint32_t ub = (col >> 3) * 16;
            const uint32_t off0 = r0 * 640 + (ub ^ sw0) + (col & 7) * 2;
            const uint32_t off1 = (r0 + 8) * 640 + (ub ^ sw1) + (col & 7) * 2;
            *(__half2*)(smc + AT_K + off0) =
                __halves2half2(__float2half_rn(C[ni][0] * i0), __float2half_rn(C[ni][1] * i0));
            *(__half2*)(smc + AT_K + off1) =
                __halves2half2(__float2half_rn(C[ni][2] * i1), __float2half_rn(C[ni][3] * i1));
        }
    }
    CP_WAIT0();
    __syncthreads();

    // ---- P @ V (1-term, paired x4.trans; 4 uniform n-tiles, pad cols are zero) ----
    const int wnv = wid >> 2;
    const int mv_base = (wid & 3) * 16;
    const int nv_base = wnv * 32;
    const int p_row = mv_base + (lane & 7) + ((lane >> 3) & 1) * 8;
    const int p_unit = lane >> 4;
    const int v_krow_off = (lane & 7) + ((lane >> 3) & 1) * 8;
    const int v_col_add  = (lane >> 4) << 3;

    float O[4][4];
#pragma unroll
    for (int i = 0; i < 4; i++)
#pragma unroll
        for (int j = 0; j < 4; j++) O[i][j] = 0.f;

    for (int ks = 0; ks < 20; ks++) {
        uint32_t p4[4];
        ldsm4(p4, sb + AT_K + p_row * 640 + (((ks * 2 + p_unit) * 16) ^ ((p_row & 7) << 4)));
        const int krow = ks * 16 + v_krow_off;
        const uint32_t swk = (krow & 7) << 4;
#pragma unroll
        for (int ntp = 0; ntp < 2; ntp++) {
            const int colbyte = (nv_base + ntp * 16 + v_col_add) * 2;
            uint32_t v4[4];
            ldsm4t(v4, sb + AT_V + krow * 128 + (colbyte ^ swk));
            mma16816(O[2 * ntp],     p4, v4);
            mma16816(O[2 * ntp + 1], p4, v4 + 2);
        }
    }

    // O (scale 32) single fp16
#pragma unroll
    for (int nt = 0; nt < 4; nt++) {
        const int d = nv_base + nt * 8 + qp * 2;
        if (d >= 50) continue;
#pragma unroll
        for (int hf = 0; hf < 2; hf++) {
            const int r = mv_base + g + hf * 8;
            const size_t idx = ((size_t)b * 64 + r) * 200 + h * 50 + d;
            *(__half2*)(g_oh + idx) =
                __halves2half2(__float2half_rn(O[nt][hf * 2 + 0]),
                               __float2half_rn(O[nt][hf * 2 + 1]));
        }
    }
}

// =====================================================================
// Out projection HMMA: 2-term (A = O hi only), fp32 out, 2 CTAs/SM
// (q_mma-shaped: A hi 32K @0, B hi 32K @32768, B lo 32K @65536)
// =====================================================================
__global__ __launch_bounds__(256, 2) void out_mma(const float* __restrict__ ob,
                                                  float* __restrict__ outp, int b0arg)
{
    extern __shared__ char smc[];
    const uint32_t sb = smem_u32(smc);
    const int tid = threadIdx.x, lane = tid & 31, wid = tid >> 5;
    const int b = blockIdx.x + b0arg;
    const int wm = wid & 1, wn = wid >> 1;
    const int m_base = wm * 32;

    for (int i = tid; i < 448; i += 256) {
        const int r = i / 7, u = 1 + i % 7;
        const uint32_t off = QM_AH + 3 * 8192 + r * 128 + ((u * 16) ^ ((r & 7) << 4));
        *(uint4*)(smc + off) = make_uint4(0, 0, 0, 0);
    }
    const size_t abase = (size_t)b * 64 * 200;
    for (int i = tid; i < 1600; i += 256) {
        const int r = i / 25, cu = i % 25, ch = cu >> 3, u = cu & 7;
        const __half* src = g_oh + abase + (size_t)r * 200 + ch * 64 + u * 8;
        cp16(sb + QM_AH + ch * 8192 + r * 128 + ((u * 16) ^ ((r & 7) << 4)), src);
    }
    CP_COMMIT();
    CP_WAIT0();

    const int a_row  = (lane & 7) + ((lane >> 3) & 1) * 8;
    const int a_koff = (lane >> 4) * 16;
    const int b_row  = lane & 7;
    const int b_koff = ((lane >> 3) & 1) * 16;

    float C[2][8][4];
#pragma unroll
    for (int a = 0; a < 2; a++)
#pragma unroll
        for (int n = 0; n < 8; n++)
#pragma unroll
            for (int c = 0; c < 4; c++) C[a][n][c] = 0.f;

    for (int ck = 0; ck < 4; ck++) {
        __syncthreads();
        for (int i = tid; i < 4096; i += 256) {
            const int a = i / 2048, rem = i % 2048;
            const int r = rem >> 3, u = rem & 7;
            const __half* src = (a ? g_wol : g_woh) + (size_t)r * 256 + ck * 64 + u * 8;
            cp16(sb + (a ? QM_BL : QM_BH) + r * 128 + ((u * 16) ^ ((r & 7) << 4)), src);
        }
        CP_COMMIT();
        CP_WAIT0();
        __syncthreads();
        const int nks = (ck < 3) ? 4 : 1;
        for (int ks = 0; ks < nks; ks++) {
            uint32_t bhf[8][2], blf[8][2];
#pragma unroll
            for (int ni = 0; ni < 8; ni++) {
                const int nr = wn * 64 + ni * 8 + b_row;
                const uint32_t ad = sb + QM_BH + nr * 128 + ((ks * 32 + b_koff) ^ ((nr & 7) << 4));
                ldsm2(bhf[ni], ad);
                ldsm2(blf[ni], ad + 32768);
            }
#pragma unroll
            for (int mi = 0; mi < 2; mi++) {
                const int ar = m_base + mi * 16 + a_row;
                uint32_t ah[4];
                const uint32_t aa = sb + QM_AH + ck * 8192 + ar * 128 + ((ks * 32 + a_koff) ^ ((ar & 7) << 4));
                ldsm4(ah, aa);
#pragma unroll
                for (int ni = 0; ni < 8; ni++) {
                    mma16816(C[mi][ni], ah, bhf[ni]);
                    mma16816(C[mi][ni], ah, blf[ni]);
                }
            }
        }
    }

    const int g = lane >> 2, qp = lane & 3;
    const float invS = 1.f / 8192.f;
#pragma unroll
    for (int mi = 0; mi < 2; mi++) {
#pragma unroll
        for (int ni = 0; ni < 8; ni++) {
            const int jj = wn * 64 + ni * 8 + qp * 2;
            if (jj >= 200) continue;
            const float b0 = __ldg(ob + jj), b1 = __ldg(ob + jj + 1);
#pragma unroll
            for (int hf = 0; hf < 2; hf++) {
                const int r = m_base + mi * 16 + g + hf * 8;
                *(float2*)(outp + ((size_t)b * 64 + r) * 200 + jj) =
                    make_float2(C[mi][ni][hf * 2 + 0] * invS + b0,
                                C[mi][ni][hf * 2 + 1] * invS + b1);
            }
        }
    }
}

// =====================================================================
// launch: forked streams + split-batch tail pipelining (as R14)
// =====================================================================
struct LaunchRes {
    cudaStream_t s1, s2;
    cudaEvent_t e0, eA, eW1, eKV0, eKV1, eQ, eT1;
    LaunchRes() {
        cudaStreamCreateWithFlags(&s1, cudaStreamNonBlocking);
        cudaStreamCreateWithFlags(&s2, cudaStreamNonBlocking);
        cudaEventCreateWithFlags(&e0,   cudaEventDisableTiming);
        cudaEventCreateWithFlags(&eA,   cudaEventDisableTiming);
        cudaEventCreateWithFlags(&eW1,  cudaEventDisableTiming);
        cudaEventCreateWithFlags(&eKV0, cudaEventDisableTiming);
        cudaEventCreateWithFlags(&eKV1, cudaEventDisableTiming);
        cudaEventCreateWithFlags(&eQ,   cudaEventDisableTiming);
        cudaEventCreateWithFlags(&eT1,  cudaEventDisableTiming);
    }
};

extern "C" void kernel_launch(void* const* d_in, const int* in_sizes, int n_in,
                              void* d_out, int out_size)
{
    const float* bands = (const float*)d_in[0];
    const float* w1    = (const float*)d_in[1];
    const float* b1    = (const float*)d_in[2];
    const float* w2    = (const float*)d_in[3];
    const float* b2    = (const float*)d_in[4];
    const float* ipw   = (const float*)d_in[5];
    const float* ipb   = (const float*)d_in[6];
    const float* ow    = (const float*)d_in[7];
    const float* ob    = (const float*)d_in[8];
    float* outp = (float*)d_out;

    static LaunchRes R;

    cudaFuncSetAttribute(router_mma, cudaFuncAttributeMaxDynamicSharedMemorySize, R_SMEM);
    cudaFuncSetAttribute(kv_mma, cudaFuncAttributeMaxDynamicSharedMemorySize, KV_SMEM);
    cudaFuncSetAttribute(q_mma, cudaFuncAttributeMaxDynamicSharedMemorySize, QM_SMEM);
    cudaFuncSetAttribute(out_mma, cudaFuncAttributeMaxDynamicSharedMemorySize, QM_SMEM);
    cudaFuncSetAttribute(attn_mma, cudaFuncAttributeMaxDynamicSharedMemorySize, AT_SMEM);

    __half *bh, *blp, *w1h, *w1l, *wqh, *wql, *woh, *wol;
    cudaGetSymbolAddress((void**)&bh,  g_bh);
    cudaGetSymbolAddress((void**)&blp, g_bl);
    cudaGetSymbolAddress((void**)&w1h, g_w1h);
    cudaGetSymbolAddress((void**)&w1l, g_w1l);
    cudaGetSymbolAddress((void**)&wqh, g_wqh);
    cudaGetSymbolAddress((void**)&wql, g_wql);
    cudaGetSymbolAddress((void**)&woh, g_woh);
    cudaGetSymbolAddress((void**)&wol, g_wol);

    const int n4 = (NB * (int)BAND_STRIDE) / 4;

    // fork
    cudaEventRecord(R.e0, 0);
    cudaStreamWaitEvent(R.s1, R.e0, 0);
    cudaStreamWaitEvent(R.s2, R.e0, 0);

    // s2: w1 conversion
    conv_split<<<(n4 + 255) / 256, 256, 0, R.s2>>>(w1, w1h, w1l, n4, 256.f);
    cudaEventRecord(R.eW1, R.s2);

    // s1: kv weight conversion
    conv_wkv_k<<<448, 256, 0, R.s1>>>(ipw);

    // default: bands conversion + small weight convs
    conv_split<<<(n4 + 255) / 256, 256>>>(bands, bh, blp, n4, 4.f);
    cudaEventRecord(R.eA, 0);
    conv_w256<<<256, 256>>>(ipw, wqh, wql);
    conv_w256<<<256, 256>>>(ow, woh, wol);

    // s1: kv projection in two batch-halves
    cudaStreamWaitEvent(R.s1, R.eA, 0);
    kv_mma<<<dim3(NB, 128), 256, KV_SMEM, R.s1>>>(ipb, 0);     // batches 0..255
    cudaEventRecord(R.eKV0, R.s1);
    kv_mma<<<dim3(NB, 128), 256, KV_SMEM, R.s1>>>(ipb, 128);   // batches 256..511
    cudaEventRecord(R.eKV1, R.s1);

    // default: router chain
    cudaStreamWaitEvent(0, R.eW1, 0);
    router_mma   <<<dim3(8, 4, R_NSPLIT), 256, R_SMEM>>>();
    router_select<<<BATCH, 128>>>(b1, w2, b2);
    q_mma        <<<BATCH, 256, QM_SMEM>>>(ipb);
    cudaEventRecord(R.eQ, 0);

    // half 1 (batches 256..511) on s1 after its kv + q
    cudaStreamWaitEvent(R.s1, R.eQ, 0);
    attn_mma<<<dim3(HEADS, 256), 256, AT_SMEM, R.s1>>>(256);
    out_mma <<<256, 256, QM_SMEM, R.s1>>>(ob, outp, 256);
    cudaEventRecord(R.eT1, R.s1);

    // half 0 on default
    cudaStreamWaitEvent(0, R.eKV0, 0);
    attn_mma<<<dim3(HEADS, 256), 256, AT_SMEM>>>(0);
    out_mma <<<256, 256, QM_SMEM>>>(ob, outp, 0);

    // join
    cudaStreamWaitEvent(0, R.eT1, 0);
}

// round 16
// speedup vs baseline: 1.6542x; 1.0054x over previous
#include <cuda_runtime.h>
#include <cuda_fp16.h>
#include <cstdint>
#include <math.h>

// ---------------- problem constants ----------------
#define NB 5
#define BATCH 512
#define KQ 64
#define D 200
#define HEADS 4
#define HD 50
#define TKV 320
#define HID 512
#define FIN 64000
#define BAND_STRIDE 6553600ull   // BATCH*KQ*D (elements)
#define ROW_STRIDE 12800         // KQ*D
#define R_NSPLIT 9

// ---------------- scratch ----------------
__device__ float  g_hpart[(size_t)R_NSPLIT * BATCH * HID];
__device__ int    g_sel[BATCH];
__device__ __half g_bh [(size_t)NB * BAND_STRIDE];   // bands * 4, hi
__device__ __half g_bl [(size_t)NB * BAND_STRIDE];   // bands * 4, lo
__device__ __half g_w1h[(size_t)HID * FIN];          // w1 * 256, hi
__device__ __half g_w1l[(size_t)HID * FIN];          // w1 * 256, lo
__device__ __half g_wkvh[448 * 256];                 // wk|wv * 256 padded, hi
__device__ __half g_wkvl[448 * 256];                 // lo
__device__ __half g_wqh[256 * 256];                  // wq * 256 padded, hi
__device__ __half g_wql[256 * 256];                  // lo
__device__ __half g_woh[256 * 256];                  // out_w * 256 padded, hi
__device__ __half g_wol[256 * 256];                  // lo
// head-split padded layouts, values scaled *32, pad cols 50..55 zero (single fp16)
__device__ __half g_qh[(size_t)BATCH * HEADS * 64 * 56];
__device__ __half g_kh[(size_t)BATCH * HEADS * 320 * 56];
__device__ __half g_vh[(size_t)BATCH * HEADS * 320 * 56];
// attention output, scaled *32, [b*64][200], single fp16
__device__ __half g_oh[(size_t)BATCH * KQ * D];

// =====================================================================
// helpers
// =====================================================================
__device__ __forceinline__ uint32_t smem_u32(const void* p) {
    uint32_t a;
    asm("{ .reg .u64 t; cvta.to.shared.u64 t, %1; cvt.u32.u64 %0, t; }" : "=r"(a) : "l"(p));
    return a;
}
__device__ __forceinline__ void cp16(uint32_t dst, const void* src) {
    asm volatile("cp.async.cg.shared.global [%0], [%1], 16;" :: "r"(dst), "l"(src));
}
#define CP_COMMIT() asm volatile("cp.async.commit_group;" ::: "memory")
#define CP_WAIT2()  asm volatile("cp.async.wait_group 2;" ::: "memory")
#define CP_WAIT1()  asm volatile("cp.async.wait_group 1;" ::: "memory")
#define CP_WAIT0()  asm volatile("cp.async.wait_group 0;" ::: "memory")

__device__ __forceinline__ void ldsm4(uint32_t* r, uint32_t a) {
    asm volatile("ldmatrix.sync.aligned.m8n8.x4.shared.b16 {%0,%1,%2,%3}, [%4];"
        : "=r"(r[0]), "=r"(r[1]), "=r"(r[2]), "=r"(r[3]) : "r"(a));
}
__device__ __forceinline__ void ldsm4t(uint32_t* r, uint32_t a) {
    asm volatile("ldmatrix.sync.aligned.m8n8.x4.trans.shared.b16 {%0,%1,%2,%3}, [%4];"
        : "=r"(r[0]), "=r"(r[1]), "=r"(r[2]), "=r"(r[3]) : "r"(a));
}
__device__ __forceinline__ void ldsm2(uint32_t* r, uint32_t a) {
    asm volatile("ldmatrix.sync.aligned.m8n8.x2.shared.b16 {%0,%1}, [%2];"
        : "=r"(r[0]), "=r"(r[1]) : "r"(a));
}
__device__ __forceinline__ void mma16816(float* c, const uint32_t* a, const uint32_t* b) {
    asm volatile("mma.sync.aligned.m16n8k16.row.col.f32.f16.f16.f32 "
        "{%0,%1,%2,%3}, {%4,%5,%6,%7}, {%8,%9}, {%0,%1,%2,%3};"
        : "+f"(c[0]), "+f"(c[1]), "+f"(c[2]), "+f"(c[3])
        : "r"(a[0]), "r"(a[1]), "r"(a[2]), "r"(a[3]), "r"(b[0]), "r"(b[1]));
}

// =====================================================================
// Conversion kernels
// =====================================================================
__global__ __launch_bounds__(256) void conv_split(const float* __restrict__ src,
                                                  __half* __restrict__ dh,
                                                  __half* __restrict__ dl,
                                                  int n4, float s)
{
    int i = blockIdx.x * blockDim.x + threadIdx.x;
    if (i >= n4) return;
    float4 v = ((const float4*)src)[i];
    float x0 = v.x * s, x1 = v.y * s, x2 = v.z * s, x3 = v.w * s;
    __half h0 = __float2half_rn(x0), h1 = __float2half_rn(x1);
    __half h2 = __float2half_rn(x2), h3 = __float2half_rn(x3);
    __half l0 = __float2half_rn(x0 - __half2float(h0));
    __half l1 = __float2half_rn(x1 - __half2float(h1));
    __half l2 = __float2half_rn(x2 - __half2float(h2));
    __half l3 = __float2half_rn(x3 - __half2float(h3));
    ((__half2*)dh)[2 * i]     = __halves2half2(h0, h1);
    ((__half2*)dh)[2 * i + 1] = __halves2half2(h2, h3);
    ((__half2*)dl)[2 * i]     = __halves2half2(l0, l1);
    ((__half2*)dl)[2 * i + 1] = __halves2half2(l2, l3);
}

__global__ __launch_bounds__(256) void conv_wkv_k(const float* __restrict__ ipw)
{
    const int row = blockIdx.x;
    const int col = threadIdx.x;
    float v = 0.f;
    if (row < 400 && col < 200) v = ipw[(size_t)(200 + row) * 200 + col] * 256.f;
    __half h = __float2half_rn(v);
    __half l = __float2half_rn(v - __half2float(h));
    g_wkvh[row * 256 + col] = h;
    g_wkvl[row * 256 + col] = l;
}

__global__ __launch_bounds__(256) void conv_w256(const float* __restrict__ W,
                                                 __half* __restrict__ dh,
                                                 __half* __restrict__ dl)
{
    const int row = blockIdx.x;
    const int col = threadIdx.x;
    float v = 0.f;
    if (row < 200 && col < 200) v = W[(size_t)row * 200 + col] * 256.f;
    __half h = __float2half_rn(v);
    __half l = __float2half_rn(v - __half2float(h));
    dh[row * 256 + col] = h;
    dl[row * 256 + col] = l;
}

// =====================================================================
// Router GEMM: M=128, N=64, kc=64, splitK=9, 2-stage cp.async, 2 CTAs/SM
// (unchanged from R15)
// =====================================================================
#define R_STAGE 49152
#define R_SMEM (2 * R_STAGE)
__global__ __launch_bounds__(256, 2) void router_mma(void)
{
    extern __shared__ char smc[];
    const uint32_t sb = smem_u32(smc);
    const int tid = threadIdx.x, lane = tid & 31, wid = tid >> 5;
    const int jt = blockIdx.x, mt = blockIdx.y, sp = blockIdx.z;
    const int b0 = mt * 128, j0 = jt * 64;
    const int wm = wid & 1, wn = wid >> 1;
    const int m_base = wm * 64;

    const int a_row  = (lane & 7) + ((lane >> 3) & 1) * 8;
    const int a_koff = (lane >> 4) * 16;
    const int bl_    = lane & 15;
    const int b_row  = bl_ & 7;
    const int b_koff = (bl_ >> 3) * 16;
    int rowbyteA[4], rowbyteB[2];
#pragma unroll
    for (int mi = 0; mi < 4; mi++) rowbyteA[mi] = (m_base + mi * 16 + a_row) * 128;
#pragma unroll
    for (int ni = 0; ni < 2; ni++) rowbyteB[ni] = (wn * 16 + ni * 8 + b_row) * 128;
    const int swzA = (lane & 7) << 4;
    const int swzB = b_row << 4;

    float C[4][2][4];
#pragma unroll
    for (int a = 0; a < 4; a++)
#pragma unroll
        for (int b = 0; b < 2; b++)
#pragma unroll
            for (int c = 0; c < 4; c++) C[a][b][c] = 0.f;

    const int cbeg = sp * 111 + (sp > 0 ? 1 : 0);
    const int cnt  = 111 + (sp == 0 ? 1 : 0);

    auto issue_chunk = [&](int c, int p) {
        const int n = c / 200;
        const int rr = (c - n * 200) * 64;
        const __half* Ah = g_bh + (size_t)n * BAND_STRIDE + (size_t)b0 * ROW_STRIDE + rr;
        const __half* Al = g_bl + (size_t)n * BAND_STRIDE + (size_t)b0 * ROW_STRIDE + rr;
        const size_t f0 = (size_t)c * 64;
        const uint32_t so = sb + p * R_STAGE;
#pragma unroll
        for (int j = 0; j < 4; j++) {
            const int u = tid + j * 256;
            const int row = u >> 3, uu = u & 7;
            const uint32_t d = row * 128 + ((uu * 16) ^ ((row & 7) << 4));
            cp16(so + d,         Ah + (size_t)row * ROW_STRIDE + uu * 8);
            cp16(so + 16384 + d, Al + (size_t)row * ROW_STRIDE + uu * 8);
        }
#pragma unroll
        for (int j = 0; j < 2; j++) {
            const int u = tid + j * 256;
            const int row = u >> 3, uu = u & 7;
            const uint32_t d = row * 128 + ((uu * 16) ^ ((row & 7) << 4));
            cp16(so + 32768 + d, g_w1h + (size_t)(j0 + row) * FIN + f0 + uu * 8);
            cp16(so + 40960 + d, g_w1l + (size_t)(j0 + row) * FIN + f0 + uu * 8);
        }
    };

    issue_chunk(cbeg, 0);
    CP_COMMIT();
    if (cnt > 1) { issue_chunk(cbeg + 1, 1); CP_COMMIT(); }

    for (int c = 0; c < cnt; c++) {
        const int p = c & 1;
        if (c + 1 < cnt) CP_WAIT1(); else CP_WAIT0();
        __syncthreads();
        const uint32_t so = sb + p * R_STAGE;
#pragma unroll
        for (int ks = 0; ks < 4; ks++) {
            uint32_t bhf[2][2], blf[2][2];
#pragma unroll
            for (int ni = 0; ni < 2; ni++) {
                const uint32_t ad = so + 32768 + rowbyteB[ni] + ((ks * 32 + b_koff) ^ swzB);
                ldsm2(bhf[ni], ad);
                ldsm2(blf[ni], ad + 8192);
            }
#pragma unroll
            for (int mi = 0; mi < 4; mi++) {
                uint32_t ah[4], al[4];
                const uint32_t aa = so + rowbyteA[mi] + ((ks * 32 + a_koff) ^ swzA);
                ldsm4(ah, aa);
                ldsm4(al, aa + 16384);
#pragma unroll
                for (int ni = 0; ni < 2; ni++) {
                    mma16816(C[mi][ni], ah, bhf[ni]);
                    mma16816(C[mi][ni], ah, blf[ni]);
                    mma16816(C[mi][ni], al, bhf[ni]);
                }
            }
        }
        __syncthreads();
        if (c + 2 < cnt) { issue_chunk(cbeg + c + 2, p); CP_COMMIT(); }
    }

    const float invS = 1.f / 1024.f;
    float* outp = g_hpart + (size_t)sp * (BATCH * HID);
    const int g = lane >> 2, qp = lane & 3;
#pragma unroll
    for (int mi = 0; mi < 4; mi++) {
#pragma unroll
        for (int ni = 0; ni < 2; ni++) {
            const int row = b0 + m_base + mi * 16 + g;
            const int col = j0 + wn * 16 + ni * 8 + qp * 2;
            *(float2*)(outp + (size_t)row * HID + col) =
                make_float2(C[mi][ni][0] * invS, C[mi][ni][1] * invS);
            *(float2*)(outp + (size_t)(row + 8) * HID + col) =
                make_float2(C[mi][ni][2] * invS, C[mi][ni][3] * invS);
        }
    }
}

// =====================================================================
// Router select
// =====================================================================
__global__ __launch_bounds__(128) void router_select(const float* __restrict__ b1,
                                                     const float* __restrict__ w2,
                                                     const float* __restrict__ b2)
{
    const int b = blockIdx.x, tid = threadIdx.x;
    float acc[NB] = {0.f, 0.f, 0.f, 0.f, 0.f};
    for (int j = tid; j < HID; j += 128) {
        float hv = b1[j];
#pragma unroll
        for (int s = 0; s < R_NSPLIT; s++)
            hv += g_hpart[(size_t)s * BATCH * HID + (size_t)b * HID + j];
        hv = fmaxf(hv, 0.f);
#pragma unroll
        for (int n = 0; n < NB; n++) acc[n] += hv * w2[n * HID + j];
    }
    __shared__ float red[NB][128];
#pragma unroll
    for (int n = 0; n < NB; n++) red[n][tid] = acc[n];
    __syncthreads();
    for (int s = 64; s > 0; s >>= 1) {
        if (tid < s) {
#pragma unroll
            for (int n = 0; n < NB; n++) red[n][tid] += red[n][tid + s];
        }
        __syncthreads();
    }
    if (tid == 0) {
        int best = 0;
        float bv = red[0][0] + b2[0];
        for (int n = 1; n < NB; n++) {
            float v = red[n][0] + b2[n];
            if (v > bv) { bv = v; best = n; }
        }
        g_sel[b] = best;
    }
}

// =====================================================================
// Q projection HMMA (2-term), single-fp16 Q out, 2 CTAs/SM,
// B streamed as 7 k-chunks of 32 cols, 2-stage cp.async ring.
// smem: A 32K @0; B stage p @32768+p*32768 (hi 16K, lo 16K). 64B B rows,
// swizzle (u ^ ((r>>1)&3))*16 keeps 8-row ldsm conflict-free.
// =====================================================================
#define QM_AH 0
#define QM_B  32768
#define QM_SMEM 98304
__global__ __launch_bounds__(256, 2) void q_mma(const float* __restrict__ ipb)
{
    extern __shared__ char smc[];
    const uint32_t sb = smem_u32(smc);
    const int tid = threadIdx.x, lane = tid & 31, wid = tid >> 5;
    const int b = blockIdx.x;
    const int wm = wid & 1, wn = wid >> 1;
    const int m_base = wm * 32;

    for (int i = tid; i < 448; i += 256) {
        const int r = i / 7, u = 1 + i % 7;
        const uint32_t off = QM_AH + 3 * 8192 + r * 128 + ((u * 16) ^ ((r & 7) << 4));
        *(uint4*)(smc + off) = make_uint4(0, 0, 0, 0);
    }

    auto load_B = [&](int ck, int p) {
        const uint32_t so = sb + QM_B + p * 32768;
#pragma unroll
        for (int j = 0; j < 8; j++) {
            const int u = tid + j * 256;        // 0..2047
            const int a = u >> 10;
            const int rem = u & 1023;
            const int r = rem >> 2, uu = rem & 3;
            const __half* src = (a ? g_wql : g_wqh) + (size_t)r * 256 + ck * 32 + uu * 8;
            cp16(so + a * 16384 + r * 64 + ((uu ^ ((r >> 1) & 3)) << 4), src);
        }
    };

    const size_t abase = (size_t)g_sel[b] * BAND_STRIDE + (size_t)b * ROW_STRIDE;
    for (int i = tid; i < 1600; i += 256) {
        const int r = i / 25, cu = i % 25, ch = cu >> 3, u = cu & 7;
        const __half* src = g_bh + abase + (size_t)r * 200 + ch * 64 + u * 8;
        cp16(sb + QM_AH + ch * 8192 + r * 128 + ((u * 16) ^ ((r & 7) << 4)), src);
    }
    CP_COMMIT();
    load_B(0, 0); CP_COMMIT();
    load_B(1, 1); CP_COMMIT();

    const int a_row  = (lane & 7) + ((lane >> 3) & 1) * 8;
    const int a_koff = (lane >> 4) * 16;
    const int b_row  = lane & 7;
    const int b_sel  = (lane >> 3) & 1;

    float C[2][8][4];
#pragma unroll
    for (int a = 0; a < 2; a++)
#pragma unroll
        for (int n = 0; n < 8; n++)
#pragma unroll
            for (int c = 0; c < 4; c++) C[a][n][c] = 0.f;

    for (int ck = 0; ck < 7; ck++) {
        const int p = ck & 1;
        if (ck + 1 < 7) CP_WAIT1(); else CP_WAIT0();
        __syncthreads();
        const uint32_t soB = sb + QM_B + p * 32768;
#pragma unroll
        for (int kl = 0; kl < 2; kl++) {
            const int ksg = ck * 2 + kl;
            const int ch = ksg >> 2, ki = ksg & 3;
            const int bu = kl * 2 + b_sel;
            uint32_t bhf[8][2], blf[8][2];
#pragma unroll
            for (int ni = 0; ni < 8; ni++) {
                const int nr = wn * 64 + ni * 8 + b_row;
                const uint32_t ad = soB + nr * 64 + ((bu ^ ((nr >> 1) & 3)) << 4);
                ldsm2(bhf[ni], ad);
                ldsm2(blf[ni], ad + 16384);
            }
#pragma unroll
            for (int mi = 0; mi < 2; mi++) {
                const int ar = m_base + mi * 16 + a_row;
                uint32_t ah[4];
                const uint32_t aa = sb + QM_AH + ch * 8192 + ar * 128 + ((ki * 32 + a_koff) ^ ((ar & 7) << 4));
                ldsm4(ah, aa);
#pragma unroll
                for (int ni = 0; ni < 8; ni++) {
                    mma16816(C[mi][ni], ah, bhf[ni]);
                    mma16816(C[mi][ni], ah, blf[ni]);
                }
            }
        }
        __syncthreads();
        if (ck + 2 < 7) { load_B(ck + 2, p); CP_COMMIT(); }
    }

    const int g = lane >> 2, qp = lane & 3;
    const float invS = 1.f / 1024.f;
#pragma unroll
    for (int mi = 0; mi < 2; mi++) {
#pragma unroll
        for (int ni = 0; ni < 8; ni++) {
            const int j = wn * 64 + ni * 8 + qp * 2;
#pragma unroll
            for (int e = 0; e < 2; e++) {
                const int jj = j + e;
                if (jj >= 200) continue;
                const int hh = jj / 50, dd = jj % 50;
                const float bia = __ldg(ipb + jj);
#pragma unroll
                for (int hf = 0; hf < 2; hf++) {
                    const int r = m_base + mi * 16 + g + hf * 8;
                    const float v = C[mi][ni][hf * 2 + e] * invS + bia;
                    const size_t idx = ((size_t)(b * 4 + hh) * 64 + r) * 56 + dd;
                    g_qh[idx] = __float2half_rn(v * 32.f);
                }
            }
        }
    }
    for (int i = tid; i < 768; i += 256) {
        const int hh = i / 192, rem2 = i % 192;
        const int t = rem2 / 3, uo = rem2 % 3;
        *((uint32_t*)(g_qh + ((size_t)(b * 4 + hh) * 64 + t) * 56 + 50) + uo) = 0u;
    }
}

// =====================================================================
// K/V projection HMMA (2-term), single-fp16 K/V, B tiles double-buffered
// (unchanged from R15)
// =====================================================================
#define KV_AH 0
#define KV_B  65536
#define KV_BIAS 196608
#define KV_SMEM (196608 + 1664)
#define KV_NT 7
__global__ __launch_bounds__(256) void kv_mma(const float* __restrict__ ipb, int bp0)
{
    extern __shared__ char smc[];
    const uint32_t sb = smem_u32(smc);
    const int tid = threadIdx.x, lane = tid & 31, wid = tid >> 5;
    const int n = blockIdx.x, bp = blockIdx.y + bp0;
    const int wm = wid & 1, wn = wid >> 1;
    const int m_base = wm * 64;

    float* bias = (float*)(smc + KV_BIAS);
    for (int i = tid; i < 400; i += 256) bias[i] = ipb[200 + i];

#pragma unroll
    for (int j = 0; j < 4; j++) {
        const int u = tid + j * 256;
        if (u < 896) {
            const int row = u / 7, uu = 1 + (u % 7);
            const uint32_t d = 3 * 16384 + row * 128 + ((uu * 16) ^ ((row & 7) << 4));
            *(uint4*)(smc + KV_AH + d) = make_uint4(0, 0, 0, 0);
        }
    }

    auto load_B = [&](int nt, int p) {
        const uint32_t so = sb + KV_B + p * 65536;
#pragma unroll
        for (int j = 0; j < 8; j++) {
            const int u = tid + j * 256;
            const int lr = u >> 5;
            const int rem = u & 31;
            const int ch = rem >> 3, uu = rem & 7;
            const int nr = nt * 64 + lr;
            const uint32_t d = ch * 8192 + lr * 128 + ((uu * 16) ^ ((lr & 7) << 4));
            cp16(so + d,         g_wkvh + (size_t)nr * 256 + ch * 64 + uu * 8);
            cp16(so + 32768 + d, g_wkvl + (size_t)nr * 256 + ch * 64 + uu * 8);
        }
    };

    {
        const size_t abase = (size_t)n * BAND_STRIDE + (size_t)(bp * 128) * 200;
#pragma unroll
        for (int j = 0; j < 13; j++) {
            const int u = tid + j * 256;
            if (u < 3200) {
                const int row = u / 25;
                const int rem = u - row * 25;
                const int ch = rem >> 3, uu = rem & 7;
                const uint32_t d = ch * 16384 + row * 128 + ((uu * 16) ^ ((row & 7) << 4));
                cp16(sb + KV_AH + d, g_bh + abase + (size_t)row * 200 + ch * 64 + uu * 8);
            }
        }
    }
    CP_COMMIT();
    load_B(0, 0); CP_COMMIT();
    load_B(1, 1); CP_COMMIT();
    CP_WAIT2();
    __syncthreads();

    const int a_row  = (lane & 7) + ((lane >> 3) & 1) * 8;
    const int a_koff = (lane >> 4) * 16;
    const int bl_    = lane & 15;
    const int b_row  = bl_ & 7;
    const int b_koff = (bl_ >> 3) * 16;
    int rowbyteA[4], rowbyteB[2];
#pragma unroll
    for (int mi = 0; mi < 4; mi++) rowbyteA[mi] = (m_base + mi * 16 + a_row) * 128;
#pragma unroll
    for (int ni = 0; ni < 2; ni++) rowbyteB[ni] = (wn * 16 + ni * 8 + b_row) * 128;
    const int swzA = (lane & 7) << 4;
    const int swzB = b_row << 4;
    const int g = lane >> 2, qp = lane & 3;
    const float invS = 1.f / 1024.f;

    for (int nt = 0; nt < KV_NT; nt++) {
        const int p = nt & 1;
        if (nt + 1 < KV_NT) CP_WAIT1(); else CP_WAIT0();
        __syncthreads();
        const uint32_t soB = sb + KV_B + p * 65536;

        float C[4][2][4];
#pragma unroll
        for (int a = 0; a < 4; a++)
#pragma unroll
            for (int b = 0; b < 2; b++)
#pragma unroll
                for (int c = 0; c < 4; c++) C[a][b][c] = 0.f;

        for (int ks = 0; ks < 13; ks++) {
            const int ch = ks >> 2, ki = ks & 3;
            uint32_t bhf[2][2], blf[2][2];
#pragma unroll
            for (int ni = 0; ni < 2; ni++) {
                const uint32_t ad = soB + ch * 8192 + rowbyteB[ni] + ((ki * 32 + b_koff) ^ swzB);
                ldsm2(bhf[ni], ad);
                ldsm2(blf[ni], ad + 32768);
            }
#pragma unroll
            for (int mi = 0; mi < 4; mi++) {
                uint32_t ah[4];
                const uint32_t aa = sb + KV_AH + ch * 16384 + rowbyteA[mi] + ((ki * 32 + a_koff) ^ swzA);
                ldsm4(ah, aa);
#pragma unroll
                for (int ni = 0; ni < 2; ni++) {
                    mma16816(C[mi][ni], ah, bhf[ni]);
                    mma16816(C[mi][ni], ah, blf[ni]);
                }
            }
        }
        __syncthreads();
        if (nt + 2 < KV_NT) { load_B(nt + 2, p); CP_COMMIT(); }

#pragma unroll
        for (int mi = 0; mi < 4; mi++) {
#pragma unroll
            for (int ni = 0; ni < 2; ni++) {
                const int col = nt * 64 + wn * 16 + ni * 8 + qp * 2;
#pragma unroll
                for (int e = 0; e < 2; e++) {
                    const int ce = col + e;
                    if (ce >= 400) continue;
                    const float bia = bias[ce];
                    const int isV = (ce >= 200);
                    const int c2 = isV ? (ce - 200) : ce;
                    const int hh = c2 / 50, dd = c2 % 50;
                    __half* dsth = isV ? g_vh : g_kh;
#pragma unroll
                    for (int hf = 0; hf < 2; hf++) {
                        const int r = m_base + mi * 16 + g + hf * 8;
                        const int b = 2 * bp + (r >> 6);
                        const int tloc = n * 64 + (r & 63);
                        const float v = C[mi][ni][hf * 2 + e] * invS + bia;
                        const size_t idx = ((size_t)(b * 4 + hh) * 320 + tloc) * 56 + dd;
                        dsth[idx] = __float2half_rn(v * 32.f);
                    }
                }
            }
        }
    }
    for (int i = tid; i < 3072; i += 256) {
        const int a = i / 1536, rem = i % 1536;
        const int bb = rem / 768, rem2 = rem % 768;
        const int hh = rem2 / 192, rem3 = rem2 % 192;
        const int tt = rem3 / 3, uo = rem3 % 3;
        const int bg = 2 * bp + bb;
        const int t = n * 64 + tt;
        __half* base = (a == 0) ? g_kh : g_vh;
        *((uint32_t*)(base + ((size_t)(bg * 4 + hh) * 320 + t) * 56 + 50) + uo) = 0u;
    }
}

// =====================================================================
// Attention HMMA: single-fp16 Q/K/V, 1-term, register-resident P
// (QK^T accum fragments repacked in-register as PV A-operands; per-warp
// partial O over its 160-t slice; cross-warp pair reduce via smem)
// =====================================================================
#define AT_Q  0
#define AT_K  8192       // later O-reduce buffer (64 x 68 fp32)
#define AT_V  49152
#define AT_RED  90112
#define AT_RED2 90624
#define AT_SMEM 91136
__global__ __launch_bounds__(256, 2) void attn_mma(int b0arg)
{
    extern __shared__ char smc[];
    const uint32_t sb = smem_u32(smc);
    const int tid = threadIdx.x, lane = tid & 31, wid = tid >> 5;
    const int h = blockIdx.x, b = blockIdx.y + b0arg;
    const size_t kvbase = ((size_t)b * 4 + h) * 320;
    const size_t qbase  = ((size_t)b * 4 + h) * 64;

    for (int i = tid; i < 704; i += 256) {
        uint32_t base; int row;
        if (i < 64)       { base = AT_Q; row = i; }
        else if (i < 384) { base = AT_K; row = i - 64; }
        else              { base = AT_V; row = i - 384; }
        *(uint4*)(smc + base + row * 128 + (112 ^ ((row & 7) << 4))) = make_uint4(0, 0, 0, 0);
    }
    for (int i = tid; i < 448; i += 256) {
        const int r = i / 7, u = i % 7;
        cp16(sb + AT_Q + r * 128 + ((u * 16) ^ ((r & 7) << 4)),
             g_qh + (qbase + r) * 56 + u * 8);
    }
    for (int i = tid; i < 2240; i += 256) {
        const int r = i / 7, u = i % 7;
        cp16(sb + AT_K + r * 128 + ((u * 16) ^ ((r & 7) << 4)),
             g_kh + (kvbase + r) * 56 + u * 8);
    }
    CP_COMMIT();
    for (int i = tid; i < 2240; i += 256) {
        const int r = i / 7, u = i % 7;
        cp16(sb + AT_V + r * 128 + ((u * 16) ^ ((r & 7) << 4)),
             g_vh + (kvbase + r) * 56 + u * 8);
    }
    CP_COMMIT();
    CP_WAIT1();
    __syncthreads();

    // ---- QK^T (1-term, paired ldsm4 for K) ----
    const int wm = wid & 3, wn = wid >> 2;
    const int m_base = wm * 16, n_base = wn * 160;
    const int a_row  = m_base + (lane & 7) + ((lane >> 3) & 1) * 8;
    const int a_koff = (lane >> 4) * 16;
    const int kb_row  = (lane & 7) + ((lane >> 4) << 3);
    const int kb_koff = ((lane >> 3) & 1) << 4;
    const int g = lane >> 2, qp = lane & 3;

    float C[20][4];
#pragma unroll
    for (int i = 0; i < 20; i++)
#pragma unroll
        for (int j = 0; j < 4; j++) C[i][j] = 0.f;

#pragma unroll
    for (int ks = 0; ks < 4; ks++) {
        uint32_t q4[4];
        ldsm4(q4, sb + AT_Q + a_row * 128 + ((ks * 32 + a_koff) ^ ((a_row & 7) << 4)));
#pragma unroll
        for (int nip = 0; nip < 10; nip++) {
            const int trow = n_base + nip * 16 + kb_row;
            uint32_t k4[4];
            ldsm4(k4, sb + AT_K + trow * 128 + ((ks * 32 + kb_koff) ^ ((trow & 7) << 4)));
            mma16816(C[2 * nip],     q4, k4);
            mma16816(C[2 * nip + 1], q4, k4 + 2);
        }
    }

    // ---- register softmax ----
    const float sc = 0.14142135623730951f / 1024.f;
#pragma unroll
    for (int ni = 0; ni < 20; ni++)
#pragma unroll
        for (int j = 0; j < 4; j++) C[ni][j] *= sc;

    float* RED1 = (float*)(smc + AT_RED);
    float* RED2 = (float*)(smc + AT_RED2);
    const int r0 = m_base + g;

    float m0 = -1e30f, m1 = -1e30f;
#pragma unroll
    for (int ni = 0; ni < 20; ni++) {
        m0 = fmaxf(m0, fmaxf(C[ni][0], C[ni][1]));
        m1 = fmaxf(m1, fmaxf(C[ni][2], C[ni][3]));
    }
    m0 = fmaxf(m0, __shfl_xor_sync(0xffffffffu, m0, 1));
    m0 = fmaxf(m0, __shfl_xor_sync(0xffffffffu, m0, 2));
    m1 = fmaxf(m1, __shfl_xor_sync(0xffffffffu, m1, 1));
    m1 = fmaxf(m1, __shfl_xor_sync(0xffffffffu, m1, 2));
    if (qp == 0) { RED1[wn * 64 + r0] = m0; RED1[wn * 64 + r0 + 8] = m1; }
    __syncthreads();
    const float M0 = fmaxf(RED1[r0], RED1[64 + r0]);
    const float M1 = fmaxf(RED1[r0 + 8], RED1[64 + r0 + 8]);

    float s0 = 0.f, s1 = 0.f;
#pragma unroll
    for (int ni = 0; ni < 20; ni++) {
        C[ni][0] = __expf(C[ni][0] - M0); s0 += C[ni][0];
        C[ni][1] = __expf(C[ni][1] - M0); s0 += C[ni][1];
        C[ni][2] = __expf(C[ni][2] - M1); s1 += C[ni][2];
        C[ni][3] = __expf(C[ni][3] - M1); s1 += C[ni][3];
    }
    s0 += __shfl_xor_sync(0xffffffffu, s0, 1);
    s0 += __shfl_xor_sync(0xffffffffu, s0, 2);
    s1 += __shfl_xor_sync(0xffffffffu, s1, 1);
    s1 += __shfl_xor_sync(0xffffffffu, s1, 2);
    if (qp == 0) { RED2[wn * 64 + r0] = s0; RED2[wn * 64 + r0 + 8] = s1; }
    CP_WAIT0();        // V copies issued by this thread complete
    __syncthreads();   // RED2 visible + all V copies visible
    const float i0 = 1.f / (RED2[r0] + RED2[64 + r0]);
    const float i1 = 1.f / (RED2[r0 + 8] + RED2[64 + r0 + 8]);

    // pack normalized P into PV A-fragments (in registers; frees C)
    uint32_t pa[10][4];
#pragma unroll
    for (int j = 0; j < 10; j++) {
        __half2 t0 = __floats2half2_rn(C[2 * j][0] * i0,     C[2 * j][1] * i0);
        __half2 t1 = __floats2half2_rn(C[2 * j][2] * i1,     C[2 * j][3] * i1);
        __half2 t2 = __floats2half2_rn(C[2 * j + 1][0] * i0, C[2 * j + 1][1] * i0);
        __half2 t3 = __floats2half2_rn(C[2 * j + 1][2] * i1, C[2 * j + 1][3] * i1);
        pa[j][0] = *(uint32_t*)&t0; pa[j][1] = *(uint32_t*)&t1;
        pa[j][2] = *(uint32_t*)&t2; pa[j][3] = *(uint32_t*)&t3;
    }

    // ---- P @ V (per-warp partial over its 160-t slice) ----
    const int v_krow_off = (lane & 7) + ((lane >> 3) & 1) * 8;
    const int v_col_add  = (lane >> 4) << 3;

    float O[8][4];
#pragma unroll
    for (int i = 0; i < 8; i++)
#pragma unroll
        for (int j = 0; j < 4; j++) O[i][j] = 0.f;

#pragma unroll
    for (int j = 0; j < 10; j++) {
        const int krow = n_base + j * 16 + v_krow_off;
        const uint32_t swk = (krow & 7) << 4;
        const uint32_t vrow = sb + AT_V + krow * 128;
#pragma unroll
        for (int ntp = 0; ntp < 4; ntp++) {
            uint32_t v4[4];
            ldsm4t(v4, vrow + (((ntp * 16 + v_col_add) * 2) ^ swk));
            mma16816(O[2 * ntp],     pa[j], v4);
            mma16816(O[2 * ntp + 1], pa[j], v4 + 2);
        }
    }

    // ---- cross-warp O reduce (wn=1 partial -> smem; wn=0 adds + stores) ----
    float* OS = (float*)(smc + AT_K);
    if (wn == 1) {
#pragma unroll
        for (int nt = 0; nt < 8; nt++) {
            const int col = nt * 8 + qp * 2;
            *(float2*)&OS[r0 * 68 + col]       = make_float2(O[nt][0], O[nt][1]);
            *(float2*)&OS[(r0 + 8) * 68 + col] = make_float2(O[nt][2], O[nt][3]);
        }
    }
    __syncthreads();
    if (wn == 0) {
#pragma unroll
        for (int nt = 0; nt < 7; nt++) {
            const int d = nt * 8 + qp * 2;
            if (d >= 50) continue;
            const float o0 = O[nt][0] + OS[r0 * 68 + d];
            const float o1 = O[nt][1] + OS[r0 * 68 + d + 1];
            const float o2 = O[nt][2] + OS[(r0 + 8) * 68 + d];
            const float o3 = O[nt][3] + OS[(r0 + 8) * 68 + d + 1];
            const size_t idx = ((size_t)b * 64 + r0) * 200 + h * 50 + d;
            *(__half2*)(g_oh + idx)           = __floats2half2_rn(o0, o1);
            *(__half2*)(g_oh + idx + 8 * 200) = __floats2half2_rn(o2, o3);
        }
    }
}

// =====================================================================
// Out projection HMMA: 2-term (A = O hi only), fp32 out, 2 CTAs/SM,
// B streamed as 7x32-col chunks, 2-stage ring (mirror of q_mma)
// =====================================================================
__global__ __launch_bounds__(256, 2) void out_mma(const float* __restrict__ ob,
                                                  float* __restrict__ outp, int b0arg)
{
    extern __shared__ char smc[];
    const uint32_t sb = smem_u32(smc);
    const int tid = threadIdx.x, lane = tid & 31, wid = tid >> 5;
    const int b = blockIdx.x + b0arg;
    const int wm = wid & 1, wn = wid >> 1;
    const int m_base = wm * 32;

    for (int i = tid; i < 448; i += 256) {
        const int r = i / 7, u = 1 + i % 7;
        const uint32_t off = QM_AH + 3 * 8192 + r * 128 + ((u * 16) ^ ((r & 7) << 4));
        *(uint4*)(smc + off) = make_uint4(0, 0, 0, 0);
    }

    auto load_B = [&](int ck, int p) {
        const uint32_t so = sb + QM_B + p * 32768;
#pragma unroll
        for (int j = 0; j < 8; j++) {
            const int u = tid + j * 256;
            const int a = u >> 10;
            const int rem = u & 1023;
            const int r = rem >> 2, uu = rem & 3;
            const __half* src = (a ? g_wol : g_woh) + (size_t)r * 256 + ck * 32 + uu * 8;
            cp16(so + a * 16384 + r * 64 + ((uu ^ ((r >> 1) & 3)) << 4), src);
        }
    };

    const size_t abase = (size_t)b * 64 * 200;
    for (int i = tid; i < 1600; i += 256) {
        const int r = i / 25, cu = i % 25, ch = cu >> 3, u = cu & 7;
        const __half* src = g_oh + abase + (size_t)r * 200 + ch * 64 + u * 8;
        cp16(sb + QM_AH + ch * 8192 + r * 128 + ((u * 16) ^ ((r & 7) << 4)), src);
    }
    CP_COMMIT();
    load_B(0, 0); CP_COMMIT();
    load_B(1, 1); CP_COMMIT();

    const int a_row  = (lane & 7) + ((lane >> 3) & 1) * 8;
    const int a_koff = (lane >> 4) * 16;
    const int b_row  = lane & 7;
    const int b_sel  = (lane >> 3) & 1;

    float C[2][8][4];
#pragma unroll
    for (int a = 0; a < 2; a++)
#pragma unroll
        for (int n = 0; n < 8; n++)
#pragma unroll
            for (int c = 0; c < 4; c++) C[a][n][c] = 0.f;

    for (int ck = 0; ck < 7; ck++) {
        const int p = ck & 1;
        if (ck + 1 < 7) CP_WAIT1(); else CP_WAIT0();
        __syncthreads();
        const uint32_t soB = sb + QM_B + p * 32768;
#pragma unroll
        for (int kl = 0; kl < 2; kl++) {
            const int ksg = ck * 2 + kl;
            const int ch = ksg >> 2, ki = ksg & 3;
            const int bu = kl * 2 + b_sel;
            uint32_t bhf[8][2], blf[8][2];
#pragma unroll
            for (int ni = 0; ni < 8; ni++) {
                const int nr = wn * 64 + ni * 8 + b_row;
                const uint32_t ad = soB + nr * 64 + ((bu ^ ((nr >> 1) & 3)) << 4);
                ldsm2(bhf[ni], ad);
                ldsm2(blf[ni], ad + 16384);
            }
#pragma unroll
            for (int mi = 0; mi < 2; mi++) {
                const int ar = m_base + mi * 16 + a_row;
                uint32_t ah[4];
                const uint32_t aa = sb + QM_AH + ch * 8192 + ar * 128 + ((ki * 32 + a_koff) ^ ((ar & 7) << 4));
                ldsm4(ah, aa);
#pragma unroll
                for (int ni = 0; ni < 8; ni++) {
                    mma16816(C[mi][ni], ah, bhf[ni]);
                    mma16816(C[mi][ni], ah, blf[ni]);
                }
            }
        }
        __syncthreads();
        if (ck + 2 < 7) { load_B(ck + 2, p); CP_COMMIT(); }
    }

    const int g = lane >> 2, qp = lane & 3;
    const float invS = 1.f / 8192.f;
#pragma unroll
    for (int mi = 0; mi < 2; mi++) {
#pragma unroll
        for (int ni = 0; ni < 8; ni++) {
            const int jj = wn * 64 + ni * 8 + qp * 2;
            if (jj >= 200) continue;
            const float b0 = __ldg(ob + jj), b1 = __ldg(ob + jj + 1);
#pragma unroll
            for (int hf = 0; hf < 2; hf++) {
                const int r = m_base + mi * 16 + g + hf * 8;
                *(float2*)(outp + ((size_t)b * 64 + r) * 200 + jj) =
                    make_float2(C[mi][ni][hf * 2 + 0] * invS + b0,
                                C[mi][ni][hf * 2 + 1] * invS + b1);
            }
        }
    }
}

// =====================================================================
// launch: forked streams + split-batch tail pipelining (as R15)
// =====================================================================
struct LaunchRes {
    cudaStream_t s1, s2;
    cudaEvent_t e0, eA, eW1, eKV0, eKV1, eQ, eT1;
    LaunchRes() {
        cudaStreamCreateWithFlags(&s1, cudaStreamNonBlocking);
        cudaStreamCreateWithFlags(&s2, cudaStreamNonBlocking);
        cudaEventCreateWithFlags(&e0,   cudaEventDisableTiming);
        cudaEventCreateWithFlags(&eA,   cudaEventDisableTiming);
        cudaEventCreateWithFlags(&eW1,  cudaEventDisableTiming);
        cudaEventCreateWithFlags(&eKV0, cudaEventDisableTiming);
        cudaEventCreateWithFlags(&eKV1, cudaEventDisableTiming);
        cudaEventCreateWithFlags(&eQ,   cudaEventDisableTiming);
        cudaEventCreateWithFlags(&eT1,  cudaEventDisableTiming);
    }
};

extern "C" void kernel_launch(void* const* d_in, const int* in_sizes, int n_in,
                              void* d_out, int out_size)
{
    const float* bands = (const float*)d_in[0];
    const float* w1    = (const float*)d_in[1];
    const float* b1    = (const float*)d_in[2];
    const float* w2    = (const float*)d_in[3];
    const float* b2    = (const float*)d_in[4];
    const float* ipw   = (const float*)d_in[5];
    const float* ipb   = (const float*)d_in[6];
    const float* ow    = (const float*)d_in[7];
    const float* ob    = (const float*)d_in[8];
    float* outp = (float*)d_out;

    static LaunchRes R;

    cudaFuncSetAttribute(router_mma, cudaFuncAttributeMaxDynamicSharedMemorySize, R_SMEM);
    cudaFuncSetAttribute(kv_mma, cudaFuncAttributeMaxDynamicSharedMemorySize, KV_SMEM);
    cudaFuncSetAttribute(q_mma, cudaFuncAttributeMaxDynamicSharedMemorySize, QM_SMEM);
    cudaFuncSetAttribute(out_mma, cudaFuncAttributeMaxDynamicSharedMemorySize, QM_SMEM);
    cudaFuncSetAttribute(attn_mma, cudaFuncAttributeMaxDynamicSharedMemorySize, AT_SMEM);

    __half *bh, *blp, *w1h, *w1l, *wqh, *wql, *woh, *wol;
    cudaGetSymbolAddress((void**)&bh,  g_bh);
    cudaGetSymbolAddress((void**)&blp, g_bl);
    cudaGetSymbolAddress((void**)&w1h, g_w1h);
    cudaGetSymbolAddress((void**)&w1l, g_w1l);
    cudaGetSymbolAddress((void**)&wqh, g_wqh);
    cudaGetSymbolAddress((void**)&wql, g_wql);
    cudaGetSymbolAddress((void**)&woh, g_woh);
    cudaGetSymbolAddress((void**)&wol, g_wol);

    const int n4 = (NB * (int)BAND_STRIDE) / 4;

    // fork
    cudaEventRecord(R.e0, 0);
    cudaStreamWaitEvent(R.s1, R.e0, 0);
    cudaStreamWaitEvent(R.s2, R.e0, 0);

    // s2: w1 conversion
    conv_split<<<(n4 + 255) / 256, 256, 0, R.s2>>>(w1, w1h, w1l, n4, 256.f);
    cudaEventRecord(R.eW1, R.s2);

    // s1: kv weight conversion
    conv_wkv_k<<<448, 256, 0, R.s1>>>(ipw);

    // default: bands conversion + small weight convs
    conv_split<<<(n4 + 255) / 256, 256>>>(bands, bh, blp, n4, 4.f);
    cudaEventRecord(R.eA, 0);
    conv_w256<<<256, 256>>>(ipw, wqh, wql);
    conv_w256<<<256, 256>>>(ow, woh, wol);

    // s1: kv projection in two batch-halves
    cudaStreamWaitEvent(R.s1, R.eA, 0);
    kv_mma<<<dim3(NB, 128), 256, KV_SMEM, R.s1>>>(ipb, 0);     // batches 0..255
    cudaEventRecord(R.eKV0, R.s1);
    kv_mma<<<dim3(NB, 128), 256, KV_SMEM, R.s1>>>(ipb, 128);   // batches 256..511
    cudaEventRecord(R.eKV1, R.s1);

    // default: router chain
    cudaStreamWaitEvent(0, R.eW1, 0);
    router_mma   <<<dim3(8, 4, R_NSPLIT), 256, R_SMEM>>>();
    router_select<<<BATCH, 128>>>(b1, w2, b2);
    q_mma        <<<BATCH, 256, QM_SMEM>>>(ipb);
    cudaEventRecord(R.eQ, 0);

    // half 1 (batches 256..511) on s1 after its kv + q
    cudaStreamWaitEvent(R.s1, R.eQ, 0);
    attn_mma<<<dim3(HEADS, 256), 256, AT_SMEM, R.s1>>>(256);
    out_mma <<<256, 256, QM_SMEM, R.s1>>>(ob, outp, 256);
    cudaEventRecord(R.eT1, R.s1);

    // half 0 on default
    cudaStreamWaitEvent(0, R.eKV0, 0);
    attn_mma<<<dim3(HEADS, 256), 256, AT_SMEM>>>(0);
    out_mma <<<256, 256, QM_SMEM>>>(ob, outp, 0);

    // join
    cudaStreamWaitEvent(0, R.eT1, 0);
}

// round 17
// speedup vs baseline: 1.7209x; 1.0403x over previous
#include <cuda_runtime.h>
#include <cuda_fp16.h>
#include <cstdint>
#include <math.h>

// ---------------- problem constants ----------------
#define NB 5
#define BATCH 512
#define KQ 64
#define D 200
#define HEADS 4
#define HD 50
#define TKV 320
#define HID 512
#define FIN 64000
#define BAND_STRIDE 6553600ull   // BATCH*KQ*D (elements)
#define ROW_STRIDE 12800         // KQ*D
#define R_NSPLIT 9

// ---------------- scratch ----------------
__device__ float  g_hpart[(size_t)R_NSPLIT * BATCH * HID];
__device__ int    g_sel[BATCH];
__device__ __half g_bh [(size_t)NB * BAND_STRIDE];   // bands * 4, hi
__device__ __half g_bl [(size_t)NB * BAND_STRIDE];   // bands * 4, lo
__device__ __half g_wkvh[448 * 256];                 // wk|wv * 256 padded, hi
__device__ __half g_wkvl[448 * 256];                 // lo
__device__ __half g_wqh[256 * 256];                  // wq * 256 padded, hi
__device__ __half g_wql[256 * 256];                  // lo
__device__ __half g_woh[256 * 256];                  // out_w * 256 padded, hi
__device__ __half g_wol[256 * 256];                  // lo
// head-split padded layouts, values scaled *32, pad cols 50..55 zero (single fp16)
__device__ __half g_qh[(size_t)BATCH * HEADS * 64 * 56];
__device__ __half g_kh[(size_t)BATCH * HEADS * 320 * 56];
__device__ __half g_vh[(size_t)BATCH * HEADS * 320 * 56];
// attention output, scaled *32, [b*64][200], single fp16
__device__ __half g_oh[(size_t)BATCH * KQ * D];

// =====================================================================
// helpers
// =====================================================================
__device__ __forceinline__ uint32_t smem_u32(const void* p) {
    uint32_t a;
    asm("{ .reg .u64 t; cvta.to.shared.u64 t, %1; cvt.u32.u64 %0, t; }" : "=r"(a) : "l"(p));
    return a;
}
__device__ __forceinline__ void cp16(uint32_t dst, const void* src) {
    asm volatile("cp.async.cg.shared.global [%0], [%1], 16;" :: "r"(dst), "l"(src));
}
#define CP_COMMIT() asm volatile("cp.async.commit_group;" ::: "memory")
#define CP_WAIT2()  asm volatile("cp.async.wait_group 2;" ::: "memory")
#define CP_WAIT1()  asm volatile("cp.async.wait_group 1;" ::: "memory")
#define CP_WAIT0()  asm volatile("cp.async.wait_group 0;" ::: "memory")

__device__ __forceinline__ void ldsm4(uint32_t* r, uint32_t a) {
    asm volatile("ldmatrix.sync.aligned.m8n8.x4.shared.b16 {%0,%1,%2,%3}, [%4];"
        : "=r"(r[0]), "=r"(r[1]), "=r"(r[2]), "=r"(r[3]) : "r"(a));
}
__device__ __forceinline__ void ldsm4t(uint32_t* r, uint32_t a) {
    asm volatile("ldmatrix.sync.aligned.m8n8.x4.trans.shared.b16 {%0,%1,%2,%3}, [%4];"
        : "=r"(r[0]), "=r"(r[1]), "=r"(r[2]), "=r"(r[3]) : "r"(a));
}
__device__ __forceinline__ void ldsm2(uint32_t* r, uint32_t a) {
    asm volatile("ldmatrix.sync.aligned.m8n8.x2.shared.b16 {%0,%1}, [%2];"
        : "=r"(r[0]), "=r"(r[1]) : "r"(a));
}
__device__ __forceinline__ void mma16816(float* c, const uint32_t* a, const uint32_t* b) {
    asm volatile("mma.sync.aligned.m16n8k16.row.col.f32.f16.f16.f32 "
        "{%0,%1,%2,%3}, {%4,%5,%6,%7}, {%8,%9}, {%0,%1,%2,%3};"
        : "+f"(c[0]), "+f"(c[1]), "+f"(c[2]), "+f"(c[3])
        : "r"(a[0]), "r"(a[1]), "r"(a[2]), "r"(a[3]), "r"(b[0]), "r"(b[1]));
}

// =====================================================================
// Conversion kernels
// =====================================================================
__global__ __launch_bounds__(256) void conv_split(const float* __restrict__ src,
                                                  __half* __restrict__ dh,
                                                  __half* __restrict__ dl,
                                                  int n4, float s)
{
    int i = blockIdx.x * blockDim.x + threadIdx.x;
    if (i >= n4) return;
    float4 v = ((const float4*)src)[i];
    float x0 = v.x * s, x1 = v.y * s, x2 = v.z * s, x3 = v.w * s;
    __half h0 = __float2half_rn(x0), h1 = __float2half_rn(x1);
    __half h2 = __float2half_rn(x2), h3 = __float2half_rn(x3);
    __half l0 = __float2half_rn(x0 - __half2float(h0));
    __half l1 = __float2half_rn(x1 - __half2float(h1));
    __half l2 = __float2half_rn(x2 - __half2float(h2));
    __half l3 = __float2half_rn(x3 - __half2float(h3));
    ((__half2*)dh)[2 * i]     = __halves2half2(h0, h1);
    ((__half2*)dh)[2 * i + 1] = __halves2half2(h2, h3);
    ((__half2*)dl)[2 * i]     = __halves2half2(l0, l1);
    ((__half2*)dl)[2 * i + 1] = __halves2half2(l2, l3);
}

__global__ __launch_bounds__(256) void conv_wkv_k(const float* __restrict__ ipw)
{
    const int row = blockIdx.x;
    const int col = threadIdx.x;
    float v = 0.f;
    if (row < 400 && col < 200) v = ipw[(size_t)(200 + row) * 200 + col] * 256.f;
    __half h = __float2half_rn(v);
    __half l = __float2half_rn(v - __half2float(h));
    g_wkvh[row * 256 + col] = h;
    g_wkvl[row * 256 + col] = l;
}

__global__ __launch_bounds__(256) void conv_w256(const float* __restrict__ W,
                                                 __half* __restrict__ dh,
                                                 __half* __restrict__ dl)
{
    const int row = blockIdx.x;
    const int col = threadIdx.x;
    float v = 0.f;
    if (row < 200 && col < 200) v = W[(size_t)row * 200 + col] * 256.f;
    __half h = __float2half_rn(v);
    __half l = __float2half_rn(v - __half2float(h));
    dh[row * 256 + col] = h;
    dl[row * 256 + col] = l;
}

// =====================================================================
// Router GEMM: M=128, N=64, kc=64, splitK=9, 2-stage, 2 CTAs/SM.
// B (w1) read as fp32 DIRECTLY from global and converted to scaled hi/lo
// fp16 in registers -> swizzled STS (fuses the old conv_split(w1) pass).
// stage (48KB): Ah@0(16K), Al@16K, Bh@32K(8K), Bl@40K
// =====================================================================
#define R_STAGE 49152
#define R_SMEM (2 * R_STAGE)
__global__ __launch_bounds__(256, 2) void router_mma(const float* __restrict__ w1)
{
    extern __shared__ char smc[];
    const uint32_t sb = smem_u32(smc);
    const int tid = threadIdx.x, lane = tid & 31, wid = tid >> 5;
    const int jt = blockIdx.x, mt = blockIdx.y, sp = blockIdx.z;
    const int b0 = mt * 128, j0 = jt * 64;
    const int wm = wid & 1, wn = wid >> 1;
    const int m_base = wm * 64;

    const int a_row  = (lane & 7) + ((lane >> 3) & 1) * 8;
    const int a_koff = (lane >> 4) * 16;
    const int bl_    = lane & 15;
    const int b_row  = bl_ & 7;
    const int b_koff = (bl_ >> 3) * 16;
    int rowbyteA[4], rowbyteB[2];
#pragma unroll
    for (int mi = 0; mi < 4; mi++) rowbyteA[mi] = (m_base + mi * 16 + a_row) * 128;
#pragma unroll
    for (int ni = 0; ni < 2; ni++) rowbyteB[ni] = (wn * 16 + ni * 8 + b_row) * 128;
    const int swzA = (lane & 7) << 4;
    const int swzB = b_row << 4;

    float C[4][2][4];
#pragma unroll
    for (int a = 0; a < 4; a++)
#pragma unroll
        for (int b = 0; b < 2; b++)
#pragma unroll
            for (int c = 0; c < 4; c++) C[a][b][c] = 0.f;

    const int cbeg = sp * 111 + (sp > 0 ? 1 : 0);
    const int cnt  = 111 + (sp == 0 ? 1 : 0);

    // per-thread B mapping: 4 float4 groups; row = u>>4 (0..63), f4 = u&15
    const int brow_t = tid >> 4;         // rows tid/16 .. stepping by 16 rows per j
    const int bf4_t  = tid & 15;

    auto issue_chunk = [&](int c, int p) {
        const int n = c / 200;
        const int rr = (c - n * 200) * 64;
        const __half* Ah = g_bh + (size_t)n * BAND_STRIDE + (size_t)b0 * ROW_STRIDE + rr;
        const __half* Al = g_bl + (size_t)n * BAND_STRIDE + (size_t)b0 * ROW_STRIDE + rr;
        const size_t f0 = (size_t)c * 64;
        const uint32_t so = sb + p * R_STAGE;
#pragma unroll
        for (int j = 0; j < 4; j++) {
            const int u = tid + j * 256;          // 0..1023
            const int row = u >> 3, uu = u & 7;
            const uint32_t d = row * 128 + ((uu * 16) ^ ((row & 7) << 4));
            cp16(so + d,         Ah + (size_t)row * ROW_STRIDE + uu * 8);
            cp16(so + 16384 + d, Al + (size_t)row * ROW_STRIDE + uu * 8);
        }
        // B: fp32 load + in-register hi/lo split (scale 256) + swizzled STS
        float4 vb[4];
#pragma unroll
        for (int j = 0; j < 4; j++) {
            const int row = brow_t + j * 16;
            vb[j] = *(const float4*)(w1 + (size_t)(j0 + row) * FIN + f0 + bf4_t * 4);
        }
#pragma unroll
        for (int j = 0; j < 4; j++) {
            const int row = brow_t + j * 16;
            const int uu = bf4_t >> 1;
            const uint32_t d = row * 128 + (((uu * 16) ^ ((row & 7) << 4)) | ((bf4_t & 1) * 8));
            float x0 = vb[j].x * 256.f, x1 = vb[j].y * 256.f;
            float x2 = vb[j].z * 256.f, x3 = vb[j].w * 256.f;
            __half h0 = __float2half_rn(x0), h1 = __float2half_rn(x1);
            __half h2 = __float2half_rn(x2), h3 = __float2half_rn(x3);
            __half2 hh0 = __halves2half2(h0, h1), hh1 = __halves2half2(h2, h3);
            __half2 ll0 = __halves2half2(__float2half_rn(x0 - __half2float(h0)),
                                         __float2half_rn(x1 - __half2float(h1)));
            __half2 ll1 = __halves2half2(__float2half_rn(x2 - __half2float(h2)),
                                         __float2half_rn(x3 - __half2float(h3)));
            *(uint2*)(smc + p * R_STAGE + 32768 + d) =
                make_uint2(*(uint32_t*)&hh0, *(uint32_t*)&hh1);
            *(uint2*)(smc + p * R_STAGE + 40960 + d) =
                make_uint2(*(uint32_t*)&ll0, *(uint32_t*)&ll1);
        }
    };

    issue_chunk(cbeg, 0);
    CP_COMMIT();
    if (cnt > 1) { issue_chunk(cbeg + 1, 1); CP_COMMIT(); }

    for (int c = 0; c < cnt; c++) {
        const int p = c & 1;
        if (c + 1 < cnt) CP_WAIT1(); else CP_WAIT0();
        __syncthreads();
        const uint32_t so = sb + p * R_STAGE;
#pragma unroll
        for (int ks = 0; ks < 4; ks++) {
            uint32_t bhf[2][2], blf[2][2];
#pragma unroll
            for (int ni = 0; ni < 2; ni++) {
                const uint32_t ad = so + 32768 + rowbyteB[ni] + ((ks * 32 + b_koff) ^ swzB);
                ldsm2(bhf[ni], ad);
                ldsm2(blf[ni], ad + 8192);
            }
#pragma unroll
            for (int mi = 0; mi < 4; mi++) {
                uint32_t ah[4], al[4];
                const uint32_t aa = so + rowbyteA[mi] + ((ks * 32 + a_koff) ^ swzA);
                ldsm4(ah, aa);
                ldsm4(al, aa + 16384);
#pragma unroll
                for (int ni = 0; ni < 2; ni++) {
                    mma16816(C[mi][ni], ah, bhf[ni]);
                    mma16816(C[mi][ni], ah, blf[ni]);
                    mma16816(C[mi][ni], al, bhf[ni]);
                }
            }
        }
        __syncthreads();
        if (c + 2 < cnt) { issue_chunk(cbeg + c + 2, p); CP_COMMIT(); }
    }

    const float invS = 1.f / 1024.f;
    float* outp = g_hpart + (size_t)sp * (BATCH * HID);
    const int g = lane >> 2, qp = lane & 3;
#pragma unroll
    for (int mi = 0; mi < 4; mi++) {
#pragma unroll
        for (int ni = 0; ni < 2; ni++) {
            const int row = b0 + m_base + mi * 16 + g;
            const int col = j0 + wn * 16 + ni * 8 + qp * 2;
            *(float2*)(outp + (size_t)row * HID + col) =
                make_float2(C[mi][ni][0] * invS, C[mi][ni][1] * invS);
            *(float2*)(outp + (size_t)(row + 8) * HID + col) =
                make_float2(C[mi][ni][2] * invS, C[mi][ni][3] * invS);
        }
    }
}

// =====================================================================
// Router select
// =====================================================================
__global__ __launch_bounds__(128) void router_select(const float* __restrict__ b1,
                                                     const float* __restrict__ w2,
                                                     const float* __restrict__ b2)
{
    const int b = blockIdx.x, tid = threadIdx.x;
    float acc[NB] = {0.f, 0.f, 0.f, 0.f, 0.f};
    for (int j = tid; j < HID; j += 128) {
        float hv = b1[j];
#pragma unroll
        for (int s = 0; s < R_NSPLIT; s++)
            hv += g_hpart[(size_t)s * BATCH * HID + (size_t)b * HID + j];
        hv = fmaxf(hv, 0.f);
#pragma unroll
        for (int n = 0; n < NB; n++) acc[n] += hv * w2[n * HID + j];
    }
    __shared__ float red[NB][128];
#pragma unroll
    for (int n = 0; n < NB; n++) red[n][tid] = acc[n];
    __syncthreads();
    for (int s = 64; s > 0; s >>= 1) {
        if (tid < s) {
#pragma unroll
            for (int n = 0; n < NB; n++) red[n][tid] += red[n][tid + s];
        }
        __syncthreads();
    }
    if (tid == 0) {
        int best = 0;
        float bv = red[0][0] + b2[0];
        for (int n = 1; n < NB; n++) {
            float v = red[n][0] + b2[n];
            if (v > bv) { bv = v; best = n; }
        }
        g_sel[b] = best;
    }
}

// =====================================================================
// Q projection HMMA (2-term), single-fp16 Q out, 2 CTAs/SM,
// B streamed as 7 k-chunks of 32 cols, 2-stage cp.async ring.
// =====================================================================
#define QM_AH 0
#define QM_B  32768
#define QM_SMEM 98304
__global__ __launch_bounds__(256, 2) void q_mma(const float* __restrict__ ipb)
{
    extern __shared__ char smc[];
    const uint32_t sb = smem_u32(smc);
    const int tid = threadIdx.x, lane = tid & 31, wid = tid >> 5;
    const int b = blockIdx.x;
    const int wm = wid & 1, wn = wid >> 1;
    const int m_base = wm * 32;

    for (int i = tid; i < 448; i += 256) {
        const int r = i / 7, u = 1 + i % 7;
        const uint32_t off = QM_AH + 3 * 8192 + r * 128 + ((u * 16) ^ ((r & 7) << 4));
        *(uint4*)(smc + off) = make_uint4(0, 0, 0, 0);
    }

    auto load_B = [&](int ck, int p) {
        const uint32_t so = sb + QM_B + p * 32768;
#pragma unroll
        for (int j = 0; j < 8; j++) {
            const int u = tid + j * 256;
            const int a = u >> 10;
            const int rem = u & 1023;
            const int r = rem >> 2, uu = rem & 3;
            const __half* src = (a ? g_wql : g_wqh) + (size_t)r * 256 + ck * 32 + uu * 8;
            cp16(so + a * 16384 + r * 64 + ((uu ^ ((r >> 1) & 3)) << 4), src);
        }
    };

    const size_t abase = (size_t)g_sel[b] * BAND_STRIDE + (size_t)b * ROW_STRIDE;
    for (int i = tid; i < 1600; i += 256) {
        const int r = i / 25, cu = i % 25, ch = cu >> 3, u = cu & 7;
        const __half* src = g_bh + abase + (size_t)r * 200 + ch * 64 + u * 8;
        cp16(sb + QM_AH + ch * 8192 + r * 128 + ((u * 16) ^ ((r & 7) << 4)), src);
    }
    CP_COMMIT();
    load_B(0, 0); CP_COMMIT();
    load_B(1, 1); CP_COMMIT();

    const int a_row  = (lane & 7) + ((lane >> 3) & 1) * 8;
    const int a_koff = (lane >> 4) * 16;
    const int b_row  = lane & 7;
    const int b_sel  = (lane >> 3) & 1;

    float C[2][8][4];
#pragma unroll
    for (int a = 0; a < 2; a++)
#pragma unroll
        for (int n = 0; n < 8; n++)
#pragma unroll
            for (int c = 0; c < 4; c++) C[a][n][c] = 0.f;

    for (int ck = 0; ck < 7; ck++) {
        const int p = ck & 1;
        if (ck + 1 < 7) CP_WAIT1(); else CP_WAIT0();
        __syncthreads();
        const uint32_t soB = sb + QM_B + p * 32768;
#pragma unroll
        for (int kl = 0; kl < 2; kl++) {
            const int ksg = ck * 2 + kl;
            const int ch = ksg >> 2, ki = ksg & 3;
            const int bu = kl * 2 + b_sel;
            uint32_t bhf[8][2], blf[8][2];
#pragma unroll
            for (int ni = 0; ni < 8; ni++) {
                const int nr = wn * 64 + ni * 8 + b_row;
                const uint32_t ad = soB + nr * 64 + ((bu ^ ((nr >> 1) & 3)) << 4);
                ldsm2(bhf[ni], ad);
                ldsm2(blf[ni], ad + 16384);
            }
#pragma unroll
            for (int mi = 0; mi < 2; mi++) {
                const int ar = m_base + mi * 16 + a_row;
                uint32_t ah[4];
                const uint32_t aa = sb + QM_AH + ch * 8192 + ar * 128 + ((ki * 32 + a_koff) ^ ((ar & 7) << 4));
                ldsm4(ah, aa);
#pragma unroll
                for (int ni = 0; ni < 8; ni++) {
                    mma16816(C[mi][ni], ah, bhf[ni]);
                    mma16816(C[mi][ni], ah, blf[ni]);
                }
            }
        }
        __syncthreads();
        if (ck + 2 < 7) { load_B(ck + 2, p); CP_COMMIT(); }
    }

    const int g = lane >> 2, qp = lane & 3;
    const float invS = 1.f / 1024.f;
#pragma unroll
    for (int mi = 0; mi < 2; mi++) {
#pragma unroll
        for (int ni = 0; ni < 8; ni++) {
            const int j = wn * 64 + ni * 8 + qp * 2;
#pragma unroll
            for (int e = 0; e < 2; e++) {
                const int jj = j + e;
                if (jj >= 200) continue;
                const int hh = jj / 50, dd = jj % 50;
                const float bia = __ldg(ipb + jj);
#pragma unroll
                for (int hf = 0; hf < 2; hf++) {
                    const int r = m_base + mi * 16 + g + hf * 8;
                    const float v = C[mi][ni][hf * 2 + e] * invS + bia;
                    const size_t idx = ((size_t)(b * 4 + hh) * 64 + r) * 56 + dd;
                    g_qh[idx] = __float2half_rn(v * 32.f);
                }
            }
        }
    }
    for (int i = tid; i < 768; i += 256) {
        const int hh = i / 192, rem2 = i % 192;
        const int t = rem2 / 3, uo = rem2 % 3;
        *((uint32_t*)(g_qh + ((size_t)(b * 4 + hh) * 64 + t) * 56 + 50) + uo) = 0u;
    }
}

// =====================================================================
// K/V projection HMMA (2-term), single-fp16 K/V, B tiles double-buffered
// =====================================================================
#define KV_AH 0
#define KV_B  65536
#define KV_BIAS 196608
#define KV_SMEM (196608 + 1664)
#define KV_NT 7
__global__ __launch_bounds__(256) void kv_mma(const float* __restrict__ ipb, int bp0)
{
    extern __shared__ char smc[];
    const uint32_t sb = smem_u32(smc);
    const int tid = threadIdx.x, lane = tid & 31, wid = tid >> 5;
    const int n = blockIdx.x, bp = blockIdx.y + bp0;
    const int wm = wid & 1, wn = wid >> 1;
    const int m_base = wm * 64;

    float* bias = (float*)(smc + KV_BIAS);
    for (int i = tid; i < 400; i += 256) bias[i] = ipb[200 + i];

#pragma unroll
    for (int j = 0; j < 4; j++) {
        const int u = tid + j * 256;
        if (u < 896) {
            const int row = u / 7, uu = 1 + (u % 7);
            const uint32_t d = 3 * 16384 + row * 128 + ((uu * 16) ^ ((row & 7) << 4));
            *(uint4*)(smc + KV_AH + d) = make_uint4(0, 0, 0, 0);
        }
    }

    auto load_B = [&](int nt, int p) {
        const uint32_t so = sb + KV_B + p * 65536;
#pragma unroll
        for (int j = 0; j < 8; j++) {
            const int u = tid + j * 256;
            const int lr = u >> 5;
            const int rem = u & 31;
            const int ch = rem >> 3, uu = rem & 7;
            const int nr = nt * 64 + lr;
            const uint32_t d = ch * 8192 + lr * 128 + ((uu * 16) ^ ((lr & 7) << 4));
            cp16(so + d,         g_wkvh + (size_t)nr * 256 + ch * 64 + uu * 8);
            cp16(so + 32768 + d, g_wkvl + (size_t)nr * 256 + ch * 64 + uu * 8);
        }
    };

    {
        const size_t abase = (size_t)n * BAND_STRIDE + (size_t)(bp * 128) * 200;
#pragma unroll
        for (int j = 0; j < 13; j++) {
            const int u = tid + j * 256;
            if (u < 3200) {
                const int row = u / 25;
                const int rem = u - row * 25;
                const int ch = rem >> 3, uu = rem & 7;
                const uint32_t d = ch * 16384 + row * 128 + ((uu * 16) ^ ((row & 7) << 4));
                cp16(sb + KV_AH + d, g_bh + abase + (size_t)row * 200 + ch * 64 + uu * 8);
            }
        }
    }
    CP_COMMIT();
    load_B(0, 0); CP_COMMIT();
    load_B(1, 1); CP_COMMIT();
    CP_WAIT2();
    __syncthreads();

    const int a_row  = (lane & 7) + ((lane >> 3) & 1) * 8;
    const int a_koff = (lane >> 4) * 16;
    const int bl_    = lane & 15;
    const int b_row  = bl_ & 7;
    const int b_koff = (bl_ >> 3) * 16;
    int rowbyteA[4], rowbyteB[2];
#pragma unroll
    for (int mi = 0; mi < 4; mi++) rowbyteA[mi] = (m_base + mi * 16 + a_row) * 128;
#pragma unroll
    for (int ni = 0; ni < 2; ni++) rowbyteB[ni] = (wn * 16 + ni * 8 + b_row) * 128;
    const int swzA = (lane & 7) << 4;
    const int swzB = b_row << 4;
    const int g = lane >> 2, qp = lane & 3;
    const float invS = 1.f / 1024.f;

    for (int nt = 0; nt < KV_NT; nt++) {
        const int p = nt & 1;
        if (nt + 1 < KV_NT) CP_WAIT1(); else CP_WAIT0();
        __syncthreads();
        const uint32_t soB = sb + KV_B + p * 65536;

        float C[4][2][4];
#pragma unroll
        for (int a = 0; a < 4; a++)
#pragma unroll
            for (int b = 0; b < 2; b++)
#pragma unroll
                for (int c = 0; c < 4; c++) C[a][b][c] = 0.f;

        for (int ks = 0; ks < 13; ks++) {
            const int ch = ks >> 2, ki = ks & 3;
            uint32_t bhf[2][2], blf[2][2];
#pragma unroll
            for (int ni = 0; ni < 2; ni++) {
                const uint32_t ad = soB + ch * 8192 + rowbyteB[ni] + ((ki * 32 + b_koff) ^ swzB);
                ldsm2(bhf[ni], ad);
                ldsm2(blf[ni], ad + 32768);
            }
#pragma unroll
            for (int mi = 0; mi < 4; mi++) {
                uint32_t ah[4];
                const uint32_t aa = sb + KV_AH + ch * 16384 + rowbyteA[mi] + ((ki * 32 + a_koff) ^ swzA);
                ldsm4(ah, aa);
#pragma unroll
                for (int ni = 0; ni < 2; ni++) {
                    mma16816(C[mi][ni], ah, bhf[ni]);
                    mma16816(C[mi][ni], ah, blf[ni]);
                }
            }
        }
        __syncthreads();
        if (nt + 2 < KV_NT) { load_B(nt + 2, p); CP_COMMIT(); }

#pragma unroll
        for (int mi = 0; mi < 4; mi++) {
#pragma unroll
            for (int ni = 0; ni < 2; ni++) {
                const int col = nt * 64 + wn * 16 + ni * 8 + qp * 2;
#pragma unroll
                for (int e = 0; e < 2; e++) {
                    const int ce = col + e;
                    if (ce >= 400) continue;
                    const float bia = bias[ce];
                    const int isV = (ce >= 200);
                    const int c2 = isV ? (ce - 200) : ce;
                    const int hh = c2 / 50, dd = c2 % 50;
                    __half* dsth = isV ? g_vh : g_kh;
#pragma unroll
                    for (int hf = 0; hf < 2; hf++) {
                        const int r = m_base + mi * 16 + g + hf * 8;
                        const int b = 2 * bp + (r >> 6);
                        const int tloc = n * 64 + (r & 63);
                        const float v = C[mi][ni][hf * 2 + e] * invS + bia;
                        const size_t idx = ((size_t)(b * 4 + hh) * 320 + tloc) * 56 + dd;
                        dsth[idx] = __float2half_rn(v * 32.f);
                    }
                }
            }
        }
    }
    for (int i = tid; i < 3072; i += 256) {
        const int a = i / 1536, rem = i % 1536;
        const int bb = rem / 768, rem2 = rem % 768;
        const int hh = rem2 / 192, rem3 = rem2 % 192;
        const int tt = rem3 / 3, uo = rem3 % 3;
        const int bg = 2 * bp + bb;
        const int t = n * 64 + tt;
        __half* base = (a == 0) ? g_kh : g_vh;
        *((uint32_t*)(base + ((size_t)(bg * 4 + hh) * 320 + t) * 56 + 50) + uo) = 0u;
    }
}

// =====================================================================
// Attention HMMA: single-fp16 Q/K/V, 1-term, register-resident P
// =====================================================================
#define AT_Q  0
#define AT_K  8192       // later O-reduce buffer (64 x 68 fp32)
#define AT_V  49152
#define AT_RED  90112
#define AT_RED2 90624
#define AT_SMEM 91136
__global__ __launch_bounds__(256, 2) void attn_mma(int b0arg)
{
    extern __shared__ char smc[];
    const uint32_t sb = smem_u32(smc);
    const int tid = threadIdx.x, lane = tid & 31, wid = tid >> 5;
    const int h = blockIdx.x, b = blockIdx.y + b0arg;
    const size_t kvbase = ((size_t)b * 4 + h) * 320;
    const size_t qbase  = ((size_t)b * 4 + h) * 64;

    for (int i = tid; i < 704; i += 256) {
        uint32_t base; int row;
        if (i < 64)       { base = AT_Q; row = i; }
        else if (i < 384) { base = AT_K; row = i - 64; }
        else              { base = AT_V; row = i - 384; }
        *(uint4*)(smc + base + row * 128 + (112 ^ ((row & 7) << 4))) = make_uint4(0, 0, 0, 0);
    }
    for (int i = tid; i < 448; i += 256) {
        const int r = i / 7, u = i % 7;
        cp16(sb + AT_Q + r * 128 + ((u * 16) ^ ((r & 7) << 4)),
             g_qh + (qbase + r) * 56 + u * 8);
    }
    for (int i = tid; i < 2240; i += 256) {
        const int r = i / 7, u = i % 7;
        cp16(sb + AT_K + r * 128 + ((u * 16) ^ ((r & 7) << 4)),
             g_kh + (kvbase + r) * 56 + u * 8);
    }
    CP_COMMIT();
    for (int i = tid; i < 2240; i += 256) {
        const int r = i / 7, u = i % 7;
        cp16(sb + AT_V + r * 128 + ((u * 16) ^ ((r & 7) << 4)),
             g_vh + (kvbase + r) * 56 + u * 8);
    }
    CP_COMMIT();
    CP_WAIT1();
    __syncthreads();

    // ---- QK^T (1-term, paired ldsm4 for K) ----
    const int wm = wid & 3, wn = wid >> 2;
    const int m_base = wm * 16, n_base = wn * 160;
    const int a_row  = m_base + (lane & 7) + ((lane >> 3) & 1) * 8;
    const int a_koff = (lane >> 4) * 16;
    const int kb_row  = (lane & 7) + ((lane >> 4) << 3);
    const int kb_koff = ((lane >> 3) & 1) << 4;
    const int g = lane >> 2, qp = lane & 3;

    float C[20][4];
#pragma unroll
    for (int i = 0; i < 20; i++)
#pragma unroll
        for (int j = 0; j < 4; j++) C[i][j] = 0.f;

#pragma unroll
    for (int ks = 0; ks < 4; ks++) {
        uint32_t q4[4];
        ldsm4(q4, sb + AT_Q + a_row * 128 + ((ks * 32 + a_koff) ^ ((a_row & 7) << 4)));
#pragma unroll
        for (int nip = 0; nip < 10; nip++) {
            const int trow = n_base + nip * 16 + kb_row;
            uint32_t k4[4];
            ldsm4(k4, sb + AT_K + trow * 128 + ((ks * 32 + kb_koff) ^ ((trow & 7) << 4)));
            mma16816(C[2 * nip],     q4, k4);
            mma16816(C[2 * nip + 1], q4, k4 + 2);
        }
    }

    // ---- register softmax ----
    const float sc = 0.14142135623730951f / 1024.f;
#pragma unroll
    for (int ni = 0; ni < 20; ni++)
#pragma unroll
        for (int j = 0; j < 4; j++) C[ni][j] *= sc;

    float* RED1 = (float*)(smc + AT_RED);
    float* RED2 = (float*)(smc + AT_RED2);
    const int r0 = m_base + g;

    float m0 = -1e30f, m1 = -1e30f;
#pragma unroll
    for (int ni = 0; ni < 20; ni++) {
        m0 = fmaxf(m0, fmaxf(C[ni][0], C[ni][1]));
        m1 = fmaxf(m1, fmaxf(C[ni][2], C[ni][3]));
    }
    m0 = fmaxf(m0, __shfl_xor_sync(0xffffffffu, m0, 1));
    m0 = fmaxf(m0, __shfl_xor_sync(0xffffffffu, m0, 2));
    m1 = fmaxf(m1, __shfl_xor_sync(0xffffffffu, m1, 1));
    m1 = fmaxf(m1, __shfl_xor_sync(0xffffffffu, m1, 2));
    if (qp == 0) { RED1[wn * 64 + r0] = m0; RED1[wn * 64 + r0 + 8] = m1; }
    __syncthreads();
    const float M0 = fmaxf(RED1[r0], RED1[64 + r0]);
    const float M1 = fmaxf(RED1[r0 + 8], RED1[64 + r0 + 8]);

    float s0 = 0.f, s1 = 0.f;
#pragma unroll
    for (int ni = 0; ni < 20; ni++) {
        C[ni][0] = __expf(C[ni][0] - M0); s0 += C[ni][0];
        C[ni][1] = __expf(C[ni][1] - M0); s0 += C[ni][1];
        C[ni][2] = __expf(C[ni][2] - M1); s1 += C[ni][2];
        C[ni][3] = __expf(C[ni][3] - M1); s1 += C[ni][3];
    }
    s0 += __shfl_xor_sync(0xffffffffu, s0, 1);
    s0 += __shfl_xor_sync(0xffffffffu, s0, 2);
    s1 += __shfl_xor_sync(0xffffffffu, s1, 1);
    s1 += __shfl_xor_sync(0xffffffffu, s1, 2);
    if (qp == 0) { RED2[wn * 64 + r0] = s0; RED2[wn * 64 + r0 + 8] = s1; }
    CP_WAIT0();
    __syncthreads();
    const float i0 = 1.f / (RED2[r0] + RED2[64 + r0]);
    const float i1 = 1.f / (RED2[r0 + 8] + RED2[64 + r0 + 8]);

    // pack normalized P into PV A-fragments
    uint32_t pa[10][4];
#pragma unroll
    for (int j = 0; j < 10; j++) {
        __half2 t0 = __floats2half2_rn(C[2 * j][0] * i0,     C[2 * j][1] * i0);
        __half2 t1 = __floats2half2_rn(C[2 * j][2] * i1,     C[2 * j][3] * i1);
        __half2 t2 = __floats2half2_rn(C[2 * j + 1][0] * i0, C[2 * j + 1][1] * i0);
        __half2 t3 = __floats2half2_rn(C[2 * j + 1][2] * i1, C[2 * j + 1][3] * i1);
        pa[j][0] = *(uint32_t*)&t0; pa[j][1] = *(uint32_t*)&t1;
        pa[j][2] = *(uint32_t*)&t2; pa[j][3] = *(uint32_t*)&t3;
    }

    // ---- P @ V (per-warp partial over its 160-t slice) ----
    const int v_krow_off = (lane & 7) + ((lane >> 3) & 1) * 8;
    const int v_col_add  = (lane >> 4) << 3;

    float O[8][4];
#pragma unroll
    for (int i = 0; i < 8; i++)
#pragma unroll
        for (int j = 0; j < 4; j++) O[i][j] = 0.f;

#pragma unroll
    for (int j = 0; j < 10; j++) {
        const int krow = n_base + j * 16 + v_krow_off;
        const uint32_t swk = (krow & 7) << 4;
        const uint32_t vrow = sb + AT_V + krow * 128;
#pragma unroll
        for (int ntp = 0; ntp < 4; ntp++) {
            uint32_t v4[4];
            ldsm4t(v4, vrow + (((ntp * 16 + v_col_add) * 2) ^ swk));
            mma16816(O[2 * ntp],     pa[j], v4);
            mma16816(O[2 * ntp + 1], pa[j], v4 + 2);
        }
    }

    // ---- cross-warp O reduce ----
    float* OS = (float*)(smc + AT_K);
    if (wn == 1) {
#pragma unroll
        for (int nt = 0; nt < 8; nt++) {
            const int col = nt * 8 + qp * 2;
            *(float2*)&OS[r0 * 68 + col]       = make_float2(O[nt][0], O[nt][1]);
            *(float2*)&OS[(r0 + 8) * 68 + col] = make_float2(O[nt][2], O[nt][3]);
        }
    }
    __syncthreads();
    if (wn == 0) {
#pragma unroll
        for (int nt = 0; nt < 7; nt++) {
            const int d = nt * 8 + qp * 2;
            if (d >= 50) continue;
            const float o0 = O[nt][0] + OS[r0 * 68 + d];
            const float o1 = O[nt][1] + OS[r0 * 68 + d + 1];
            const float o2 = O[nt][2] + OS[(r0 + 8) * 68 + d];
            const float o3 = O[nt][3] + OS[(r0 + 8) * 68 + d + 1];
            const size_t idx = ((size_t)b * 64 + r0) * 200 + h * 50 + d;
            *(__half2*)(g_oh + idx)           = __floats2half2_rn(o0, o1);
            *(__half2*)(g_oh + idx + 8 * 200) = __floats2half2_rn(o2, o3);
        }
    }
}

// =====================================================================
// Out projection HMMA: 2-term (A = O hi only), fp32 out, 2 CTAs/SM
// =====================================================================
__global__ __launch_bounds__(256, 2) void out_mma(const float* __restrict__ ob,
                                                  float* __restrict__ outp, int b0arg)
{
    extern __shared__ char smc[];
    const uint32_t sb = smem_u32(smc);
    const int tid = threadIdx.x, lane = tid & 31, wid = tid >> 5;
    const int b = blockIdx.x + b0arg;
    const int wm = wid & 1, wn = wid >> 1;
    const int m_base = wm * 32;

    for (int i = tid; i < 448; i += 256) {
        const int r = i / 7, u = 1 + i % 7;
        const uint32_t off = QM_AH + 3 * 8192 + r * 128 + ((u * 16) ^ ((r & 7) << 4));
        *(uint4*)(smc + off) = make_uint4(0, 0, 0, 0);
    }

    auto load_B = [&](int ck, int p) {
        const uint32_t so = sb + QM_B + p * 32768;
#pragma unroll
        for (int j = 0; j < 8; j++) {
            const int u = tid + j * 256;
            const int a = u >> 10;
            const int rem = u & 1023;
            const int r = rem >> 2, uu = rem & 3;
            const __half* src = (a ? g_wol : g_woh) + (size_t)r * 256 + ck * 32 + uu * 8;
            cp16(so + a * 16384 + r * 64 + ((uu ^ ((r >> 1) & 3)) << 4), src);
        }
    };

    const size_t abase = (size_t)b * 64 * 200;
    for (int i = tid; i < 1600; i += 256) {
        const int r = i / 25, cu = i % 25, ch = cu >> 3, u = cu & 7;
        const __half* src = g_oh + abase + (size_t)r * 200 + ch * 64 + u * 8;
        cp16(sb + QM_AH + ch * 8192 + r * 128 + ((u * 16) ^ ((r & 7) << 4)), src);
    }
    CP_COMMIT();
    load_B(0, 0); CP_COMMIT();
    load_B(1, 1); CP_COMMIT();

    const int a_row  = (lane & 7) + ((lane >> 3) & 1) * 8;
    const int a_koff = (lane >> 4) * 16;
    const int b_row  = lane & 7;
    const int b_sel  = (lane >> 3) & 1;

    float C[2][8][4];
#pragma unroll
    for (int a = 0; a < 2; a++)
#pragma unroll
        for (int n = 0; n < 8; n++)
#pragma unroll
            for (int c = 0; c < 4; c++) C[a][n][c] = 0.f;

    for (int ck = 0; ck < 7; ck++) {
        const int p = ck & 1;
        if (ck + 1 < 7) CP_WAIT1(); else CP_WAIT0();
        __syncthreads();
        const uint32_t soB = sb + QM_B + p * 32768;
#pragma unroll
        for (int kl = 0; kl < 2; kl++) {
            const int ksg = ck * 2 + kl;
            const int ch = ksg >> 2, ki = ksg & 3;
            const int bu = kl * 2 + b_sel;
            uint32_t bhf[8][2], blf[8][2];
#pragma unroll
            for (int ni = 0; ni < 8; ni++) {
                const int nr = wn * 64 + ni * 8 + b_row;
                const uint32_t ad = soB + nr * 64 + ((bu ^ ((nr >> 1) & 3)) << 4);
                ldsm2(bhf[ni], ad);
                ldsm2(blf[ni], ad + 16384);
            }
#pragma unroll
            for (int mi = 0; mi < 2; mi++) {
                const int ar = m_base + mi * 16 + a_row;
                uint32_t ah[4];
                const uint32_t aa = sb + QM_AH + ch * 8192 + ar * 128 + ((ki * 32 + a_koff) ^ ((ar & 7) << 4));
                ldsm4(ah, aa);
#pragma unroll
                for (int ni = 0; ni < 8; ni++) {
                    mma16816(C[mi][ni], ah, bhf[ni]);
                    mma16816(C[mi][ni], ah, blf[ni]);
                }
            }
        }
        __syncthreads();
        if (ck + 2 < 7) { load_B(ck + 2, p); CP_COMMIT(); }
    }

    const int g = lane >> 2, qp = lane & 3;
    const float invS = 1.f / 8192.f;
#pragma unroll
    for (int mi = 0; mi < 2; mi++) {
#pragma unroll
        for (int ni = 0; ni < 8; ni++) {
            const int jj = wn * 64 + ni * 8 + qp * 2;
            if (jj >= 200) continue;
            const float b0 = __ldg(ob + jj), b1 = __ldg(ob + jj + 1);
#pragma unroll
            for (int hf = 0; hf < 2; hf++) {
                const int r = m_base + mi * 16 + g + hf * 8;
                *(float2*)(outp + ((size_t)b * 64 + r) * 200 + jj) =
                    make_float2(C[mi][ni][hf * 2 + 0] * invS + b0,
                                C[mi][ni][hf * 2 + 1] * invS + b1);
            }
        }
    }
}

// =====================================================================
// launch: forked streams + split-batch tail; w1 conversion fused into router
// =====================================================================
struct LaunchRes {
    cudaStream_t s1;
    cudaEvent_t e0, eA, eKV0, eKV1, eQ, eT1;
    LaunchRes() {
        cudaStreamCreateWithFlags(&s1, cudaStreamNonBlocking);
        cudaEventCreateWithFlags(&e0,   cudaEventDisableTiming);
        cudaEventCreateWithFlags(&eA,   cudaEventDisableTiming);
        cudaEventCreateWithFlags(&eKV0, cudaEventDisableTiming);
        cudaEventCreateWithFlags(&eKV1, cudaEventDisableTiming);
        cudaEventCreateWithFlags(&eQ,   cudaEventDisableTiming);
        cudaEventCreateWithFlags(&eT1,  cudaEventDisableTiming);
    }
};

extern "C" void kernel_launch(void* const* d_in, const int* in_sizes, int n_in,
                              void* d_out, int out_size)
{
    const float* bands = (const float*)d_in[0];
    const float* w1    = (const float*)d_in[1];
    const float* b1    = (const float*)d_in[2];
    const float* w2    = (const float*)d_in[3];
    const float* b2    = (const float*)d_in[4];
    const float* ipw   = (const float*)d_in[5];
    const float* ipb   = (const float*)d_in[6];
    const float* ow    = (const float*)d_in[7];
    const float* ob    = (const float*)d_in[8];
    float* outp = (float*)d_out;

    static LaunchRes R;

    cudaFuncSetAttribute(router_mma, cudaFuncAttributeMaxDynamicSharedMemorySize, R_SMEM);
    cudaFuncSetAttribute(kv_mma, cudaFuncAttributeMaxDynamicSharedMemorySize, KV_SMEM);
    cudaFuncSetAttribute(q_mma, cudaFuncAttributeMaxDynamicSharedMemorySize, QM_SMEM);
    cudaFuncSetAttribute(out_mma, cudaFuncAttributeMaxDynamicSharedMemorySize, QM_SMEM);
    cudaFuncSetAttribute(attn_mma, cudaFuncAttributeMaxDynamicSharedMemorySize, AT_SMEM);

    __half *bh, *blp, *wqh, *wql, *woh, *wol;
    cudaGetSymbolAddress((void**)&bh,  g_bh);
    cudaGetSymbolAddress((void**)&blp, g_bl);
    cudaGetSymbolAddress((void**)&wqh, g_wqh);
    cudaGetSymbolAddress((void**)&wql, g_wql);
    cudaGetSymbolAddress((void**)&woh, g_woh);
    cudaGetSymbolAddress((void**)&wol, g_wol);

    const int n4 = (NB * (int)BAND_STRIDE) / 4;

    // fork
    cudaEventRecord(R.e0, 0);
    cudaStreamWaitEvent(R.s1, R.e0, 0);

    // s1: kv weight conversion (needs only ipw)
    conv_wkv_k<<<448, 256, 0, R.s1>>>(ipw);

    // default: bands conversion + small weight convs
    conv_split<<<(n4 + 255) / 256, 256>>>(bands, bh, blp, n4, 4.f);
    cudaEventRecord(R.eA, 0);
    conv_w256<<<256, 256>>>(ipw, wqh, wql);
    conv_w256<<<256, 256>>>(ow, woh, wol);

    // s1: kv projection in two batch-halves
    cudaStreamWaitEvent(R.s1, R.eA, 0);
    kv_mma<<<dim3(NB, 128), 256, KV_SMEM, R.s1>>>(ipb, 0);     // batches 0..255
    cudaEventRecord(R.eKV0, R.s1);
    kv_mma<<<dim3(NB, 128), 256, KV_SMEM, R.s1>>>(ipb, 128);   // batches 256..511
    cudaEventRecord(R.eKV1, R.s1);

    // default: router chain (w1 read as fp32 inside router — no pre-conversion)
    router_mma   <<<dim3(8, 4, R_NSPLIT), 256, R_SMEM>>>(w1);
    router_select<<<BATCH, 128>>>(b1, w2, b2);
    q_mma        <<<BATCH, 256, QM_SMEM>>>(ipb);
    cudaEventRecord(R.eQ, 0);

    // half 1 (batches 256..511) on s1 after its kv + q
    cudaStreamWaitEvent(R.s1, R.eQ, 0);
    attn_mma<<<dim3(HEADS, 256), 256, AT_SMEM, R.s1>>>(256);
    out_mma <<<256, 256, QM_SMEM, R.s1>>>(ob, outp, 256);
    cudaEventRecord(R.eT1, R.s1);

    // half 0 on default
    cudaStreamWaitEvent(0, R.eKV0, 0);
    attn_mma<<<dim3(HEADS, 256), 256, AT_SMEM>>>(0);
    out_mma <<<256, 256, QM_SMEM>>>(ob, outp, 0);

    // join
    cudaStreamWaitEvent(0, R.eT1, 0);
}